// round 5
// baseline (speedup 1.0000x reference)
#include <cuda_runtime.h>
#include <cuda_bf16.h>
#include <stdint.h>
#include <math.h>

#define B_  2
#define S_  2048
#define D_  1024
#define H_  16
#define DH_ 64
#define M_  (B_*S_)   /* 4096 */

// ---- scratch (static device allocations; no cudaMalloc allowed) ----
__device__ __align__(16) float g_q [M_*D_];
__device__ __align__(16) float g_k [M_*D_];
__device__ __align__(16) float g_v [M_*D_];
__device__ __align__(16) float g_g [M_*D_];

// bf16 hi/lo split operands for the bf16 mma GEMMs
__device__ __align__(16) __nv_bfloat16 g_xh [M_*D_], g_xl [M_*D_];
__device__ __align__(16) __nv_bfloat16 g_aoh[M_*D_], g_aol[M_*D_];
__device__ __align__(16) __nv_bfloat16 g_wqh[D_*D_], g_wql[D_*D_];
__device__ __align__(16) __nv_bfloat16 g_wkh[D_*D_], g_wkl[D_*D_];
__device__ __align__(16) __nv_bfloat16 g_wvh[D_*D_], g_wvl[D_*D_];
__device__ __align__(16) __nv_bfloat16 g_wgh[D_*D_], g_wgl[D_*D_];
__device__ __align__(16) __nv_bfloat16 g_woh[D_*D_], g_wol[D_*D_];

// ============================================================================
// PTX helpers
// ============================================================================
__device__ __forceinline__ uint32_t smem_u32(const void* p)
{
    uint32_t a;
    asm("{ .reg .u64 t; cvta.to.shared.u64 t, %1; cvt.u32.u64 %0, t; }"
        : "=r"(a) : "l"(p));
    return a;
}

__device__ __forceinline__ void cp16(uint32_t s, const void* g)
{
    asm volatile("cp.async.cg.shared.global [%0], [%1], 16;" :: "r"(s), "l"(g));
}
#define CP_COMMIT() asm volatile("cp.async.commit_group;" ::: "memory")
template<int N> __device__ __forceinline__ void cp_wait()
{
    asm volatile("cp.async.wait_group %0;" :: "n"(N) : "memory");
}

#define LDSM4(r, addr) \
    asm volatile("ldmatrix.sync.aligned.m8n8.x4.shared.b16 {%0,%1,%2,%3}, [%4];" \
        : "=r"((r)[0]), "=r"((r)[1]), "=r"((r)[2]), "=r"((r)[3]) : "r"(addr))

__device__ __forceinline__ void mma_bf16(float c[4], const uint32_t a[4],
                                         uint32_t b0, uint32_t b1)
{
    asm volatile(
        "mma.sync.aligned.m16n8k16.row.col.f32.bf16.bf16.f32 "
        "{%0,%1,%2,%3},{%4,%5,%6,%7},{%8,%9},{%0,%1,%2,%3};"
        : "+f"(c[0]), "+f"(c[1]), "+f"(c[2]), "+f"(c[3])
        : "r"(a[0]), "r"(a[1]), "r"(a[2]), "r"(a[3]), "r"(b0), "r"(b1));
}

// ============================================================================
// hi/lo bf16 split kernel
// ============================================================================
__device__ __forceinline__ uint32_t bf_split_hi(float a, float& rem)
{
    __nv_bfloat16 h = __float2bfloat16(a);
    rem = a - __bfloat162float(h);
    return (uint32_t)__bfloat16_as_ushort(h);
}

__global__ void split_kernel(const float* __restrict__ x,
                             const float* __restrict__ wq, const float* __restrict__ wk,
                             const float* __restrict__ wv, const float* __restrict__ wg,
                             const float* __restrict__ wo)
{
    const float* src;
    __nv_bfloat16 *dh, *dl;
    int n4;
    switch (blockIdx.y) {
        case 0: src = x;  dh = g_xh;  dl = g_xl;  n4 = M_*D_/4; break;
        case 1: src = wq; dh = g_wqh; dl = g_wql; n4 = D_*D_/4; break;
        case 2: src = wk; dh = g_wkh; dl = g_wkl; n4 = D_*D_/4; break;
        case 3: src = wv; dh = g_wvh; dl = g_wvl; n4 = D_*D_/4; break;
        case 4: src = wg; dh = g_wgh; dl = g_wgl; n4 = D_*D_/4; break;
        default:src = wo; dh = g_woh; dl = g_wol; n4 = D_*D_/4; break;
    }
    int i4 = blockIdx.x * blockDim.x + threadIdx.x;
    if (i4 >= n4) return;
    float4 v = ((const float4*)src)[i4];
    float r0, r1, r2, r3, d0;
    uint32_t h0 = bf_split_hi(v.x, r0), h1 = bf_split_hi(v.y, r1);
    uint32_t h2 = bf_split_hi(v.z, r2), h3 = bf_split_hi(v.w, r3);
    uint32_t l0 = bf_split_hi(r0, d0), l1 = bf_split_hi(r1, d0);
    uint32_t l2 = bf_split_hi(r2, d0), l3 = bf_split_hi(r3, d0);
    ((uint2*)dh)[i4] = make_uint2(h0 | (h1 << 16), h2 | (h3 << 16));
    ((uint2*)dl)[i4] = make_uint2(l0 | (l1 << 16), l2 | (l3 << 16));
}

// ============================================================================
// bf16 split GEMM: C[M,N] = A @ W^T, A/W as bf16 hi+lo.
// BM=128, BN=128, BK=32(bf16), 256 threads (8 warps 2x4), warp tile 64x32.
// 3-stage cp.async pipeline. smem rows = 32 halves = 64B, xor-swizzled.
// D = Ah*Bh + Al*Bh + Ah*Bl  (fp32 accumulate)
// ============================================================================
#define BKH     32
#define NITG    (D_/BKH)              /* 32 */
#define TILE_HB (128*BKH*2)           /* 8192 B per (tile,half) */
#define STAGE_B (4*TILE_HB)           /* 32768 B */
#define NSTG    3
#define GEMM_SMEM (NSTG*STAGE_B)      /* 98304 B */

struct GemmSrcs { const __nv_bfloat16 *ah, *al, *bh, *bl; };

__device__ __forceinline__ void issue_stage(uint32_t sb, int stage, int k0,
                                            const GemmSrcs& s, int tid)
{
    const __nv_bfloat16* srcs[4] = { s.ah, s.al, s.bh, s.bl };
    const uint32_t stg = sb + stage * STAGE_B;
    #pragma unroll
    for (int m = 0; m < 4; m++) {
        const __nv_bfloat16* src = srcs[m] + k0;
        const uint32_t tb = stg + m * TILE_HB;
        #pragma unroll
        for (int i = 0; i < 2; i++) {
            int j   = tid + i * 256;          // 0..511
            int row = j >> 2;                 // 0..127
            int c   = j & 3;                  // 16B chunk
            int csw = c ^ ((row >> 1) & 3);
            cp16(tb + row * 64 + csw * 16, src + (size_t)row * D_ + c * 8);
        }
    }
}

__device__ __forceinline__ void gemm_bf16_body(const GemmSrcs& s, float* __restrict__ C)
{
    extern __shared__ char dsm[];
    const uint32_t sb = smem_u32(dsm);
    const int tid  = threadIdx.x;
    const int lane = tid & 31;
    const int w    = tid >> 5;
    const int wm   = (w >> 2) * 64;
    const int wn   = (w & 3) * 32;

    // fragment address precompute
    const int l7 = lane & 7;
    uint32_t aoff[4], asw[4], boff[2], bsw[2];
    const int akb = (lane >> 4) & 1;          // A k-half bit
    const int bkb = (lane >> 3) & 1;          // B k-half bit
    #pragma unroll
    for (int mf = 0; mf < 4; mf++) {
        int row = wm + mf * 16 + l7 + 8 * ((lane >> 3) & 1);
        aoff[mf] = row * 64;
        asw[mf]  = (row >> 1) & 3;
    }
    #pragma unroll
    for (int nfp = 0; nfp < 2; nfp++) {
        int row = wn + nfp * 16 + l7 + 8 * ((lane >> 4) & 1);
        boff[nfp] = row * 64;
        bsw[nfp]  = (row >> 1) & 3;
    }

    float acc[4][4][4];
    #pragma unroll
    for (int i = 0; i < 4; i++)
        #pragma unroll
        for (int j = 0; j < 4; j++)
            #pragma unroll
            for (int r = 0; r < 4; r++) acc[i][j][r] = 0.f;

    // prefetch stages 0,1
    issue_stage(sb, 0, 0, s, tid);   CP_COMMIT();
    issue_stage(sb, 1, BKH, s, tid); CP_COMMIT();

    for (int it = 0; it < NITG; it++) {
        if (it == NITG - 1) cp_wait<0>(); else cp_wait<1>();
        __syncthreads();
        if (it + 2 < NITG) issue_stage(sb, (it + 2) % NSTG, (it + 2) * BKH, s, tid);
        CP_COMMIT();

        const uint32_t stg = sb + (it % NSTG) * STAGE_B;
        const uint32_t sAh = stg, sAl = stg + TILE_HB;
        const uint32_t sBh = stg + 2*TILE_HB, sBl = stg + 3*TILE_HB;

        #pragma unroll
        for (int ks = 0; ks < 2; ks++) {
            uint32_t ah[4][4], al[4][4], bh[2][4], bl[2][4];
            #pragma unroll
            for (int mf = 0; mf < 4; mf++) {
                uint32_t off = aoff[mf] + ((((uint32_t)(2*ks + akb)) ^ asw[mf]) << 4);
                LDSM4(ah[mf], sAh + off);
                LDSM4(al[mf], sAl + off);
            }
            #pragma unroll
            for (int nfp = 0; nfp < 2; nfp++) {
                uint32_t off = boff[nfp] + ((((uint32_t)(2*ks + bkb)) ^ bsw[nfp]) << 4);
                LDSM4(bh[nfp], sBh + off);
                LDSM4(bl[nfp], sBl + off);
            }
            #pragma unroll
            for (int mf = 0; mf < 4; mf++)
                #pragma unroll
                for (int nf = 0; nf < 4; nf++) {
                    uint32_t bh0 = bh[nf >> 1][(nf & 1)*2], bh1 = bh[nf >> 1][(nf & 1)*2 + 1];
                    uint32_t bl0 = bl[nf >> 1][(nf & 1)*2], bl1 = bl[nf >> 1][(nf & 1)*2 + 1];
                    mma_bf16(acc[mf][nf], ah[mf], bh0, bh1);
                    mma_bf16(acc[mf][nf], al[mf], bh0, bh1);
                    mma_bf16(acc[mf][nf], ah[mf], bl0, bl1);
                }
        }
        __syncthreads();
    }

    // epilogue
    const int rbase = blockIdx.y * 128 + wm + (lane >> 2);
    const int cbase = blockIdx.x * 128 + wn + ((lane & 3) << 1);
    #pragma unroll
    for (int mf = 0; mf < 4; mf++)
        #pragma unroll
        for (int nf = 0; nf < 4; nf++) {
            float* p0 = C + (size_t)(rbase + mf*16) * D_ + cbase + nf*8;
            *(float2*)p0 = make_float2(acc[mf][nf][0], acc[mf][nf][1]);
            float* p1 = p0 + (size_t)8 * D_;
            *(float2*)p1 = make_float2(acc[mf][nf][2], acc[mf][nf][3]);
        }
}

__global__ __launch_bounds__(256, 1)
void gemm_qkvg_bf()
{
    GemmSrcs s;
    float* C;
    switch (blockIdx.z) {
        case 0:  s.bh = g_wqh; s.bl = g_wql; C = g_q; break;
        case 1:  s.bh = g_wkh; s.bl = g_wkl; C = g_k; break;
        case 2:  s.bh = g_wvh; s.bl = g_wvl; C = g_v; break;
        default: s.bh = g_wgh; s.bl = g_wgl; C = g_g; break;
    }
    const size_t yoff = (size_t)blockIdx.y * 128 * D_;
    const size_t xoff = (size_t)blockIdx.x * 128 * D_;
    s.ah = g_xh + yoff; s.al = g_xl + yoff;
    s.bh += xoff;       s.bl += xoff;
    gemm_bf16_body(s, C);
}

__global__ __launch_bounds__(256, 1)
void gemm_out_bf(float* __restrict__ C)
{
    GemmSrcs s;
    const size_t yoff = (size_t)blockIdx.y * 128 * D_;
    const size_t xoff = (size_t)blockIdx.x * 128 * D_;
    s.ah = g_aoh + yoff; s.al = g_aol + yoff;
    s.bh = g_woh + xoff; s.bl = g_wol + xoff;
    gemm_bf16_body(s, C);
}

// ============================================================================
// RoPE in-place on q, k
// ============================================================================
__global__ void rope_kernel()
{
    int i = blockIdx.x * blockDim.x + threadIdx.x;
    if (i >= M_ * H_ * 32) return;
    int j  = i & 31;
    int h  = (i >> 5) & (H_ - 1);
    int bs = i >> 9;
    int s  = bs & (S_ - 1);

    float inv = exp2f(-(float)j * 0.41524101186092029f);
    float ang = (float)s * inv;
    float sn, cs;
    sincosf(ang, &sn, &cs);

    int base = bs * D_ + h * DH_ + j;
    float q1 = g_q[base], q2 = g_q[base + 32];
    g_q[base]      = q1 * cs - q2 * sn;
    g_q[base + 32] = q2 * cs + q1 * sn;
    float k1 = g_k[base], k2 = g_k[base + 32];
    g_k[base]      = k1 * cs - k2 * sn;
    g_k[base + 32] = k2 * cs + k1 * sn;
}

// ============================================================================
// TF32 helpers for attention
// ============================================================================
__device__ __forceinline__ uint32_t f2tf(float x)
{
    uint32_t r;
    asm("cvt.rna.tf32.f32 %0, %1;" : "=r"(r) : "f"(x));
    return r;
}

__device__ __forceinline__ void mma_tf32(float c[4],
                                         uint32_t a0, uint32_t a1,
                                         uint32_t a2, uint32_t a3,
                                         uint32_t b0, uint32_t b1)
{
    asm volatile(
        "mma.sync.aligned.m16n8k8.row.col.f32.tf32.tf32.f32 "
        "{%0,%1,%2,%3},{%4,%5,%6,%7},{%8,%9},{%0,%1,%2,%3};"
        : "+f"(c[0]), "+f"(c[1]), "+f"(c[2]), "+f"(c[3])
        : "r"(a0), "r"(a1), "r"(a2), "r"(a3), "r"(b0), "r"(b1));
}

__device__ __forceinline__ void bf_hilo(float a, uint32_t& hb, uint32_t& lb)
{
    __nv_bfloat16 h = __float2bfloat16(a);
    __nv_bfloat16 l = __float2bfloat16(a - __bfloat162float(h));
    hb = (uint32_t)__bfloat16_as_ushort(h);
    lb = (uint32_t)__bfloat16_as_ushort(l);
}

// ============================================================================
// Fused causal retention (TF32 mma), silu-gate epilogue emitting bf16 hi/lo
// ============================================================================
__global__ __launch_bounds__(256, 2)
void attn_kernel()
{
    __shared__ uint32_t Qs[64][68];
    __shared__ uint32_t Ks[32][68];
    __shared__ uint32_t Vs[32][68];
    __shared__ uint32_t Ss[64][36];

    const int qt   = (int)gridDim.x - 1 - (int)blockIdx.x;  // heavy tiles first
    const int h    = blockIdx.y;
    const int b    = blockIdx.z;
    const int tid  = threadIdx.x;
    const int lane = tid & 31;
    const int w    = tid >> 5;
    const int wm   = (w >> 1) * 16;
    const int wns  = (w & 1) * 16;
    const int wno  = (w & 1) * 32;

    const float gamma = 1.0f - exp2f(-5.0f - (float)h);
    const float lg    = log2f(gamma);

    const float* qp = g_q + (size_t)(b * S_ + qt * 64) * D_ + h * DH_;
    const float* kp = g_k + (size_t)(b * S_) * D_ + h * DH_;
    const float* vp = g_v + (size_t)(b * S_) * D_ + h * DH_;

    #pragma unroll
    for (int i = 0; i < 4; i++) {
        int idx = tid + i * 256;
        int r   = idx >> 4;
        int c   = (idx & 15) << 2;
        float4 v = *(const float4*)(qp + (size_t)r * D_ + c);
        *(uint4*)&Qs[r][c] = make_uint4(f2tf(v.x), f2tf(v.y), f2tf(v.z), f2tf(v.w));
    }

    const int rloc = wm + (lane >> 2);
    float grow0 = 0.125f * exp2f(lg * (float)rloc);
    float grow1 = 0.125f * exp2f(lg * (float)(rloc + 8));
    float gcolv[2][2];
    #pragma unroll
    for (int nf = 0; nf < 2; nf++)
        #pragma unroll
        for (int j = 0; j < 2; j++) {
            int t = wns + nf*8 + ((lane & 3) << 1) + j;
            gcolv[nf][j] = exp2f(-lg * (float)t);
        }

    float oacc[4][4];
    #pragma unroll
    for (int i = 0; i < 4; i++)
        #pragma unroll
        for (int j = 0; j < 4; j++) oacc[i][j] = 0.f;

    const int nkt = 2 * qt + 2;
    __syncthreads();

    for (int kt = 0; kt < nkt; kt++) {
        #pragma unroll
        for (int i = 0; i < 2; i++) {
            int idx = tid + i * 256;
            int r   = idx >> 4;
            int c   = (idx & 15) << 2;
            size_t off = (size_t)(kt * 32 + r) * D_ + c;
            float4 kv = *(const float4*)(kp + off);
            *(uint4*)&Ks[r][c] = make_uint4(f2tf(kv.x), f2tf(kv.y), f2tf(kv.z), f2tf(kv.w));
            float4 vv = *(const float4*)(vp + off);
            *(uint4*)&Vs[r][c] = make_uint4(f2tf(vv.x), f2tf(vv.y), f2tf(vv.z), f2tf(vv.w));
        }
        __syncthreads();

        float sc[2][4];
        #pragma unroll
        for (int nf = 0; nf < 2; nf++)
            #pragma unroll
            for (int r = 0; r < 4; r++) sc[nf][r] = 0.f;

        #pragma unroll
        for (int ks = 0; ks < 8; ks++) {
            const uint32_t* pa = &Qs[wm + (lane >> 2)][ks*8 + (lane & 3)];
            uint32_t a0 = pa[0],       a2 = pa[4];
            uint32_t a1 = pa[8*68],    a3 = pa[8*68 + 4];
            #pragma unroll
            for (int nf = 0; nf < 2; nf++) {
                const uint32_t* pb = &Ks[wns + nf*8 + (lane >> 2)][ks*8 + (lane & 3)];
                mma_tf32(sc[nf], a0, a1, a2, a3, pb[0], pb[4]);
            }
        }

        const int   dbase = qt * 64 - kt * 32;
        const float f     = exp2f(lg * (float)dbase);
        const float fg0   = f * grow0;
        const float fg1   = f * grow1;
        #pragma unroll
        for (int nf = 0; nf < 2; nf++) {
            const int t  = wns + nf*8 + ((lane & 3) << 1);
            const int d0 = dbase + rloc - t;
            float v00 = (d0     >= 0) ? sc[nf][0] * fg0 * gcolv[nf][0] : 0.f;
            float v01 = (d0 - 1 >= 0) ? sc[nf][1] * fg0 * gcolv[nf][1] : 0.f;
            float v10 = (d0 + 8 >= 0) ? sc[nf][2] * fg1 * gcolv[nf][0] : 0.f;
            float v11 = (d0 + 7 >= 0) ? sc[nf][3] * fg1 * gcolv[nf][1] : 0.f;
            uint32_t* ps = &Ss[wm + (lane >> 2)][t];
            *(uint2*)ps             = make_uint2(f2tf(v00), f2tf(v01));
            *(uint2*)(ps + 8*36)    = make_uint2(f2tf(v10), f2tf(v11));
        }
        __syncthreads();

        #pragma unroll
        for (int ks = 0; ks < 4; ks++) {
            const uint32_t* pa = &Ss[wm + (lane >> 2)][ks*8 + (lane & 3)];
            uint32_t a0 = pa[0],       a2 = pa[4];
            uint32_t a1 = pa[8*36],    a3 = pa[8*36 + 4];
            #pragma unroll
            for (int nf = 0; nf < 4; nf++) {
                const uint32_t* pb = &Vs[ks*8 + (lane & 3)][wno + nf*8 + (lane >> 2)];
                mma_tf32(oacc[nf], a0, a1, a2, a3, pb[0], pb[4*68]);
            }
        }
        __syncthreads();
    }

    // epilogue: y = O * silu(g) -> bf16 hi/lo into g_aoh / g_aol
    const size_t rowbase = (size_t)(b * S_ + qt * 64) * D_ + h * DH_;
    const float* gp = g_g + rowbase;
    #pragma unroll
    for (int nf = 0; nf < 4; nf++) {
        const int c = wno + nf*8 + ((lane & 3) << 1);
        #pragma unroll
        for (int half = 0; half < 2; half++) {
            const size_t o = (size_t)(rloc + half * 8) * D_ + c;
            float2 gv = *(const float2*)(gp + o);
            float s0 = gv.x / (1.f + expf(-gv.x));
            float s1 = gv.y / (1.f + expf(-gv.y));
            float y0 = oacc[nf][half*2 + 0] * s0;
            float y1 = oacc[nf][half*2 + 1] * s1;
            uint32_t h0, l0, h1, l1;
            bf_hilo(y0, h0, l0);
            bf_hilo(y1, h1, l1);
            const size_t idx = rowbase + o;
            *(uint32_t*)&g_aoh[idx] = h0 | (h1 << 16);
            *(uint32_t*)&g_aol[idx] = l0 | (l1 << 16);
        }
    }
}

// ============================================================================
extern "C" void kernel_launch(void* const* d_in, const int* in_sizes, int n_in,
                              void* d_out, int out_size)
{
    const float* x  = (const float*)d_in[0];
    const float* wq = (const float*)d_in[1];
    const float* wk = (const float*)d_in[2];
    const float* wv = (const float*)d_in[3];
    const float* wg = (const float*)d_in[4];
    const float* wo = (const float*)d_in[5];
    float* out = (float*)d_out;

    cudaFuncSetAttribute(gemm_qkvg_bf,
                         cudaFuncAttributeMaxDynamicSharedMemorySize, GEMM_SMEM);
    cudaFuncSetAttribute(gemm_out_bf,
                         cudaFuncAttributeMaxDynamicSharedMemorySize, GEMM_SMEM);

    split_kernel<<<dim3(M_*D_/4/256, 6), 256>>>(x, wq, wk, wv, wg, wo);

    gemm_qkvg_bf<<<dim3(D_/128, M_/128, 4), 256, GEMM_SMEM>>>();

    int nrope = M_ * H_ * 32;
    rope_kernel<<<(nrope + 255) / 256, 256>>>();

    attn_kernel<<<dim3(S_/64, H_, B_), 256>>>();

    gemm_out_bf<<<dim3(D_/128, M_/128), 256, GEMM_SMEM>>>(out);
}

// round 6
// speedup vs baseline: 1.0114x; 1.0114x over previous
#include <cuda_runtime.h>
#include <cuda_bf16.h>
#include <stdint.h>
#include <math.h>

#define B_  2
#define S_  2048
#define D_  1024
#define H_  16
#define DH_ 64
#define M_  (B_*S_)   /* 4096 */

// ---- scratch (static device allocations; no cudaMalloc allowed) ----
__device__ __align__(16) float g_q [M_*D_];
__device__ __align__(16) float g_k [M_*D_];
__device__ __align__(16) float g_v [M_*D_];
__device__ __align__(16) float g_g [M_*D_];

// bf16 hi/lo split operands for the bf16 mma GEMMs
__device__ __align__(16) __nv_bfloat16 g_xh [M_*D_], g_xl [M_*D_];
__device__ __align__(16) __nv_bfloat16 g_aoh[M_*D_], g_aol[M_*D_];
__device__ __align__(16) __nv_bfloat16 g_wqh[D_*D_], g_wql[D_*D_];
__device__ __align__(16) __nv_bfloat16 g_wkh[D_*D_], g_wkl[D_*D_];
__device__ __align__(16) __nv_bfloat16 g_wvh[D_*D_], g_wvl[D_*D_];
__device__ __align__(16) __nv_bfloat16 g_wgh[D_*D_], g_wgl[D_*D_];
__device__ __align__(16) __nv_bfloat16 g_woh[D_*D_], g_wol[D_*D_];

// ============================================================================
// PTX helpers
// ============================================================================
__device__ __forceinline__ uint32_t smem_u32(const void* p)
{
    uint32_t a;
    asm("{ .reg .u64 t; cvta.to.shared.u64 t, %1; cvt.u32.u64 %0, t; }"
        : "=r"(a) : "l"(p));
    return a;
}

__device__ __forceinline__ void cp16(uint32_t s, const void* g)
{
    asm volatile("cp.async.cg.shared.global [%0], [%1], 16;" :: "r"(s), "l"(g));
}
#define CP_COMMIT() asm volatile("cp.async.commit_group;" ::: "memory")
template<int N> __device__ __forceinline__ void cp_wait()
{
    asm volatile("cp.async.wait_group %0;" :: "n"(N) : "memory");
}

#define LDSM4(r, addr) \
    asm volatile("ldmatrix.sync.aligned.m8n8.x4.shared.b16 {%0,%1,%2,%3}, [%4];" \
        : "=r"((r)[0]), "=r"((r)[1]), "=r"((r)[2]), "=r"((r)[3]) : "r"(addr))

#define LDSM4T(r, addr) \
    asm volatile("ldmatrix.sync.aligned.m8n8.x4.trans.shared.b16 {%0,%1,%2,%3}, [%4];" \
        : "=r"((r)[0]), "=r"((r)[1]), "=r"((r)[2]), "=r"((r)[3]) : "r"(addr))

__device__ __forceinline__ void mma_bf16(float c[4], const uint32_t a[4],
                                         uint32_t b0, uint32_t b1)
{
    asm volatile(
        "mma.sync.aligned.m16n8k16.row.col.f32.bf16.bf16.f32 "
        "{%0,%1,%2,%3},{%4,%5,%6,%7},{%8,%9},{%0,%1,%2,%3};"
        : "+f"(c[0]), "+f"(c[1]), "+f"(c[2]), "+f"(c[3])
        : "r"(a[0]), "r"(a[1]), "r"(a[2]), "r"(a[3]), "r"(b0), "r"(b1));
}

// pack two floats into bf16x2 hi, return lo pair via out-param
__device__ __forceinline__ uint32_t pack2_hilo(float a, float b, uint32_t& lo)
{
    __nv_bfloat16 ha = __float2bfloat16(a), hb = __float2bfloat16(b);
    float ra = a - __bfloat162float(ha);
    float rb = b - __bfloat162float(hb);
    __nv_bfloat16 la = __float2bfloat16(ra), lb = __float2bfloat16(rb);
    lo = (uint32_t)__bfloat16_as_ushort(la) | ((uint32_t)__bfloat16_as_ushort(lb) << 16);
    return (uint32_t)__bfloat16_as_ushort(ha) | ((uint32_t)__bfloat16_as_ushort(hb) << 16);
}

// ============================================================================
// hi/lo bf16 split kernel for GEMM operands
// ============================================================================
__device__ __forceinline__ uint32_t bf_split_hi(float a, float& rem)
{
    __nv_bfloat16 h = __float2bfloat16(a);
    rem = a - __bfloat162float(h);
    return (uint32_t)__bfloat16_as_ushort(h);
}

__global__ void split_kernel(const float* __restrict__ x,
                             const float* __restrict__ wq, const float* __restrict__ wk,
                             const float* __restrict__ wv, const float* __restrict__ wg,
                             const float* __restrict__ wo)
{
    const float* src;
    __nv_bfloat16 *dh, *dl;
    int n4;
    switch (blockIdx.y) {
        case 0: src = x;  dh = g_xh;  dl = g_xl;  n4 = M_*D_/4; break;
        case 1: src = wq; dh = g_wqh; dl = g_wql; n4 = D_*D_/4; break;
        case 2: src = wk; dh = g_wkh; dl = g_wkl; n4 = D_*D_/4; break;
        case 3: src = wv; dh = g_wvh; dl = g_wvl; n4 = D_*D_/4; break;
        case 4: src = wg; dh = g_wgh; dl = g_wgl; n4 = D_*D_/4; break;
        default:src = wo; dh = g_woh; dl = g_wol; n4 = D_*D_/4; break;
    }
    int i4 = blockIdx.x * blockDim.x + threadIdx.x;
    if (i4 >= n4) return;
    float4 v = ((const float4*)src)[i4];
    float r0, r1, r2, r3, d0;
    uint32_t h0 = bf_split_hi(v.x, r0), h1 = bf_split_hi(v.y, r1);
    uint32_t h2 = bf_split_hi(v.z, r2), h3 = bf_split_hi(v.w, r3);
    uint32_t l0 = bf_split_hi(r0, d0), l1 = bf_split_hi(r1, d0);
    uint32_t l2 = bf_split_hi(r2, d0), l3 = bf_split_hi(r3, d0);
    ((uint2*)dh)[i4] = make_uint2(h0 | (h1 << 16), h2 | (h3 << 16));
    ((uint2*)dl)[i4] = make_uint2(l0 | (l1 << 16), l2 | (l3 << 16));
}

// ============================================================================
// bf16 split GEMM (unchanged from R5): C = A @ W^T, 3-pass hi/lo
// ============================================================================
#define BKH     32
#define NITG    (D_/BKH)
#define TILE_HB (128*BKH*2)
#define STAGE_B (4*TILE_HB)
#define NSTG    3
#define GEMM_SMEM (NSTG*STAGE_B)

struct GemmSrcs { const __nv_bfloat16 *ah, *al, *bh, *bl; };

__device__ __forceinline__ void issue_stage(uint32_t sb, int stage, int k0,
                                            const GemmSrcs& s, int tid)
{
    const __nv_bfloat16* srcs[4] = { s.ah, s.al, s.bh, s.bl };
    const uint32_t stg = sb + stage * STAGE_B;
    #pragma unroll
    for (int m = 0; m < 4; m++) {
        const __nv_bfloat16* src = srcs[m] + k0;
        const uint32_t tb = stg + m * TILE_HB;
        #pragma unroll
        for (int i = 0; i < 2; i++) {
            int j   = tid + i * 256;
            int row = j >> 2;
            int c   = j & 3;
            int csw = c ^ ((row >> 1) & 3);
            cp16(tb + row * 64 + csw * 16, src + (size_t)row * D_ + c * 8);
        }
    }
}

__device__ __forceinline__ void gemm_bf16_body(const GemmSrcs& s, float* __restrict__ C)
{
    extern __shared__ char dsm[];
    const uint32_t sb = smem_u32(dsm);
    const int tid  = threadIdx.x;
    const int lane = tid & 31;
    const int w    = tid >> 5;
    const int wm   = (w >> 2) * 64;
    const int wn   = (w & 3) * 32;

    const int l7 = lane & 7;
    uint32_t aoff[4], asw[4], boff[2], bsw[2];
    const int akb = (lane >> 4) & 1;
    const int bkb = (lane >> 3) & 1;
    #pragma unroll
    for (int mf = 0; mf < 4; mf++) {
        int row = wm + mf * 16 + l7 + 8 * ((lane >> 3) & 1);
        aoff[mf] = row * 64;
        asw[mf]  = (row >> 1) & 3;
    }
    #pragma unroll
    for (int nfp = 0; nfp < 2; nfp++) {
        int row = wn + nfp * 16 + l7 + 8 * ((lane >> 4) & 1);
        boff[nfp] = row * 64;
        bsw[nfp]  = (row >> 1) & 3;
    }

    float acc[4][4][4];
    #pragma unroll
    for (int i = 0; i < 4; i++)
        #pragma unroll
        for (int j = 0; j < 4; j++)
            #pragma unroll
            for (int r = 0; r < 4; r++) acc[i][j][r] = 0.f;

    issue_stage(sb, 0, 0, s, tid);   CP_COMMIT();
    issue_stage(sb, 1, BKH, s, tid); CP_COMMIT();

    for (int it = 0; it < NITG; it++) {
        if (it == NITG - 1) cp_wait<0>(); else cp_wait<1>();
        __syncthreads();
        if (it + 2 < NITG) issue_stage(sb, (it + 2) % NSTG, (it + 2) * BKH, s, tid);
        CP_COMMIT();

        const uint32_t stg = sb + (it % NSTG) * STAGE_B;
        const uint32_t sAh = stg, sAl = stg + TILE_HB;
        const uint32_t sBh = stg + 2*TILE_HB, sBl = stg + 3*TILE_HB;

        #pragma unroll
        for (int ks = 0; ks < 2; ks++) {
            uint32_t ah[4][4], al[4][4], bh[2][4], bl[2][4];
            #pragma unroll
            for (int mf = 0; mf < 4; mf++) {
                uint32_t off = aoff[mf] + ((((uint32_t)(2*ks + akb)) ^ asw[mf]) << 4);
                LDSM4(ah[mf], sAh + off);
                LDSM4(al[mf], sAl + off);
            }
            #pragma unroll
            for (int nfp = 0; nfp < 2; nfp++) {
                uint32_t off = boff[nfp] + ((((uint32_t)(2*ks + bkb)) ^ bsw[nfp]) << 4);
                LDSM4(bh[nfp], sBh + off);
                LDSM4(bl[nfp], sBl + off);
            }
            #pragma unroll
            for (int mf = 0; mf < 4; mf++)
                #pragma unroll
                for (int nf = 0; nf < 4; nf++) {
                    uint32_t bh0 = bh[nf >> 1][(nf & 1)*2], bh1 = bh[nf >> 1][(nf & 1)*2 + 1];
                    uint32_t bl0 = bl[nf >> 1][(nf & 1)*2], bl1 = bl[nf >> 1][(nf & 1)*2 + 1];
                    mma_bf16(acc[mf][nf], ah[mf], bh0, bh1);
                    mma_bf16(acc[mf][nf], al[mf], bh0, bh1);
                    mma_bf16(acc[mf][nf], ah[mf], bl0, bl1);
                }
        }
        __syncthreads();
    }

    const int rbase = blockIdx.y * 128 + wm + (lane >> 2);
    const int cbase = blockIdx.x * 128 + wn + ((lane & 3) << 1);
    #pragma unroll
    for (int mf = 0; mf < 4; mf++)
        #pragma unroll
        for (int nf = 0; nf < 4; nf++) {
            float* p0 = C + (size_t)(rbase + mf*16) * D_ + cbase + nf*8;
            *(float2*)p0 = make_float2(acc[mf][nf][0], acc[mf][nf][1]);
            float* p1 = p0 + (size_t)8 * D_;
            *(float2*)p1 = make_float2(acc[mf][nf][2], acc[mf][nf][3]);
        }
}

__global__ __launch_bounds__(256, 1)
void gemm_qkvg_bf()
{
    GemmSrcs s;
    float* C;
    switch (blockIdx.z) {
        case 0:  s.bh = g_wqh; s.bl = g_wql; C = g_q; break;
        case 1:  s.bh = g_wkh; s.bl = g_wkl; C = g_k; break;
        case 2:  s.bh = g_wvh; s.bl = g_wvl; C = g_v; break;
        default: s.bh = g_wgh; s.bl = g_wgl; C = g_g; break;
    }
    const size_t yoff = (size_t)blockIdx.y * 128 * D_;
    const size_t xoff = (size_t)blockIdx.x * 128 * D_;
    s.ah = g_xh + yoff; s.al = g_xl + yoff;
    s.bh += xoff;       s.bl += xoff;
    gemm_bf16_body(s, C);
}

__global__ __launch_bounds__(256, 1)
void gemm_out_bf(float* __restrict__ C)
{
    GemmSrcs s;
    const size_t yoff = (size_t)blockIdx.y * 128 * D_;
    const size_t xoff = (size_t)blockIdx.x * 128 * D_;
    s.ah = g_aoh + yoff; s.al = g_aol + yoff;
    s.bh = g_woh + xoff; s.bl = g_wol + xoff;
    gemm_bf16_body(s, C);
}

// ============================================================================
// RoPE in-place on q, k
// ============================================================================
__global__ void rope_kernel()
{
    int i = blockIdx.x * blockDim.x + threadIdx.x;
    if (i >= M_ * H_ * 32) return;
    int j  = i & 31;
    int h  = (i >> 5) & (H_ - 1);
    int bs = i >> 9;
    int s  = bs & (S_ - 1);

    float inv = exp2f(-(float)j * 0.41524101186092029f);
    float ang = (float)s * inv;
    float sn, cs;
    sincosf(ang, &sn, &cs);

    int base = bs * D_ + h * DH_ + j;
    float q1 = g_q[base], q2 = g_q[base + 32];
    g_q[base]      = q1 * cs - q2 * sn;
    g_q[base + 32] = q2 * cs + q1 * sn;
    float k1 = g_k[base], k2 = g_k[base + 32];
    g_k[base]      = k1 * cs - k2 * sn;
    g_k[base + 32] = k2 * cs + k1 * sn;
}

// ============================================================================
// bf16 hi/lo flash retention.
// CTA = 128 q-rows x (h,b); K tile 64. 256 threads, 8 warps.
// Warp w owns q-rows [w*16, w*16+16) x all 64 keys -> S stays in registers
// (QK^T C-frag layout == SV A-frag layout). All frag loads via ldmatrix.
// smem: Qh 16K | Ql 16K | Kh 8K | Kl 8K | Vh 8K | Vl 8K = 64 KB
// ============================================================================
#define QT_ 128
#define KT_ 64
#define OFF_QH 0
#define OFF_QL 16384
#define OFF_KH 32768
#define OFF_KL 40960
#define OFF_VH 49152
#define OFF_VL 57344
#define ATTN_SMEM 65536

// stage a 64x64 fp32 tile as hi/lo bf16 into swizzled 128B rows
__device__ __forceinline__ void stage64(char* dsm, int offh, int offl,
                                        const float* __restrict__ src, int tid)
{
    int r  = tid >> 2;
    int cg = (tid & 3) * 16;
    const float* p = src + (size_t)r * D_ + cg;
    float4 f0 = *(const float4*)(p);
    float4 f1 = *(const float4*)(p + 4);
    float4 f2 = *(const float4*)(p + 8);
    float4 f3 = *(const float4*)(p + 12);
    uint32_t h[8], l[8];
    h[0] = pack2_hilo(f0.x, f0.y, l[0]); h[1] = pack2_hilo(f0.z, f0.w, l[1]);
    h[2] = pack2_hilo(f1.x, f1.y, l[2]); h[3] = pack2_hilo(f1.z, f1.w, l[3]);
    h[4] = pack2_hilo(f2.x, f2.y, l[4]); h[5] = pack2_hilo(f2.z, f2.w, l[5]);
    h[6] = pack2_hilo(f3.x, f3.y, l[6]); h[7] = pack2_hilo(f3.z, f3.w, l[7]);
    uint32_t c0 = (uint32_t)((((tid & 3) * 2)     ^ (r & 7)) * 16);
    uint32_t c1 = (uint32_t)((((tid & 3) * 2 + 1) ^ (r & 7)) * 16);
    char* rowh = dsm + offh + r * 128;
    char* rowl = dsm + offl + r * 128;
    *(uint4*)(rowh + c0) = make_uint4(h[0], h[1], h[2], h[3]);
    *(uint4*)(rowh + c1) = make_uint4(h[4], h[5], h[6], h[7]);
    *(uint4*)(rowl + c0) = make_uint4(l[0], l[1], l[2], l[3]);
    *(uint4*)(rowl + c1) = make_uint4(l[4], l[5], l[6], l[7]);
}

__global__ __launch_bounds__(256, 2)
void attn_kernel()
{
    extern __shared__ char dsm[];
    const uint32_t sb = smem_u32(dsm);

    const int qt   = (int)gridDim.x - 1 - (int)blockIdx.x;  // heavy tiles first
    const int h    = blockIdx.y;
    const int b    = blockIdx.z;
    const int tid  = threadIdx.x;
    const int lane = tid & 31;
    const int w    = tid >> 5;
    const int l7   = lane & 7;

    const float gamma = 1.0f - exp2f(-5.0f - (float)h);
    const float lg    = log2f(gamma);

    const float* qp = g_q + (size_t)(b * S_ + qt * QT_) * D_ + h * DH_;
    const float* kp = g_k + (size_t)(b * S_) * D_ + h * DH_;
    const float* vp = g_v + (size_t)(b * S_) * D_ + h * DH_;

    // ---- stage Q (128x64) once: thread t -> row t>>1, cols (t&1)*32..+31
    {
        int r  = tid >> 1;
        int cg = (tid & 1) * 32;
        const float* p = qp + (size_t)r * D_ + cg;
        char* rowh = dsm + OFF_QH + r * 128;
        char* rowl = dsm + OFF_QL + r * 128;
        #pragma unroll
        for (int q8 = 0; q8 < 4; q8++) {
            float4 f0 = *(const float4*)(p + q8 * 8);
            float4 f1 = *(const float4*)(p + q8 * 8 + 4);
            uint32_t hh[4], ll[4];
            hh[0] = pack2_hilo(f0.x, f0.y, ll[0]); hh[1] = pack2_hilo(f0.z, f0.w, ll[1]);
            hh[2] = pack2_hilo(f1.x, f1.y, ll[2]); hh[3] = pack2_hilo(f1.z, f1.w, ll[3]);
            uint32_t c = (uint32_t)(((cg / 8 + q8) ^ (r & 7)) * 16);
            *(uint4*)(rowh + c) = make_uint4(hh[0], hh[1], hh[2], hh[3]);
            *(uint4*)(rowl + c) = make_uint4(ll[0], ll[1], ll[2], ll[3]);
        }
    }

    // per-thread decay constants
    const int rl0 = w * 16 + (lane >> 2);          // local q row (half 0)
    const float grow0 = 0.125f * exp2f(lg * (float)rl0);
    const float grow1 = 0.125f * exp2f(lg * (float)(rl0 + 8));
    const float ginv  = exp2f(-lg);                // gamma^-1
    float gc[8];
    #pragma unroll
    for (int p = 0; p < 8; p++)
        gc[p] = exp2f(-lg * (float)(p * 8 + (lane & 3) * 2));  // gamma^-tloc (j=0)

    float oacc[8][4];
    #pragma unroll
    for (int p = 0; p < 8; p++)
        #pragma unroll
        for (int r = 0; r < 4; r++) oacc[p][r] = 0.f;

    // fragment address components
    const uint32_t arow = (uint32_t)(w * 16 + l7 + 8 * ((lane >> 3) & 1));  // A rows (Q)
    const uint32_t akb  = (lane >> 4) & 1;
    const uint32_t brow = (uint32_t)(l7 + 8 * ((lane >> 4) & 1));           // B rows (K), within 16-grp
    const uint32_t bkb  = (lane >> 3) & 1;
    const uint32_t vrow = (uint32_t)(l7 + 8 * ((lane >> 3) & 1));           // V k-rows, within 16-grp
    const uint32_t vnb  = (lane >> 4) & 1;

    const int nkt = 2 * qt + 2;

    for (int kt = 0; kt < nkt; kt++) {
        __syncthreads();
        stage64(dsm, OFF_KH, OFF_KL, kp + (size_t)(kt * KT_) * D_, tid);
        stage64(dsm, OFF_VH, OFF_VL, vp + (size_t)(kt * KT_) * D_, tid);
        __syncthreads();

        // ---- S = Q K^T (hi/lo 3-pass), S in registers
        float sacc[8][4];
        #pragma unroll
        for (int p = 0; p < 8; p++)
            #pragma unroll
            for (int r = 0; r < 4; r++) sacc[p][r] = 0.f;

        #pragma unroll
        for (int ks = 0; ks < 4; ks++) {
            uint32_t qa = (uint32_t)sb + OFF_QH + arow * 128
                        + (((2*ks + akb) ^ (arow & 7)) << 4);
            uint32_t ah[4], al[4];
            LDSM4(ah, qa);
            LDSM4(al, qa + (OFF_QL - OFF_QH));
            #pragma unroll
            for (int g = 0; g < 4; g++) {
                uint32_t br = g * 16 + brow;
                uint32_t ba = (uint32_t)sb + OFF_KH + br * 128
                            + (((2*ks + bkb) ^ (br & 7)) << 4);
                uint32_t bh[4], bl[4];
                LDSM4(bh, ba);
                mma_bf16(sacc[2*g],   ah, bh[0], bh[1]);
                mma_bf16(sacc[2*g+1], ah, bh[2], bh[3]);
                mma_bf16(sacc[2*g],   al, bh[0], bh[1]);
                mma_bf16(sacc[2*g+1], al, bh[2], bh[3]);
                LDSM4(bl, ba + (OFF_KL - OFF_KH));
                mma_bf16(sacc[2*g],   ah, bl[0], bl[1]);
                mma_bf16(sacc[2*g+1], ah, bl[2], bl[3]);
            }
        }

        // ---- decay + causal mask + split to bf16 A-frags (registers only)
        const int   dbase = qt * QT_ - kt * KT_;
        const float f     = exp2f(lg * (float)dbase);
        const float fr0   = f * grow0;
        const float fr1   = f * grow1;
        const bool  edge  = (dbase < KT_);
        uint32_t SAh[4][4], SAl[4][4];
        #pragma unroll
        for (int p = 0; p < 8; p++) {
            const float c0 = gc[p], c1 = gc[p] * ginv;
            float v00 = sacc[p][0] * fr0 * c0;
            float v01 = sacc[p][1] * fr0 * c1;
            float v10 = sacc[p][2] * fr1 * c0;
            float v11 = sacc[p][3] * fr1 * c1;
            if (edge) {
                const int tl0 = p * 8 + (lane & 3) * 2;
                const int d00 = dbase + rl0 - tl0;
                if (d00 < 0)     v00 = 0.f;
                if (d00 - 1 < 0) v01 = 0.f;
                if (d00 + 8 < 0) v10 = 0.f;
                if (d00 + 7 < 0) v11 = 0.f;
            }
            const int j = p >> 1, o = (p & 1) * 2;
            SAh[j][o]     = pack2_hilo(v00, v01, SAl[j][o]);
            SAh[j][o + 1] = pack2_hilo(v10, v11, SAl[j][o + 1]);
        }

        // ---- O += S @ V (hi/lo 3-pass), V via ldmatrix.trans
        #pragma unroll
        for (int j = 0; j < 4; j++) {
            uint32_t vr = j * 16 + vrow;
            #pragma unroll
            for (int g = 0; g < 4; g++) {
                uint32_t va = (uint32_t)sb + OFF_VH + vr * 128
                            + (((2*g + vnb) ^ (vr & 7)) << 4);
                uint32_t bvh[4], bvl[4];
                LDSM4T(bvh, va);
                mma_bf16(oacc[2*g],   SAh[j], bvh[0], bvh[1]);
                mma_bf16(oacc[2*g+1], SAh[j], bvh[2], bvh[3]);
                mma_bf16(oacc[2*g],   SAl[j], bvh[0], bvh[1]);
                mma_bf16(oacc[2*g+1], SAl[j], bvh[2], bvh[3]);
                LDSM4T(bvl, va + (OFF_VL - OFF_VH));
                mma_bf16(oacc[2*g],   SAh[j], bvl[0], bvl[1]);
                mma_bf16(oacc[2*g+1], SAh[j], bvl[2], bvl[3]);
            }
        }
    }

    // ---- epilogue: y = O * silu(g) -> bf16 hi/lo
    const size_t row0 = (size_t)(b * S_ + qt * QT_ + rl0);
    #pragma unroll
    for (int p = 0; p < 8; p++) {
        const int col = h * DH_ + p * 8 + (lane & 3) * 2;
        #pragma unroll
        for (int half = 0; half < 2; half++) {
            const size_t idx = (row0 + half * 8) * D_ + col;
            float2 gv = *(const float2*)(g_g + idx);
            float s0 = gv.x / (1.f + expf(-gv.x));
            float s1 = gv.y / (1.f + expf(-gv.y));
            float y0 = oacc[p][half*2 + 0] * s0;
            float y1 = oacc[p][half*2 + 1] * s1;
            uint32_t lo;
            uint32_t hi = pack2_hilo(y0, y1, lo);
            *(uint32_t*)&g_aoh[idx] = hi;
            *(uint32_t*)&g_aol[idx] = lo;
        }
    }
}

// ============================================================================
extern "C" void kernel_launch(void* const* d_in, const int* in_sizes, int n_in,
                              void* d_out, int out_size)
{
    const float* x  = (const float*)d_in[0];
    const float* wq = (const float*)d_in[1];
    const float* wk = (const float*)d_in[2];
    const float* wv = (const float*)d_in[3];
    const float* wg = (const float*)d_in[4];
    const float* wo = (const float*)d_in[5];
    float* out = (float*)d_out;

    cudaFuncSetAttribute(gemm_qkvg_bf,
                         cudaFuncAttributeMaxDynamicSharedMemorySize, GEMM_SMEM);
    cudaFuncSetAttribute(gemm_out_bf,
                         cudaFuncAttributeMaxDynamicSharedMemorySize, GEMM_SMEM);
    cudaFuncSetAttribute(attn_kernel,
                         cudaFuncAttributeMaxDynamicSharedMemorySize, ATTN_SMEM);

    split_kernel<<<dim3(M_*D_/4/256, 6), 256>>>(x, wq, wk, wv, wg, wo);

    gemm_qkvg_bf<<<dim3(D_/128, M_/128, 4), 256, GEMM_SMEM>>>();

    int nrope = M_ * H_ * 32;
    rope_kernel<<<(nrope + 255) / 256, 256>>>();

    attn_kernel<<<dim3(S_/QT_, H_, B_), 256, ATTN_SMEM>>>();

    gemm_out_bf<<<dim3(D_/128, M_/128), 256, GEMM_SMEM>>>(out);
}

// round 7
// speedup vs baseline: 1.1995x; 1.1859x over previous
#include <cuda_runtime.h>
#include <cuda_bf16.h>
#include <stdint.h>
#include <math.h>

#define B_  2
#define S_  2048
#define D_  1024
#define H_  16
#define DH_ 64
#define M_  (B_*S_)   /* 4096 */

// ---- scratch (static device allocations; no cudaMalloc allowed) ----
__device__ __align__(16) float g_q [M_*D_];
__device__ __align__(16) float g_k [M_*D_];
__device__ __align__(16) float g_g [M_*D_];

// bf16 hi/lo split operands
__device__ __align__(16) __nv_bfloat16 g_qh [M_*D_], g_ql [M_*D_];
__device__ __align__(16) __nv_bfloat16 g_kh [M_*D_], g_kl [M_*D_];
__device__ __align__(16) __nv_bfloat16 g_vh [M_*D_], g_vl [M_*D_];
__device__ __align__(16) __nv_bfloat16 g_xh [M_*D_], g_xl [M_*D_];
__device__ __align__(16) __nv_bfloat16 g_aoh[M_*D_], g_aol[M_*D_];
__device__ __align__(16) __nv_bfloat16 g_wqh[D_*D_], g_wql[D_*D_];
__device__ __align__(16) __nv_bfloat16 g_wkh[D_*D_], g_wkl[D_*D_];
__device__ __align__(16) __nv_bfloat16 g_wvh[D_*D_], g_wvl[D_*D_];
__device__ __align__(16) __nv_bfloat16 g_wgh[D_*D_], g_wgl[D_*D_];
__device__ __align__(16) __nv_bfloat16 g_woh[D_*D_], g_wol[D_*D_];

// ============================================================================
// PTX helpers
// ============================================================================
__device__ __forceinline__ uint32_t smem_u32(const void* p)
{
    uint32_t a;
    asm("{ .reg .u64 t; cvta.to.shared.u64 t, %1; cvt.u32.u64 %0, t; }"
        : "=r"(a) : "l"(p));
    return a;
}

__device__ __forceinline__ void cp16(uint32_t s, const void* g)
{
    asm volatile("cp.async.cg.shared.global [%0], [%1], 16;" :: "r"(s), "l"(g));
}
#define CP_COMMIT() asm volatile("cp.async.commit_group;" ::: "memory")
template<int N> __device__ __forceinline__ void cp_wait()
{
    asm volatile("cp.async.wait_group %0;" :: "n"(N) : "memory");
}

#define LDSM4(r, addr) \
    asm volatile("ldmatrix.sync.aligned.m8n8.x4.shared.b16 {%0,%1,%2,%3}, [%4];" \
        : "=r"((r)[0]), "=r"((r)[1]), "=r"((r)[2]), "=r"((r)[3]) : "r"(addr))

#define LDSM4T(r, addr) \
    asm volatile("ldmatrix.sync.aligned.m8n8.x4.trans.shared.b16 {%0,%1,%2,%3}, [%4];" \
        : "=r"((r)[0]), "=r"((r)[1]), "=r"((r)[2]), "=r"((r)[3]) : "r"(addr))

__device__ __forceinline__ void mma_bf16(float c[4], const uint32_t a[4],
                                         uint32_t b0, uint32_t b1)
{
    asm volatile(
        "mma.sync.aligned.m16n8k16.row.col.f32.bf16.bf16.f32 "
        "{%0,%1,%2,%3},{%4,%5,%6,%7},{%8,%9},{%0,%1,%2,%3};"
        : "+f"(c[0]), "+f"(c[1]), "+f"(c[2]), "+f"(c[3])
        : "r"(a[0]), "r"(a[1]), "r"(a[2]), "r"(a[3]), "r"(b0), "r"(b1));
}

__device__ __forceinline__ uint32_t pack2_hilo(float a, float b, uint32_t& lo)
{
    __nv_bfloat16 ha = __float2bfloat16(a), hb = __float2bfloat16(b);
    float ra = a - __bfloat162float(ha);
    float rb = b - __bfloat162float(hb);
    __nv_bfloat16 la = __float2bfloat16(ra), lb = __float2bfloat16(rb);
    lo = (uint32_t)__bfloat16_as_ushort(la) | ((uint32_t)__bfloat16_as_ushort(lb) << 16);
    return (uint32_t)__bfloat16_as_ushort(ha) | ((uint32_t)__bfloat16_as_ushort(hb) << 16);
}

__device__ __forceinline__ uint32_t bf_split_hi(float a, float& rem)
{
    __nv_bfloat16 h = __float2bfloat16(a);
    rem = a - __bfloat162float(h);
    return (uint32_t)__bfloat16_as_ushort(h);
}

// ============================================================================
// hi/lo bf16 split kernel for x + weights
// ============================================================================
__global__ void split_kernel(const float* __restrict__ x,
                             const float* __restrict__ wq, const float* __restrict__ wk,
                             const float* __restrict__ wv, const float* __restrict__ wg,
                             const float* __restrict__ wo)
{
    const float* src;
    __nv_bfloat16 *dh, *dl;
    int n4;
    switch (blockIdx.y) {
        case 0: src = x;  dh = g_xh;  dl = g_xl;  n4 = M_*D_/4; break;
        case 1: src = wq; dh = g_wqh; dl = g_wql; n4 = D_*D_/4; break;
        case 2: src = wk; dh = g_wkh; dl = g_wkl; n4 = D_*D_/4; break;
        case 3: src = wv; dh = g_wvh; dl = g_wvl; n4 = D_*D_/4; break;
        case 4: src = wg; dh = g_wgh; dl = g_wgl; n4 = D_*D_/4; break;
        default:src = wo; dh = g_woh; dl = g_wol; n4 = D_*D_/4; break;
    }
    int i4 = blockIdx.x * blockDim.x + threadIdx.x;
    if (i4 >= n4) return;
    float4 v = ((const float4*)src)[i4];
    float r0, r1, r2, r3, d0;
    uint32_t h0 = bf_split_hi(v.x, r0), h1 = bf_split_hi(v.y, r1);
    uint32_t h2 = bf_split_hi(v.z, r2), h3 = bf_split_hi(v.w, r3);
    uint32_t l0 = bf_split_hi(r0, d0), l1 = bf_split_hi(r1, d0);
    uint32_t l2 = bf_split_hi(r2, d0), l3 = bf_split_hi(r3, d0);
    ((uint2*)dh)[i4] = make_uint2(h0 | (h1 << 16), h2 | (h3 << 16));
    ((uint2*)dl)[i4] = make_uint2(l0 | (l1 << 16), l2 | (l3 << 16));
}

// ============================================================================
// bf16 split GEMM: C = A @ W^T, 3-pass hi/lo. OM=0: float C. OM=1: hilo bf16.
// ============================================================================
#define BKH     32
#define NITG    (D_/BKH)
#define TILE_HB (128*BKH*2)
#define STAGE_B (4*TILE_HB)
#define NSTG    3
#define GEMM_SMEM (NSTG*STAGE_B)

struct GemmSrcs { const __nv_bfloat16 *ah, *al, *bh, *bl; };

__device__ __forceinline__ void issue_stage(uint32_t sb, int stage, int k0,
                                            const GemmSrcs& s, int tid)
{
    const __nv_bfloat16* srcs[4] = { s.ah, s.al, s.bh, s.bl };
    const uint32_t stg = sb + stage * STAGE_B;
    #pragma unroll
    for (int m = 0; m < 4; m++) {
        const __nv_bfloat16* src = srcs[m] + k0;
        const uint32_t tb = stg + m * TILE_HB;
        #pragma unroll
        for (int i = 0; i < 2; i++) {
            int j   = tid + i * 256;
            int row = j >> 2;
            int c   = j & 3;
            int csw = c ^ ((row >> 1) & 3);
            cp16(tb + row * 64 + csw * 16, src + (size_t)row * D_ + c * 8);
        }
    }
}

template<int OM>
__device__ __forceinline__ void gemm_bf16_body(const GemmSrcs& s, float* C,
                                               __nv_bfloat16* Ch, __nv_bfloat16* Cl)
{
    extern __shared__ char dsm[];
    const uint32_t sb = smem_u32(dsm);
    const int tid  = threadIdx.x;
    const int lane = tid & 31;
    const int w    = tid >> 5;
    const int wm   = (w >> 2) * 64;
    const int wn   = (w & 3) * 32;

    const int l7 = lane & 7;
    uint32_t aoff[4], asw[4], boff[2], bsw[2];
    const int akb = (lane >> 4) & 1;
    const int bkb = (lane >> 3) & 1;
    #pragma unroll
    for (int mf = 0; mf < 4; mf++) {
        int row = wm + mf * 16 + l7 + 8 * ((lane >> 3) & 1);
        aoff[mf] = row * 64;
        asw[mf]  = (row >> 1) & 3;
    }
    #pragma unroll
    for (int nfp = 0; nfp < 2; nfp++) {
        int row = wn + nfp * 16 + l7 + 8 * ((lane >> 4) & 1);
        boff[nfp] = row * 64;
        bsw[nfp]  = (row >> 1) & 3;
    }

    float acc[4][4][4];
    #pragma unroll
    for (int i = 0; i < 4; i++)
        #pragma unroll
        for (int j = 0; j < 4; j++)
            #pragma unroll
            for (int r = 0; r < 4; r++) acc[i][j][r] = 0.f;

    issue_stage(sb, 0, 0, s, tid);   CP_COMMIT();
    issue_stage(sb, 1, BKH, s, tid); CP_COMMIT();

    for (int it = 0; it < NITG; it++) {
        if (it == NITG - 1) cp_wait<0>(); else cp_wait<1>();
        __syncthreads();
        if (it + 2 < NITG) issue_stage(sb, (it + 2) % NSTG, (it + 2) * BKH, s, tid);
        CP_COMMIT();

        const uint32_t stg = sb + (it % NSTG) * STAGE_B;
        const uint32_t sAh = stg, sAl = stg + TILE_HB;
        const uint32_t sBh = stg + 2*TILE_HB, sBl = stg + 3*TILE_HB;

        #pragma unroll
        for (int ks = 0; ks < 2; ks++) {
            uint32_t ah[4][4], al[4][4], bh[2][4], bl[2][4];
            #pragma unroll
            for (int mf = 0; mf < 4; mf++) {
                uint32_t off = aoff[mf] + ((((uint32_t)(2*ks + akb)) ^ asw[mf]) << 4);
                LDSM4(ah[mf], sAh + off);
                LDSM4(al[mf], sAl + off);
            }
            #pragma unroll
            for (int nfp = 0; nfp < 2; nfp++) {
                uint32_t off = boff[nfp] + ((((uint32_t)(2*ks + bkb)) ^ bsw[nfp]) << 4);
                LDSM4(bh[nfp], sBh + off);
                LDSM4(bl[nfp], sBl + off);
            }
            #pragma unroll
            for (int mf = 0; mf < 4; mf++)
                #pragma unroll
                for (int nf = 0; nf < 4; nf++) {
                    uint32_t bh0 = bh[nf >> 1][(nf & 1)*2], bh1 = bh[nf >> 1][(nf & 1)*2 + 1];
                    uint32_t bl0 = bl[nf >> 1][(nf & 1)*2], bl1 = bl[nf >> 1][(nf & 1)*2 + 1];
                    mma_bf16(acc[mf][nf], ah[mf], bh0, bh1);
                    mma_bf16(acc[mf][nf], al[mf], bh0, bh1);
                    mma_bf16(acc[mf][nf], ah[mf], bl0, bl1);
                }
        }
        __syncthreads();
    }

    const int rbase = blockIdx.y * 128 + wm + (lane >> 2);
    const int cbase = blockIdx.x * 128 + wn + ((lane & 3) << 1);
    #pragma unroll
    for (int mf = 0; mf < 4; mf++)
        #pragma unroll
        for (int nf = 0; nf < 4; nf++) {
            const size_t i0 = (size_t)(rbase + mf*16) * D_ + cbase + nf*8;
            const size_t i1 = i0 + (size_t)8 * D_;
            if (OM == 0) {
                *(float2*)(C + i0) = make_float2(acc[mf][nf][0], acc[mf][nf][1]);
                *(float2*)(C + i1) = make_float2(acc[mf][nf][2], acc[mf][nf][3]);
            } else {
                uint32_t lo0, lo1;
                uint32_t hi0 = pack2_hilo(acc[mf][nf][0], acc[mf][nf][1], lo0);
                uint32_t hi1 = pack2_hilo(acc[mf][nf][2], acc[mf][nf][3], lo1);
                *(uint32_t*)&Ch[i0] = hi0; *(uint32_t*)&Cl[i0] = lo0;
                *(uint32_t*)&Ch[i1] = hi1; *(uint32_t*)&Cl[i1] = lo1;
            }
        }
}

__global__ __launch_bounds__(256, 1)
void gemm_qkvg_bf()
{
    GemmSrcs s;
    const size_t yoff = (size_t)blockIdx.y * 128 * D_;
    const size_t xoff = (size_t)blockIdx.x * 128 * D_;
    s.ah = g_xh + yoff; s.al = g_xl + yoff;
    if (blockIdx.z == 2) {
        s.bh = g_wvh + xoff; s.bl = g_wvl + xoff;
        gemm_bf16_body<1>(s, nullptr, g_vh, g_vl);
        return;
    }
    float* C;
    switch (blockIdx.z) {
        case 0:  s.bh = g_wqh + xoff; s.bl = g_wql + xoff; C = g_q; break;
        case 1:  s.bh = g_wkh + xoff; s.bl = g_wkl + xoff; C = g_k; break;
        default: s.bh = g_wgh + xoff; s.bl = g_wgl + xoff; C = g_g; break;
    }
    gemm_bf16_body<0>(s, C, nullptr, nullptr);
}

__global__ __launch_bounds__(256, 1)
void gemm_out_bf(float* __restrict__ C)
{
    GemmSrcs s;
    const size_t yoff = (size_t)blockIdx.y * 128 * D_;
    const size_t xoff = (size_t)blockIdx.x * 128 * D_;
    s.ah = g_aoh + yoff; s.al = g_aol + yoff;
    s.bh = g_woh + xoff; s.bl = g_wol + xoff;
    gemm_bf16_body<0>(s, C, nullptr, nullptr);
}

// ============================================================================
// RoPE: read float q/k, write rotated values as bf16 hi/lo
// ============================================================================
__global__ void rope_kernel()
{
    int i = blockIdx.x * blockDim.x + threadIdx.x;
    if (i >= M_ * H_ * 32) return;
    int j  = i & 31;
    int h  = (i >> 5) & (H_ - 1);
    int bs = i >> 9;
    int s  = bs & (S_ - 1);

    float inv = exp2f(-(float)j * 0.41524101186092029f);
    float ang = (float)s * inv;
    float sn, cs;
    sincosf(ang, &sn, &cs);

    int base = bs * D_ + h * DH_ + j;
    float q1 = g_q[base], q2 = g_q[base + 32];
    float k1 = g_k[base], k2 = g_k[base + 32];
    float qo1 = q1 * cs - q2 * sn, qo2 = q2 * cs + q1 * sn;
    float ko1 = k1 * cs - k2 * sn, ko2 = k2 * cs + k1 * sn;

    float r;
    g_qh[base]      = __ushort_as_bfloat16((unsigned short)bf_split_hi(qo1, r));
    g_ql[base]      = __float2bfloat16(r);
    g_qh[base + 32] = __ushort_as_bfloat16((unsigned short)bf_split_hi(qo2, r));
    g_ql[base + 32] = __float2bfloat16(r);
    g_kh[base]      = __ushort_as_bfloat16((unsigned short)bf_split_hi(ko1, r));
    g_kl[base]      = __float2bfloat16(r);
    g_kh[base + 32] = __ushort_as_bfloat16((unsigned short)bf_split_hi(ko2, r));
    g_kl[base + 32] = __float2bfloat16(r);
}

// ============================================================================
// bf16 hi/lo flash retention, cp.async double-buffered K/V.
// CTA = 128 q-rows x (h,b). 256 threads, 8 warps; warp owns 16 q-rows.
// smem: Qh 16K | Ql 16K | 2 stages x (Kh 8K | Kl 8K | Vh 8K | Vl 8K) = 96 KB
// ============================================================================
#define QT_ 128
#define KT_ 64
#define OFF_QH 0
#define OFF_QL 16384
#define OFF_ST 32768
#define STG_SZ 32768
#define ATTN_SMEM 98304

__device__ __forceinline__ void attn_issue_q(uint32_t sb, const __nv_bfloat16* qh,
                                             const __nv_bfloat16* ql, int tid)
{
    #pragma unroll
    for (int m = 0; m < 2; m++) {
        const __nv_bfloat16* src = m ? ql : qh;
        const uint32_t off = sb + (m ? OFF_QL : OFF_QH);
        #pragma unroll
        for (int i = 0; i < 4; i++) {
            int u   = tid + i * 256;          // 0..1023
            int row = u >> 3;
            int c   = u & 7;
            int cs  = c ^ (row & 7);
            cp16(off + row * 128 + cs * 16, src + (size_t)row * D_ + c * 8);
        }
    }
}

__device__ __forceinline__ void attn_issue_kv(uint32_t sb, int stage, int kt,
                                              const __nv_bfloat16* kh,
                                              const __nv_bfloat16* kl,
                                              const __nv_bfloat16* vh,
                                              const __nv_bfloat16* vl, int tid)
{
    const __nv_bfloat16* srcs[4] = {
        kh + (size_t)(kt * KT_) * D_, kl + (size_t)(kt * KT_) * D_,
        vh + (size_t)(kt * KT_) * D_, vl + (size_t)(kt * KT_) * D_ };
    const uint32_t stg = sb + OFF_ST + stage * STG_SZ;
    #pragma unroll
    for (int m = 0; m < 4; m++) {
        const __nv_bfloat16* src = srcs[m];
        const uint32_t tb = stg + m * 8192;
        #pragma unroll
        for (int i = 0; i < 2; i++) {
            int u   = tid + i * 256;          // 0..511
            int row = u >> 3;
            int c   = u & 7;
            int cs  = c ^ (row & 7);
            cp16(tb + row * 128 + cs * 16, src + (size_t)row * D_ + c * 8);
        }
    }
}

__global__ __launch_bounds__(256, 2)
void attn_kernel()
{
    extern __shared__ char dsm[];
    const uint32_t sb = smem_u32(dsm);

    // global heavy-first: all (h,b) of the heaviest qt launch first
    const int idx = blockIdx.x;
    const int qt  = (S_/QT_ - 1) - (idx >> 5);
    const int h   = idx & 15;
    const int b   = (idx >> 4) & 1;

    const int tid  = threadIdx.x;
    const int lane = tid & 31;
    const int w    = tid >> 5;
    const int l7   = lane & 7;

    const float gamma = 1.0f - exp2f(-5.0f - (float)h);
    const float lg    = log2f(gamma);

    const size_t qoff = (size_t)(b * S_ + qt * QT_) * D_ + h * DH_;
    const size_t koff = (size_t)(b * S_) * D_ + h * DH_;
    const int nkt = 2 * qt + 2;

    // pipeline prologue
    attn_issue_q(sb, g_qh + qoff, g_ql + qoff, tid);
    attn_issue_kv(sb, 0, 0, g_kh + koff, g_kl + koff, g_vh + koff, g_vl + koff, tid);
    CP_COMMIT();
    if (nkt > 1)
        attn_issue_kv(sb, 1, 1, g_kh + koff, g_kl + koff, g_vh + koff, g_vl + koff, tid);
    CP_COMMIT();

    // per-thread decay constants
    const int rl0 = w * 16 + (lane >> 2);
    const float grow0 = 0.125f * exp2f(lg * (float)rl0);
    const float grow1 = 0.125f * exp2f(lg * (float)(rl0 + 8));
    const float ginv  = exp2f(-lg);
    float gc[8];
    #pragma unroll
    for (int p = 0; p < 8; p++)
        gc[p] = exp2f(-lg * (float)(p * 8 + (lane & 3) * 2));

    float oacc[8][4];
    #pragma unroll
    for (int p = 0; p < 8; p++)
        #pragma unroll
        for (int r = 0; r < 4; r++) oacc[p][r] = 0.f;

    const uint32_t arow = (uint32_t)(w * 16 + l7 + 8 * ((lane >> 3) & 1));
    const uint32_t akb  = (lane >> 4) & 1;
    const uint32_t brow = (uint32_t)(l7 + 8 * ((lane >> 4) & 1));
    const uint32_t bkb  = (lane >> 3) & 1;
    const uint32_t vrow = (uint32_t)(l7 + 8 * ((lane >> 3) & 1));
    const uint32_t vnb  = (lane >> 4) & 1;

    for (int kt = 0; kt < nkt; kt++) {
        cp_wait<1>();
        __syncthreads();

        const uint32_t stg = sb + OFF_ST + (kt & 1) * STG_SZ;
        const uint32_t sKH = stg, sKL = stg + 8192;
        const uint32_t sVH = stg + 16384, sVL = stg + 24576;

        // ---- S = Q K^T (hi/lo 3-pass), S in registers
        float sacc[8][4];
        #pragma unroll
        for (int p = 0; p < 8; p++)
            #pragma unroll
            for (int r = 0; r < 4; r++) sacc[p][r] = 0.f;

        #pragma unroll
        for (int ks = 0; ks < 4; ks++) {
            uint32_t qa = sb + OFF_QH + arow * 128 + (((2*ks + akb) ^ (arow & 7)) << 4);
            uint32_t ah[4], al[4];
            LDSM4(ah, qa);
            LDSM4(al, qa + (OFF_QL - OFF_QH));
            #pragma unroll
            for (int g = 0; g < 4; g++) {
                uint32_t br = g * 16 + brow;
                uint32_t ba = sKH + br * 128 + (((2*ks + bkb) ^ (br & 7)) << 4);
                uint32_t bh[4], bl[4];
                LDSM4(bh, ba);
                mma_bf16(sacc[2*g],   ah, bh[0], bh[1]);
                mma_bf16(sacc[2*g+1], ah, bh[2], bh[3]);
                mma_bf16(sacc[2*g],   al, bh[0], bh[1]);
                mma_bf16(sacc[2*g+1], al, bh[2], bh[3]);
                LDSM4(bl, ba + (sKL - sKH));
                mma_bf16(sacc[2*g],   ah, bl[0], bl[1]);
                mma_bf16(sacc[2*g+1], ah, bl[2], bl[3]);
            }
        }

        // ---- decay + causal mask + split to bf16 A-frags (registers only)
        const int   dbase = qt * QT_ - kt * KT_;
        const float f     = exp2f(lg * (float)dbase);
        const float fr0   = f * grow0;
        const float fr1   = f * grow1;
        const bool  edge  = (dbase < KT_);
        uint32_t SAh[4][4], SAl[4][4];
        #pragma unroll
        for (int p = 0; p < 8; p++) {
            const float c0 = gc[p], c1 = gc[p] * ginv;
            float v00 = sacc[p][0] * fr0 * c0;
            float v01 = sacc[p][1] * fr0 * c1;
            float v10 = sacc[p][2] * fr1 * c0;
            float v11 = sacc[p][3] * fr1 * c1;
            if (edge) {
                const int tl0 = p * 8 + (lane & 3) * 2;
                const int d00 = dbase + rl0 - tl0;
                if (d00 < 0)     v00 = 0.f;
                if (d00 - 1 < 0) v01 = 0.f;
                if (d00 + 8 < 0) v10 = 0.f;
                if (d00 + 7 < 0) v11 = 0.f;
            }
            const int j = p >> 1, o = (p & 1) * 2;
            SAh[j][o]     = pack2_hilo(v00, v01, SAl[j][o]);
            SAh[j][o + 1] = pack2_hilo(v10, v11, SAl[j][o + 1]);
        }

        // ---- O += S @ V (hi/lo 3-pass), V via ldmatrix.trans
        #pragma unroll
        for (int j = 0; j < 4; j++) {
            uint32_t vr = j * 16 + vrow;
            #pragma unroll
            for (int g = 0; g < 4; g++) {
                uint32_t va = sVH + vr * 128 + (((2*g + vnb) ^ (vr & 7)) << 4);
                uint32_t bvh[4], bvl[4];
                LDSM4T(bvh, va);
                mma_bf16(oacc[2*g],   SAh[j], bvh[0], bvh[1]);
                mma_bf16(oacc[2*g+1], SAh[j], bvh[2], bvh[3]);
                mma_bf16(oacc[2*g],   SAl[j], bvh[0], bvh[1]);
                mma_bf16(oacc[2*g+1], SAl[j], bvh[2], bvh[3]);
                LDSM4T(bvl, va + (sVL - sVH));
                mma_bf16(oacc[2*g],   SAh[j], bvl[0], bvl[1]);
                mma_bf16(oacc[2*g+1], SAh[j], bvl[2], bvl[3]);
            }
        }

        __syncthreads();
        if (kt + 2 < nkt)
            attn_issue_kv(sb, kt & 1, kt + 2,
                          g_kh + koff, g_kl + koff, g_vh + koff, g_vl + koff, tid);
        CP_COMMIT();   // empty-group commit keeps wait_group<1> correct at tail
    }

    // ---- epilogue: y = O * silu(g) -> bf16 hi/lo
    const size_t row0 = (size_t)(b * S_ + qt * QT_ + rl0);
    #pragma unroll
    for (int p = 0; p < 8; p++) {
        const int col = h * DH_ + p * 8 + (lane & 3) * 2;
        #pragma unroll
        for (int half = 0; half < 2; half++) {
            const size_t idx2 = (row0 + half * 8) * D_ + col;
            float2 gv = *(const float2*)(g_g + idx2);
            float s0 = gv.x / (1.f + expf(-gv.x));
            float s1 = gv.y / (1.f + expf(-gv.y));
            float y0 = oacc[p][half*2 + 0] * s0;
            float y1 = oacc[p][half*2 + 1] * s1;
            uint32_t lo;
            uint32_t hi = pack2_hilo(y0, y1, lo);
            *(uint32_t*)&g_aoh[idx2] = hi;
            *(uint32_t*)&g_aol[idx2] = lo;
        }
    }
}

// ============================================================================
extern "C" void kernel_launch(void* const* d_in, const int* in_sizes, int n_in,
                              void* d_out, int out_size)
{
    const float* x  = (const float*)d_in[0];
    const float* wq = (const float*)d_in[1];
    const float* wk = (const float*)d_in[2];
    const float* wv = (const float*)d_in[3];
    const float* wg = (const float*)d_in[4];
    const float* wo = (const float*)d_in[5];
    float* out = (float*)d_out;

    cudaFuncSetAttribute(gemm_qkvg_bf,
                         cudaFuncAttributeMaxDynamicSharedMemorySize, GEMM_SMEM);
    cudaFuncSetAttribute(gemm_out_bf,
                         cudaFuncAttributeMaxDynamicSharedMemorySize, GEMM_SMEM);
    cudaFuncSetAttribute(attn_kernel,
                         cudaFuncAttributeMaxDynamicSharedMemorySize, ATTN_SMEM);

    split_kernel<<<dim3(M_*D_/4/256, 6), 256>>>(x, wq, wk, wv, wg, wo);

    gemm_qkvg_bf<<<dim3(D_/128, M_/128, 4), 256, GEMM_SMEM>>>();

    int nrope = M_ * H_ * 32;
    rope_kernel<<<(nrope + 255) / 256, 256>>>();

    attn_kernel<<<(S_/QT_) * H_ * B_, 256, ATTN_SMEM>>>();

    gemm_out_bf<<<dim3(D_/128, M_/128), 256, GEMM_SMEM>>>(out);
}

// round 8
// speedup vs baseline: 1.3791x; 1.1497x over previous
#include <cuda_runtime.h>
#include <cuda_bf16.h>
#include <stdint.h>
#include <math.h>

#define B_  2
#define S_  2048
#define D_  1024
#define H_  16
#define DH_ 64
#define M_  (B_*S_)   /* 4096 */

// ---- scratch (static device allocations; no cudaMalloc allowed) ----
__device__ __align__(16) float g_q [M_*D_];
__device__ __align__(16) float g_k [M_*D_];
__device__ __align__(16) float g_g [M_*D_];

// bf16 hi/lo split operands
__device__ __align__(16) __nv_bfloat16 g_qh [M_*D_], g_ql [M_*D_];
__device__ __align__(16) __nv_bfloat16 g_kh [M_*D_], g_kl [M_*D_];
__device__ __align__(16) __nv_bfloat16 g_vh [M_*D_], g_vl [M_*D_];
__device__ __align__(16) __nv_bfloat16 g_xh [M_*D_], g_xl [M_*D_];
__device__ __align__(16) __nv_bfloat16 g_aoh[M_*D_], g_aol[M_*D_];
__device__ __align__(16) __nv_bfloat16 g_wqh[D_*D_], g_wql[D_*D_];
__device__ __align__(16) __nv_bfloat16 g_wkh[D_*D_], g_wkl[D_*D_];
__device__ __align__(16) __nv_bfloat16 g_wvh[D_*D_], g_wvl[D_*D_];
__device__ __align__(16) __nv_bfloat16 g_wgh[D_*D_], g_wgl[D_*D_];
__device__ __align__(16) __nv_bfloat16 g_woh[D_*D_], g_wol[D_*D_];

// ============================================================================
// PTX helpers
// ============================================================================
__device__ __forceinline__ uint32_t smem_u32(const void* p)
{
    uint32_t a;
    asm("{ .reg .u64 t; cvta.to.shared.u64 t, %1; cvt.u32.u64 %0, t; }"
        : "=r"(a) : "l"(p));
    return a;
}

__device__ __forceinline__ void cp16(uint32_t s, const void* g)
{
    asm volatile("cp.async.cg.shared.global [%0], [%1], 16;" :: "r"(s), "l"(g));
}
#define CP_COMMIT() asm volatile("cp.async.commit_group;" ::: "memory")
template<int N> __device__ __forceinline__ void cp_wait()
{
    asm volatile("cp.async.wait_group %0;" :: "n"(N) : "memory");
}

#define LDSM4(r, addr) \
    asm volatile("ldmatrix.sync.aligned.m8n8.x4.shared.b16 {%0,%1,%2,%3}, [%4];" \
        : "=r"((r)[0]), "=r"((r)[1]), "=r"((r)[2]), "=r"((r)[3]) : "r"(addr))

#define LDSM4T(r, addr) \
    asm volatile("ldmatrix.sync.aligned.m8n8.x4.trans.shared.b16 {%0,%1,%2,%3}, [%4];" \
        : "=r"((r)[0]), "=r"((r)[1]), "=r"((r)[2]), "=r"((r)[3]) : "r"(addr))

__device__ __forceinline__ void mma_bf16(float c[4], const uint32_t a[4],
                                         uint32_t b0, uint32_t b1)
{
    asm volatile(
        "mma.sync.aligned.m16n8k16.row.col.f32.bf16.bf16.f32 "
        "{%0,%1,%2,%3},{%4,%5,%6,%7},{%8,%9},{%0,%1,%2,%3};"
        : "+f"(c[0]), "+f"(c[1]), "+f"(c[2]), "+f"(c[3])
        : "r"(a[0]), "r"(a[1]), "r"(a[2]), "r"(a[3]), "r"(b0), "r"(b1));
}

__device__ __forceinline__ uint32_t pack2_hilo(float a, float b, uint32_t& lo)
{
    __nv_bfloat16 ha = __float2bfloat16(a), hb = __float2bfloat16(b);
    float ra = a - __bfloat162float(ha);
    float rb = b - __bfloat162float(hb);
    __nv_bfloat16 la = __float2bfloat16(ra), lb = __float2bfloat16(rb);
    lo = (uint32_t)__bfloat16_as_ushort(la) | ((uint32_t)__bfloat16_as_ushort(lb) << 16);
    return (uint32_t)__bfloat16_as_ushort(ha) | ((uint32_t)__bfloat16_as_ushort(hb) << 16);
}

__device__ __forceinline__ uint32_t bf_split_hi(float a, float& rem)
{
    __nv_bfloat16 h = __float2bfloat16(a);
    rem = a - __bfloat162float(h);
    return (uint32_t)__bfloat16_as_ushort(h);
}

// ============================================================================
// hi/lo bf16 split kernel for x + weights
// ============================================================================
__global__ void split_kernel(const float* __restrict__ x,
                             const float* __restrict__ wq, const float* __restrict__ wk,
                             const float* __restrict__ wv, const float* __restrict__ wg,
                             const float* __restrict__ wo)
{
    const float* src;
    __nv_bfloat16 *dh, *dl;
    int n4;
    switch (blockIdx.y) {
        case 0: src = x;  dh = g_xh;  dl = g_xl;  n4 = M_*D_/4; break;
        case 1: src = wq; dh = g_wqh; dl = g_wql; n4 = D_*D_/4; break;
        case 2: src = wk; dh = g_wkh; dl = g_wkl; n4 = D_*D_/4; break;
        case 3: src = wv; dh = g_wvh; dl = g_wvl; n4 = D_*D_/4; break;
        case 4: src = wg; dh = g_wgh; dl = g_wgl; n4 = D_*D_/4; break;
        default:src = wo; dh = g_woh; dl = g_wol; n4 = D_*D_/4; break;
    }
    int i4 = blockIdx.x * blockDim.x + threadIdx.x;
    if (i4 >= n4) return;
    float4 v = ((const float4*)src)[i4];
    float r0, r1, r2, r3, d0;
    uint32_t h0 = bf_split_hi(v.x, r0), h1 = bf_split_hi(v.y, r1);
    uint32_t h2 = bf_split_hi(v.z, r2), h3 = bf_split_hi(v.w, r3);
    uint32_t l0 = bf_split_hi(r0, d0), l1 = bf_split_hi(r1, d0);
    uint32_t l2 = bf_split_hi(r2, d0), l3 = bf_split_hi(r3, d0);
    ((uint2*)dh)[i4] = make_uint2(h0 | (h1 << 16), h2 | (h3 << 16));
    ((uint2*)dl)[i4] = make_uint2(l0 | (l1 << 16), l2 | (l3 << 16));
}

// ============================================================================
// bf16 split GEMM: C = A @ W^T, 3-pass hi/lo. OM=0: float C. OM=1: hilo bf16.
// 2 CTAs/SM (<=128 regs); inner loop keeps only 8 A-frag regs live.
// ============================================================================
#define BKH     32
#define NITG    (D_/BKH)
#define TILE_HB (128*BKH*2)
#define STAGE_B (4*TILE_HB)
#define NSTG    3
#define GEMM_SMEM (NSTG*STAGE_B)

struct GemmSrcs { const __nv_bfloat16 *ah, *al, *bh, *bl; };

__device__ __forceinline__ void issue_stage(uint32_t sb, int stage, int k0,
                                            const GemmSrcs& s, int tid)
{
    const __nv_bfloat16* srcs[4] = { s.ah, s.al, s.bh, s.bl };
    const uint32_t stg = sb + stage * STAGE_B;
    #pragma unroll
    for (int m = 0; m < 4; m++) {
        const __nv_bfloat16* src = srcs[m] + k0;
        const uint32_t tb = stg + m * TILE_HB;
        #pragma unroll
        for (int i = 0; i < 2; i++) {
            int j   = tid + i * 256;
            int row = j >> 2;
            int c   = j & 3;
            int csw = c ^ ((row >> 1) & 3);
            cp16(tb + row * 64 + csw * 16, src + (size_t)row * D_ + c * 8);
        }
    }
}

template<int OM>
__device__ __forceinline__ void gemm_bf16_body(const GemmSrcs& s, float* C,
                                               __nv_bfloat16* Ch, __nv_bfloat16* Cl)
{
    extern __shared__ char dsm[];
    const uint32_t sb = smem_u32(dsm);
    const int tid  = threadIdx.x;
    const int lane = tid & 31;
    const int w    = tid >> 5;
    const int wm   = (w >> 2) * 64;
    const int wn   = (w & 3) * 32;

    const int l7 = lane & 7;
    uint32_t aoff[4], asw[4], boff[2], bsw[2];
    const int akb = (lane >> 4) & 1;
    const int bkb = (lane >> 3) & 1;
    #pragma unroll
    for (int mf = 0; mf < 4; mf++) {
        int row = wm + mf * 16 + l7 + 8 * ((lane >> 3) & 1);
        aoff[mf] = row * 64;
        asw[mf]  = (row >> 1) & 3;
    }
    #pragma unroll
    for (int nfp = 0; nfp < 2; nfp++) {
        int row = wn + nfp * 16 + l7 + 8 * ((lane >> 4) & 1);
        boff[nfp] = row * 64;
        bsw[nfp]  = (row >> 1) & 3;
    }

    float acc[4][4][4];
    #pragma unroll
    for (int i = 0; i < 4; i++)
        #pragma unroll
        for (int j = 0; j < 4; j++)
            #pragma unroll
            for (int r = 0; r < 4; r++) acc[i][j][r] = 0.f;

    issue_stage(sb, 0, 0, s, tid);   CP_COMMIT();
    issue_stage(sb, 1, BKH, s, tid); CP_COMMIT();

    for (int it = 0; it < NITG; it++) {
        if (it == NITG - 1) cp_wait<0>(); else cp_wait<1>();
        __syncthreads();
        if (it + 2 < NITG) issue_stage(sb, (it + 2) % NSTG, (it + 2) * BKH, s, tid);
        CP_COMMIT();

        const uint32_t stg = sb + (it % NSTG) * STAGE_B;
        const uint32_t sAh = stg, sAl = stg + TILE_HB;
        const uint32_t sBh = stg + 2*TILE_HB, sBl = stg + 3*TILE_HB;

        #pragma unroll
        for (int ks = 0; ks < 2; ks++) {
            // B fragments for this k-step (live: 16 regs)
            uint32_t bh[2][4], bl[2][4];
            #pragma unroll
            for (int nfp = 0; nfp < 2; nfp++) {
                uint32_t off = boff[nfp] + ((((uint32_t)(2*ks + bkb)) ^ bsw[nfp]) << 4);
                LDSM4(bh[nfp], sBh + off);
                LDSM4(bl[nfp], sBl + off);
            }
            // stream A fragments per mf (live: 8 regs)
            #pragma unroll
            for (int mf = 0; mf < 4; mf++) {
                uint32_t off = aoff[mf] + ((((uint32_t)(2*ks + akb)) ^ asw[mf]) << 4);
                uint32_t ah[4], al[4];
                LDSM4(ah, sAh + off);
                LDSM4(al, sAl + off);
                #pragma unroll
                for (int nf = 0; nf < 4; nf++) {
                    uint32_t b0 = bh[nf >> 1][(nf & 1)*2], b1 = bh[nf >> 1][(nf & 1)*2 + 1];
                    uint32_t c0 = bl[nf >> 1][(nf & 1)*2], c1 = bl[nf >> 1][(nf & 1)*2 + 1];
                    mma_bf16(acc[mf][nf], ah, b0, b1);
                    mma_bf16(acc[mf][nf], al, b0, b1);
                    mma_bf16(acc[mf][nf], ah, c0, c1);
                }
            }
        }
        __syncthreads();
    }

    const int rbase = blockIdx.y * 128 + wm + (lane >> 2);
    const int cbase = blockIdx.x * 128 + wn + ((lane & 3) << 1);
    #pragma unroll
    for (int mf = 0; mf < 4; mf++)
        #pragma unroll
        for (int nf = 0; nf < 4; nf++) {
            const size_t i0 = (size_t)(rbase + mf*16) * D_ + cbase + nf*8;
            const size_t i1 = i0 + (size_t)8 * D_;
            if (OM == 0) {
                *(float2*)(C + i0) = make_float2(acc[mf][nf][0], acc[mf][nf][1]);
                *(float2*)(C + i1) = make_float2(acc[mf][nf][2], acc[mf][nf][3]);
            } else {
                uint32_t lo0, lo1;
                uint32_t hi0 = pack2_hilo(acc[mf][nf][0], acc[mf][nf][1], lo0);
                uint32_t hi1 = pack2_hilo(acc[mf][nf][2], acc[mf][nf][3], lo1);
                *(uint32_t*)&Ch[i0] = hi0; *(uint32_t*)&Cl[i0] = lo0;
                *(uint32_t*)&Ch[i1] = hi1; *(uint32_t*)&Cl[i1] = lo1;
            }
        }
}

__global__ __launch_bounds__(256, 2)
void gemm_qkvg_bf()
{
    GemmSrcs s;
    const size_t yoff = (size_t)blockIdx.y * 128 * D_;
    const size_t xoff = (size_t)blockIdx.x * 128 * D_;
    s.ah = g_xh + yoff; s.al = g_xl + yoff;
    if (blockIdx.z == 2) {
        s.bh = g_wvh + xoff; s.bl = g_wvl + xoff;
        gemm_bf16_body<1>(s, nullptr, g_vh, g_vl);
        return;
    }
    float* C;
    switch (blockIdx.z) {
        case 0:  s.bh = g_wqh + xoff; s.bl = g_wql + xoff; C = g_q; break;
        case 1:  s.bh = g_wkh + xoff; s.bl = g_wkl + xoff; C = g_k; break;
        default: s.bh = g_wgh + xoff; s.bl = g_wgl + xoff; C = g_g; break;
    }
    gemm_bf16_body<0>(s, C, nullptr, nullptr);
}

__global__ __launch_bounds__(256, 2)
void gemm_out_bf(float* __restrict__ C)
{
    GemmSrcs s;
    const size_t yoff = (size_t)blockIdx.y * 128 * D_;
    const size_t xoff = (size_t)blockIdx.x * 128 * D_;
    s.ah = g_aoh + yoff; s.al = g_aol + yoff;
    s.bh = g_woh + xoff; s.bl = g_wol + xoff;
    gemm_bf16_body<0>(s, C, nullptr, nullptr);
}

// ============================================================================
// RoPE: read float q/k, write rotated values as bf16 hi/lo
// ============================================================================
__global__ void rope_kernel()
{
    int i = blockIdx.x * blockDim.x + threadIdx.x;
    if (i >= M_ * H_ * 32) return;
    int j  = i & 31;
    int h  = (i >> 5) & (H_ - 1);
    int bs = i >> 9;
    int s  = bs & (S_ - 1);

    float inv = exp2f(-(float)j * 0.41524101186092029f);
    float ang = (float)s * inv;
    float sn, cs;
    sincosf(ang, &sn, &cs);

    int base = bs * D_ + h * DH_ + j;
    float q1 = g_q[base], q2 = g_q[base + 32];
    float k1 = g_k[base], k2 = g_k[base + 32];
    float qo1 = q1 * cs - q2 * sn, qo2 = q2 * cs + q1 * sn;
    float ko1 = k1 * cs - k2 * sn, ko2 = k2 * cs + k1 * sn;

    float r;
    g_qh[base]      = __ushort_as_bfloat16((unsigned short)bf_split_hi(qo1, r));
    g_ql[base]      = __float2bfloat16(r);
    g_qh[base + 32] = __ushort_as_bfloat16((unsigned short)bf_split_hi(qo2, r));
    g_ql[base + 32] = __float2bfloat16(r);
    g_kh[base]      = __ushort_as_bfloat16((unsigned short)bf_split_hi(ko1, r));
    g_kl[base]      = __float2bfloat16(r);
    g_kh[base + 32] = __ushort_as_bfloat16((unsigned short)bf_split_hi(ko2, r));
    g_kl[base + 32] = __float2bfloat16(r);
}

// ============================================================================
// bf16 hi/lo flash retention, cp.async double-buffered K/V (unchanged R7).
// ============================================================================
#define QT_ 128
#define KT_ 64
#define OFF_QH 0
#define OFF_QL 16384
#define OFF_ST 32768
#define STG_SZ 32768
#define ATTN_SMEM 98304

__device__ __forceinline__ void attn_issue_q(uint32_t sb, const __nv_bfloat16* qh,
                                             const __nv_bfloat16* ql, int tid)
{
    #pragma unroll
    for (int m = 0; m < 2; m++) {
        const __nv_bfloat16* src = m ? ql : qh;
        const uint32_t off = sb + (m ? OFF_QL : OFF_QH);
        #pragma unroll
        for (int i = 0; i < 4; i++) {
            int u   = tid + i * 256;
            int row = u >> 3;
            int c   = u & 7;
            int cs  = c ^ (row & 7);
            cp16(off + row * 128 + cs * 16, src + (size_t)row * D_ + c * 8);
        }
    }
}

__device__ __forceinline__ void attn_issue_kv(uint32_t sb, int stage, int kt,
                                              const __nv_bfloat16* kh,
                                              const __nv_bfloat16* kl,
                                              const __nv_bfloat16* vh,
                                              const __nv_bfloat16* vl, int tid)
{
    const __nv_bfloat16* srcs[4] = {
        kh + (size_t)(kt * KT_) * D_, kl + (size_t)(kt * KT_) * D_,
        vh + (size_t)(kt * KT_) * D_, vl + (size_t)(kt * KT_) * D_ };
    const uint32_t stg = sb + OFF_ST + stage * STG_SZ;
    #pragma unroll
    for (int m = 0; m < 4; m++) {
        const __nv_bfloat16* src = srcs[m];
        const uint32_t tb = stg + m * 8192;
        #pragma unroll
        for (int i = 0; i < 2; i++) {
            int u   = tid + i * 256;
            int row = u >> 3;
            int c   = u & 7;
            int cs  = c ^ (row & 7);
            cp16(tb + row * 128 + cs * 16, src + (size_t)row * D_ + c * 8);
        }
    }
}

__global__ __launch_bounds__(256, 2)
void attn_kernel()
{
    extern __shared__ char dsm[];
    const uint32_t sb = smem_u32(dsm);

    const int idx = blockIdx.x;
    const int qt  = (S_/QT_ - 1) - (idx >> 5);
    const int h   = idx & 15;
    const int b   = (idx >> 4) & 1;

    const int tid  = threadIdx.x;
    const int lane = tid & 31;
    const int w    = tid >> 5;
    const int l7   = lane & 7;

    const float gamma = 1.0f - exp2f(-5.0f - (float)h);
    const float lg    = log2f(gamma);

    const size_t qoff = (size_t)(b * S_ + qt * QT_) * D_ + h * DH_;
    const size_t koff = (size_t)(b * S_) * D_ + h * DH_;
    const int nkt = 2 * qt + 2;

    attn_issue_q(sb, g_qh + qoff, g_ql + qoff, tid);
    attn_issue_kv(sb, 0, 0, g_kh + koff, g_kl + koff, g_vh + koff, g_vl + koff, tid);
    CP_COMMIT();
    if (nkt > 1)
        attn_issue_kv(sb, 1, 1, g_kh + koff, g_kl + koff, g_vh + koff, g_vl + koff, tid);
    CP_COMMIT();

    const int rl0 = w * 16 + (lane >> 2);
    const float grow0 = 0.125f * exp2f(lg * (float)rl0);
    const float grow1 = 0.125f * exp2f(lg * (float)(rl0 + 8));
    const float ginv  = exp2f(-lg);
    float gc[8];
    #pragma unroll
    for (int p = 0; p < 8; p++)
        gc[p] = exp2f(-lg * (float)(p * 8 + (lane & 3) * 2));

    float oacc[8][4];
    #pragma unroll
    for (int p = 0; p < 8; p++)
        #pragma unroll
        for (int r = 0; r < 4; r++) oacc[p][r] = 0.f;

    const uint32_t arow = (uint32_t)(w * 16 + l7 + 8 * ((lane >> 3) & 1));
    const uint32_t akb  = (lane >> 4) & 1;
    const uint32_t brow = (uint32_t)(l7 + 8 * ((lane >> 4) & 1));
    const uint32_t bkb  = (lane >> 3) & 1;
    const uint32_t vrow = (uint32_t)(l7 + 8 * ((lane >> 3) & 1));
    const uint32_t vnb  = (lane >> 4) & 1;

    for (int kt = 0; kt < nkt; kt++) {
        cp_wait<1>();
        __syncthreads();

        const uint32_t stg = sb + OFF_ST + (kt & 1) * STG_SZ;
        const uint32_t sKH = stg, sKL = stg + 8192;
        const uint32_t sVH = stg + 16384, sVL = stg + 24576;

        float sacc[8][4];
        #pragma unroll
        for (int p = 0; p < 8; p++)
            #pragma unroll
            for (int r = 0; r < 4; r++) sacc[p][r] = 0.f;

        #pragma unroll
        for (int ks = 0; ks < 4; ks++) {
            uint32_t qa = sb + OFF_QH + arow * 128 + (((2*ks + akb) ^ (arow & 7)) << 4);
            uint32_t ah[4], al[4];
            LDSM4(ah, qa);
            LDSM4(al, qa + (OFF_QL - OFF_QH));
            #pragma unroll
            for (int g = 0; g < 4; g++) {
                uint32_t br = g * 16 + brow;
                uint32_t ba = sKH + br * 128 + (((2*ks + bkb) ^ (br & 7)) << 4);
                uint32_t bh[4], bl[4];
                LDSM4(bh, ba);
                mma_bf16(sacc[2*g],   ah, bh[0], bh[1]);
                mma_bf16(sacc[2*g+1], ah, bh[2], bh[3]);
                mma_bf16(sacc[2*g],   al, bh[0], bh[1]);
                mma_bf16(sacc[2*g+1], al, bh[2], bh[3]);
                LDSM4(bl, ba + (sKL - sKH));
                mma_bf16(sacc[2*g],   ah, bl[0], bl[1]);
                mma_bf16(sacc[2*g+1], ah, bl[2], bl[3]);
            }
        }

        const int   dbase = qt * QT_ - kt * KT_;
        const float f     = exp2f(lg * (float)dbase);
        const float fr0   = f * grow0;
        const float fr1   = f * grow1;
        const bool  edge  = (dbase < KT_);
        uint32_t SAh[4][4], SAl[4][4];
        #pragma unroll
        for (int p = 0; p < 8; p++) {
            const float c0 = gc[p], c1 = gc[p] * ginv;
            float v00 = sacc[p][0] * fr0 * c0;
            float v01 = sacc[p][1] * fr0 * c1;
            float v10 = sacc[p][2] * fr1 * c0;
            float v11 = sacc[p][3] * fr1 * c1;
            if (edge) {
                const int tl0 = p * 8 + (lane & 3) * 2;
                const int d00 = dbase + rl0 - tl0;
                if (d00 < 0)     v00 = 0.f;
                if (d00 - 1 < 0) v01 = 0.f;
                if (d00 + 8 < 0) v10 = 0.f;
                if (d00 + 7 < 0) v11 = 0.f;
            }
            const int j = p >> 1, o = (p & 1) * 2;
            SAh[j][o]     = pack2_hilo(v00, v01, SAl[j][o]);
            SAh[j][o + 1] = pack2_hilo(v10, v11, SAl[j][o + 1]);
        }

        #pragma unroll
        for (int j = 0; j < 4; j++) {
            uint32_t vr = j * 16 + vrow;
            #pragma unroll
            for (int g = 0; g < 4; g++) {
                uint32_t va = sVH + vr * 128 + (((2*g + vnb) ^ (vr & 7)) << 4);
                uint32_t bvh[4], bvl[4];
                LDSM4T(bvh, va);
                mma_bf16(oacc[2*g],   SAh[j], bvh[0], bvh[1]);
                mma_bf16(oacc[2*g+1], SAh[j], bvh[2], bvh[3]);
                mma_bf16(oacc[2*g],   SAl[j], bvh[0], bvh[1]);
                mma_bf16(oacc[2*g+1], SAl[j], bvh[2], bvh[3]);
                LDSM4T(bvl, va + (sVL - sVH));
                mma_bf16(oacc[2*g],   SAh[j], bvl[0], bvl[1]);
                mma_bf16(oacc[2*g+1], SAh[j], bvl[2], bvl[3]);
            }
        }

        __syncthreads();
        if (kt + 2 < nkt)
            attn_issue_kv(sb, kt & 1, kt + 2,
                          g_kh + koff, g_kl + koff, g_vh + koff, g_vl + koff, tid);
        CP_COMMIT();
    }

    const size_t row0 = (size_t)(b * S_ + qt * QT_ + rl0);
    #pragma unroll
    for (int p = 0; p < 8; p++) {
        const int col = h * DH_ + p * 8 + (lane & 3) * 2;
        #pragma unroll
        for (int half = 0; half < 2; half++) {
            const size_t idx2 = (row0 + half * 8) * D_ + col;
            float2 gv = *(const float2*)(g_g + idx2);
            float s0 = gv.x / (1.f + expf(-gv.x));
            float s1 = gv.y / (1.f + expf(-gv.y));
            float y0 = oacc[p][half*2 + 0] * s0;
            float y1 = oacc[p][half*2 + 1] * s1;
            uint32_t lo;
            uint32_t hi = pack2_hilo(y0, y1, lo);
            *(uint32_t*)&g_aoh[idx2] = hi;
            *(uint32_t*)&g_aol[idx2] = lo;
        }
    }
}

// ============================================================================
extern "C" void kernel_launch(void* const* d_in, const int* in_sizes, int n_in,
                              void* d_out, int out_size)
{
    const float* x  = (const float*)d_in[0];
    const float* wq = (const float*)d_in[1];
    const float* wk = (const float*)d_in[2];
    const float* wv = (const float*)d_in[3];
    const float* wg = (const float*)d_in[4];
    const float* wo = (const float*)d_in[5];
    float* out = (float*)d_out;

    cudaFuncSetAttribute(gemm_qkvg_bf,
                         cudaFuncAttributeMaxDynamicSharedMemorySize, GEMM_SMEM);
    cudaFuncSetAttribute(gemm_out_bf,
                         cudaFuncAttributeMaxDynamicSharedMemorySize, GEMM_SMEM);
    cudaFuncSetAttribute(attn_kernel,
                         cudaFuncAttributeMaxDynamicSharedMemorySize, ATTN_SMEM);

    split_kernel<<<dim3(M_*D_/4/256, 6), 256>>>(x, wq, wk, wv, wg, wo);

    gemm_qkvg_bf<<<dim3(D_/128, M_/128, 4), 256, GEMM_SMEM>>>();

    int nrope = M_ * H_ * 32;
    rope_kernel<<<(nrope + 255) / 256, 256>>>();

    attn_kernel<<<(S_/QT_) * H_ * B_, 256, ATTN_SMEM>>>();

    gemm_out_bf<<<dim3(D_/128, M_/128), 256, GEMM_SMEM>>>(out);
}

// round 10
// speedup vs baseline: 1.7067x; 1.2376x over previous
#include <cuda_runtime.h>
#include <cuda_bf16.h>
#include <cuda_fp16.h>
#include <stdint.h>
#include <math.h>

#define B_  2
#define S_  2048
#define D_  1024
#define H_  16
#define DH_ 64
#define M_  (B_*S_)   /* 4096 */

// ---- scratch (static device allocations; no cudaMalloc allowed) ----
__device__ __align__(16) float g_q [M_*D_];
__device__ __align__(16) float g_k [M_*D_];
__device__ __align__(16) float g_g [M_*D_];

// fp16 attention operands
__device__ __align__(16) __half g_qf[M_*D_], g_kf[M_*D_], g_vf[M_*D_];

// bf16 hi/lo split operands for the GEMMs
__device__ __align__(16) __nv_bfloat16 g_xh [M_*D_], g_xl [M_*D_];
__device__ __align__(16) __nv_bfloat16 g_aoh[M_*D_], g_aol[M_*D_];
__device__ __align__(16) __nv_bfloat16 g_wqh[D_*D_], g_wql[D_*D_];
__device__ __align__(16) __nv_bfloat16 g_wkh[D_*D_], g_wkl[D_*D_];
__device__ __align__(16) __nv_bfloat16 g_wvh[D_*D_], g_wvl[D_*D_];
__device__ __align__(16) __nv_bfloat16 g_wgh[D_*D_], g_wgl[D_*D_];
__device__ __align__(16) __nv_bfloat16 g_woh[D_*D_], g_wol[D_*D_];

// ============================================================================
// PTX helpers
// ============================================================================
__device__ __forceinline__ uint32_t smem_u32(const void* p)
{
    uint32_t a;
    asm("{ .reg .u64 t; cvta.to.shared.u64 t, %1; cvt.u32.u64 %0, t; }"
        : "=r"(a) : "l"(p));
    return a;
}

__device__ __forceinline__ void cp16(uint32_t s, const void* g)
{
    asm volatile("cp.async.cg.shared.global [%0], [%1], 16;" :: "r"(s), "l"(g));
}
#define CP_COMMIT() asm volatile("cp.async.commit_group;" ::: "memory")
template<int N> __device__ __forceinline__ void cp_wait()
{
    asm volatile("cp.async.wait_group %0;" :: "n"(N) : "memory");
}

#define LDSM4(r, addr) \
    asm volatile("ldmatrix.sync.aligned.m8n8.x4.shared.b16 {%0,%1,%2,%3}, [%4];" \
        : "=r"((r)[0]), "=r"((r)[1]), "=r"((r)[2]), "=r"((r)[3]) : "r"(addr))

#define LDSM4T(r, addr) \
    asm volatile("ldmatrix.sync.aligned.m8n8.x4.trans.shared.b16 {%0,%1,%2,%3}, [%4];" \
        : "=r"((r)[0]), "=r"((r)[1]), "=r"((r)[2]), "=r"((r)[3]) : "r"(addr))

__device__ __forceinline__ void mma_bf16(float c[4], const uint32_t a[4],
                                         uint32_t b0, uint32_t b1)
{
    asm volatile(
        "mma.sync.aligned.m16n8k16.row.col.f32.bf16.bf16.f32 "
        "{%0,%1,%2,%3},{%4,%5,%6,%7},{%8,%9},{%0,%1,%2,%3};"
        : "+f"(c[0]), "+f"(c[1]), "+f"(c[2]), "+f"(c[3])
        : "r"(a[0]), "r"(a[1]), "r"(a[2]), "r"(a[3]), "r"(b0), "r"(b1));
}

__device__ __forceinline__ void mma_f16(float c[4], const uint32_t a[4],
                                        uint32_t b0, uint32_t b1)
{
    asm volatile(
        "mma.sync.aligned.m16n8k16.row.col.f32.f16.f16.f32 "
        "{%0,%1,%2,%3},{%4,%5,%6,%7},{%8,%9},{%0,%1,%2,%3};"
        : "+f"(c[0]), "+f"(c[1]), "+f"(c[2]), "+f"(c[3])
        : "r"(a[0]), "r"(a[1]), "r"(a[2]), "r"(a[3]), "r"(b0), "r"(b1));
}

__device__ __forceinline__ uint32_t pack2_hilo(float a, float b, uint32_t& lo)
{
    __nv_bfloat16 ha = __float2bfloat16(a), hb = __float2bfloat16(b);
    float ra = a - __bfloat162float(ha);
    float rb = b - __bfloat162float(hb);
    __nv_bfloat16 la = __float2bfloat16(ra), lb = __float2bfloat16(rb);
    lo = (uint32_t)__bfloat16_as_ushort(la) | ((uint32_t)__bfloat16_as_ushort(lb) << 16);
    return (uint32_t)__bfloat16_as_ushort(ha) | ((uint32_t)__bfloat16_as_ushort(hb) << 16);
}

__device__ __forceinline__ uint32_t packh2(float a, float b)
{
    __half2 h = __floats2half2_rn(a, b);
    return *(uint32_t*)&h;
}

__device__ __forceinline__ uint32_t bf_split_hi(float a, float& rem)
{
    __nv_bfloat16 h = __float2bfloat16(a);
    rem = a - __bfloat162float(h);
    return (uint32_t)__bfloat16_as_ushort(h);
}

// ============================================================================
// hi/lo bf16 split kernel for x + weights
// ============================================================================
__global__ void split_kernel(const float* __restrict__ x,
                             const float* __restrict__ wq, const float* __restrict__ wk,
                             const float* __restrict__ wv, const float* __restrict__ wg,
                             const float* __restrict__ wo)
{
    const float* src;
    __nv_bfloat16 *dh, *dl;
    int n4;
    switch (blockIdx.y) {
        case 0: src = x;  dh = g_xh;  dl = g_xl;  n4 = M_*D_/4; break;
        case 1: src = wq; dh = g_wqh; dl = g_wql; n4 = D_*D_/4; break;
        case 2: src = wk; dh = g_wkh; dl = g_wkl; n4 = D_*D_/4; break;
        case 3: src = wv; dh = g_wvh; dl = g_wvl; n4 = D_*D_/4; break;
        case 4: src = wg; dh = g_wgh; dl = g_wgl; n4 = D_*D_/4; break;
        default:src = wo; dh = g_woh; dl = g_wol; n4 = D_*D_/4; break;
    }
    int i4 = blockIdx.x * blockDim.x + threadIdx.x;
    if (i4 >= n4) return;
    float4 v = ((const float4*)src)[i4];
    float r0, r1, r2, r3, d0;
    uint32_t h0 = bf_split_hi(v.x, r0), h1 = bf_split_hi(v.y, r1);
    uint32_t h2 = bf_split_hi(v.z, r2), h3 = bf_split_hi(v.w, r3);
    uint32_t l0 = bf_split_hi(r0, d0), l1 = bf_split_hi(r1, d0);
    uint32_t l2 = bf_split_hi(r2, d0), l3 = bf_split_hi(r3, d0);
    ((uint2*)dh)[i4] = make_uint2(h0 | (h1 << 16), h2 | (h3 << 16));
    ((uint2*)dl)[i4] = make_uint2(l0 | (l1 << 16), l2 | (l3 << 16));
}

// ============================================================================
// bf16 split GEMM: C = A @ W^T, 3-pass hi/lo.
// OM=0: float C.  OM=1: fp16 C (V projection, feeds fp16 attention).
// ============================================================================
#define BKH     32
#define NITG    (D_/BKH)
#define TILE_HB (128*BKH*2)
#define STAGE_B (4*TILE_HB)
#define NSTG    3
#define GEMM_SMEM (NSTG*STAGE_B)

struct GemmSrcs { const __nv_bfloat16 *ah, *al, *bh, *bl; };

__device__ __forceinline__ void issue_stage(uint32_t sb, int stage, int k0,
                                            const GemmSrcs& s, int tid)
{
    const __nv_bfloat16* srcs[4] = { s.ah, s.al, s.bh, s.bl };
    const uint32_t stg = sb + stage * STAGE_B;
    #pragma unroll
    for (int m = 0; m < 4; m++) {
        const __nv_bfloat16* src = srcs[m] + k0;
        const uint32_t tb = stg + m * TILE_HB;
        #pragma unroll
        for (int i = 0; i < 2; i++) {
            int j   = tid + i * 256;
            int row = j >> 2;
            int c   = j & 3;
            int csw = c ^ ((row >> 1) & 3);
            cp16(tb + row * 64 + csw * 16, src + (size_t)row * D_ + c * 8);
        }
    }
}

template<int OM>
__device__ __forceinline__ void gemm_bf16_body(const GemmSrcs& s, float* C,
                                               __half* Cf)
{
    extern __shared__ char dsm[];
    const uint32_t sb = smem_u32(dsm);
    const int tid  = threadIdx.x;
    const int lane = tid & 31;
    const int w    = tid >> 5;
    const int wm   = (w >> 2) * 64;
    const int wn   = (w & 3) * 32;

    const int l7 = lane & 7;
    uint32_t aoff[4], asw[4], boff[2], bsw[2];
    const int akb = (lane >> 4) & 1;
    const int bkb = (lane >> 3) & 1;
    #pragma unroll
    for (int mf = 0; mf < 4; mf++) {
        int row = wm + mf * 16 + l7 + 8 * ((lane >> 3) & 1);
        aoff[mf] = row * 64;
        asw[mf]  = (row >> 1) & 3;
    }
    #pragma unroll
    for (int nfp = 0; nfp < 2; nfp++) {
        int row = wn + nfp * 16 + l7 + 8 * ((lane >> 4) & 1);
        boff[nfp] = row * 64;
        bsw[nfp]  = (row >> 1) & 3;
    }

    float acc[4][4][4];
    #pragma unroll
    for (int i = 0; i < 4; i++)
        #pragma unroll
        for (int j = 0; j < 4; j++)
            #pragma unroll
            for (int r = 0; r < 4; r++) acc[i][j][r] = 0.f;

    issue_stage(sb, 0, 0, s, tid);   CP_COMMIT();
    issue_stage(sb, 1, BKH, s, tid); CP_COMMIT();

    for (int it = 0; it < NITG; it++) {
        if (it == NITG - 1) cp_wait<0>(); else cp_wait<1>();
        __syncthreads();
        if (it + 2 < NITG) issue_stage(sb, (it + 2) % NSTG, (it + 2) * BKH, s, tid);
        CP_COMMIT();

        const uint32_t stg = sb + (it % NSTG) * STAGE_B;
        const uint32_t sAh = stg, sAl = stg + TILE_HB;
        const uint32_t sBh = stg + 2*TILE_HB, sBl = stg + 3*TILE_HB;

        #pragma unroll
        for (int ks = 0; ks < 2; ks++) {
            uint32_t bh[2][4], bl[2][4];
            #pragma unroll
            for (int nfp = 0; nfp < 2; nfp++) {
                uint32_t off = boff[nfp] + ((((uint32_t)(2*ks + bkb)) ^ bsw[nfp]) << 4);
                LDSM4(bh[nfp], sBh + off);
                LDSM4(bl[nfp], sBl + off);
            }
            #pragma unroll
            for (int mf = 0; mf < 4; mf++) {
                uint32_t off = aoff[mf] + ((((uint32_t)(2*ks + akb)) ^ asw[mf]) << 4);
                uint32_t ah[4], al[4];
                LDSM4(ah, sAh + off);
                LDSM4(al, sAl + off);
                #pragma unroll
                for (int nf = 0; nf < 4; nf++) {
                    uint32_t b0 = bh[nf >> 1][(nf & 1)*2], b1 = bh[nf >> 1][(nf & 1)*2 + 1];
                    uint32_t c0 = bl[nf >> 1][(nf & 1)*2], c1 = bl[nf >> 1][(nf & 1)*2 + 1];
                    mma_bf16(acc[mf][nf], ah, b0, b1);
                    mma_bf16(acc[mf][nf], al, b0, b1);
                    mma_bf16(acc[mf][nf], ah, c0, c1);
                }
            }
        }
        __syncthreads();
    }

    const int rbase = blockIdx.y * 128 + wm + (lane >> 2);
    const int cbase = blockIdx.x * 128 + wn + ((lane & 3) << 1);
    #pragma unroll
    for (int mf = 0; mf < 4; mf++)
        #pragma unroll
        for (int nf = 0; nf < 4; nf++) {
            const size_t i0 = (size_t)(rbase + mf*16) * D_ + cbase + nf*8;
            const size_t i1 = i0 + (size_t)8 * D_;
            if (OM == 0) {
                *(float2*)(C + i0) = make_float2(acc[mf][nf][0], acc[mf][nf][1]);
                *(float2*)(C + i1) = make_float2(acc[mf][nf][2], acc[mf][nf][3]);
            } else {
                *(uint32_t*)&Cf[i0] = packh2(acc[mf][nf][0], acc[mf][nf][1]);
                *(uint32_t*)&Cf[i1] = packh2(acc[mf][nf][2], acc[mf][nf][3]);
            }
        }
}

__global__ __launch_bounds__(256, 2)
void gemm_qkvg_bf()
{
    GemmSrcs s;
    const size_t yoff = (size_t)blockIdx.y * 128 * D_;
    const size_t xoff = (size_t)blockIdx.x * 128 * D_;
    s.ah = g_xh + yoff; s.al = g_xl + yoff;
    if (blockIdx.z == 2) {
        s.bh = g_wvh + xoff; s.bl = g_wvl + xoff;
        gemm_bf16_body<1>(s, nullptr, g_vf);
        return;
    }
    float* C;
    switch (blockIdx.z) {
        case 0:  s.bh = g_wqh + xoff; s.bl = g_wql + xoff; C = g_q; break;
        case 1:  s.bh = g_wkh + xoff; s.bl = g_wkl + xoff; C = g_k; break;
        default: s.bh = g_wgh + xoff; s.bl = g_wgl + xoff; C = g_g; break;
    }
    gemm_bf16_body<0>(s, C, nullptr);
}

__global__ __launch_bounds__(256, 2)
void gemm_out_bf(float* __restrict__ C)
{
    GemmSrcs s;
    const size_t yoff = (size_t)blockIdx.y * 128 * D_;
    const size_t xoff = (size_t)blockIdx.x * 128 * D_;
    s.ah = g_aoh + yoff; s.al = g_aol + yoff;
    s.bh = g_woh + xoff; s.bl = g_wol + xoff;
    gemm_bf16_body<0>(s, C, nullptr);
}

// ============================================================================
// RoPE: read float q/k, write rotated values as fp16
// ============================================================================
__global__ void rope_kernel()
{
    int i = blockIdx.x * blockDim.x + threadIdx.x;
    if (i >= M_ * H_ * 32) return;
    int j  = i & 31;
    int h  = (i >> 5) & (H_ - 1);
    int bs = i >> 9;
    int s  = bs & (S_ - 1);

    float inv = exp2f(-(float)j * 0.41524101186092029f);
    float ang = (float)s * inv;
    float sn, cs;
    sincosf(ang, &sn, &cs);

    int base = bs * D_ + h * DH_ + j;
    float q1 = g_q[base], q2 = g_q[base + 32];
    float k1 = g_k[base], k2 = g_k[base + 32];
    g_qf[base]      = __float2half_rn(q1 * cs - q2 * sn);
    g_qf[base + 32] = __float2half_rn(q2 * cs + q1 * sn);
    g_kf[base]      = __float2half_rn(k1 * cs - k2 * sn);
    g_kf[base + 32] = __float2half_rn(k2 * cs + k1 * sn);
}

// ============================================================================
// fp16 single-pass flash retention, 4-stage cp.async K/V pipeline.
// CTA = 128 q-rows x (h,b). 256 threads, 8 warps; warp owns 16 q-rows.
// smem: Qf 16K | 4 stages x (K 8K | V 8K) = 80 KB. 2 CTAs/SM.
// ============================================================================
#define QT_ 128
#define KT_ 64
#define OFF_QF 0
#define OFF_ST 16384
#define STG_SZ 16384
#define ATTN_SMEM 81920

__device__ __forceinline__ void attn_issue_q(uint32_t sb, const __half* qf, int tid)
{
    #pragma unroll
    for (int i = 0; i < 4; i++) {
        int u   = tid + i * 256;          // 0..1023
        int row = u >> 3;
        int c   = u & 7;
        int cs  = c ^ (row & 7);
        cp16(sb + OFF_QF + row * 128 + cs * 16, qf + (size_t)row * D_ + c * 8);
    }
}

__device__ __forceinline__ void attn_issue_kv(uint32_t sb, int stage, int kt,
                                              const __half* kf, const __half* vf,
                                              int tid)
{
    const __half* srcs[2] = { kf + (size_t)(kt * KT_) * D_,
                              vf + (size_t)(kt * KT_) * D_ };
    const uint32_t stg = sb + OFF_ST + stage * STG_SZ;
    #pragma unroll
    for (int m = 0; m < 2; m++) {
        const __half* src = srcs[m];
        const uint32_t tb = stg + m * 8192;
        #pragma unroll
        for (int i = 0; i < 2; i++) {
            int u   = tid + i * 256;      // 0..511
            int row = u >> 3;
            int c   = u & 7;
            int cs  = c ^ (row & 7);
            cp16(tb + row * 128 + cs * 16, src + (size_t)row * D_ + c * 8);
        }
    }
}

__global__ __launch_bounds__(256, 2)
void attn_kernel()
{
    extern __shared__ char dsm[];
    const uint32_t sb = smem_u32(dsm);

    // global heavy-first: all (h,b) of the heaviest qt launch first
    const int idx = blockIdx.x;
    const int qt  = (S_/QT_ - 1) - (idx >> 5);
    const int h   = idx & 15;
    const int b   = (idx >> 4) & 1;

    const int tid  = threadIdx.x;
    const int lane = tid & 31;
    const int w    = tid >> 5;
    const int l7   = lane & 7;

    const float gamma = 1.0f - exp2f(-5.0f - (float)h);
    const float lg    = log2f(gamma);

    const size_t qoff = (size_t)(b * S_ + qt * QT_) * D_ + h * DH_;
    const size_t koff = (size_t)(b * S_) * D_ + h * DH_;
    const int nkt = 2 * qt + 2;

    // pipeline prologue: Q + tiles 0..2 as 3 committed groups (some may be empty)
    attn_issue_q(sb, g_qf + qoff, tid);
    attn_issue_kv(sb, 0, 0, g_kf + koff, g_vf + koff, tid);
    CP_COMMIT();
    if (1 < nkt) attn_issue_kv(sb, 1, 1, g_kf + koff, g_vf + koff, tid);
    CP_COMMIT();
    if (2 < nkt) attn_issue_kv(sb, 2, 2, g_kf + koff, g_vf + koff, tid);
    CP_COMMIT();

    // per-thread decay constants
    const int rl0 = w * 16 + (lane >> 2);
    const float grow0 = 0.125f * exp2f(lg * (float)rl0);
    const float grow1 = 0.125f * exp2f(lg * (float)(rl0 + 8));
    const float ginv  = exp2f(-lg);
    float gc[8];
    #pragma unroll
    for (int p = 0; p < 8; p++)
        gc[p] = exp2f(-lg * (float)(p * 8 + (lane & 3) * 2));

    float oacc[8][4];
    #pragma unroll
    for (int p = 0; p < 8; p++)
        #pragma unroll
        for (int r = 0; r < 4; r++) oacc[p][r] = 0.f;

    const uint32_t arow = (uint32_t)(w * 16 + l7 + 8 * ((lane >> 3) & 1));
    const uint32_t akb  = (lane >> 4) & 1;
    const uint32_t brow = (uint32_t)(l7 + 8 * ((lane >> 4) & 1));
    const uint32_t bkb  = (lane >> 3) & 1;
    const uint32_t vrow = (uint32_t)(l7 + 8 * ((lane >> 3) & 1));
    const uint32_t vnb  = (lane >> 4) & 1;

    for (int kt = 0; kt < nkt; kt++) {
        cp_wait<2>();
        __syncthreads();

        const uint32_t stg = sb + OFF_ST + (kt & 3) * STG_SZ;
        const uint32_t sK = stg, sV = stg + 8192;

        // ---- S = Q K^T (fp16 single pass), S in registers
        float sacc[8][4];
        #pragma unroll
        for (int p = 0; p < 8; p++)
            #pragma unroll
            for (int r = 0; r < 4; r++) sacc[p][r] = 0.f;

        #pragma unroll
        for (int ks = 0; ks < 4; ks++) {
            uint32_t qa = sb + OFF_QF + arow * 128 + (((2*ks + akb) ^ (arow & 7)) << 4);
            uint32_t ah[4];
            LDSM4(ah, qa);
            #pragma unroll
            for (int g = 0; g < 4; g++) {
                uint32_t br = g * 16 + brow;
                uint32_t ba = sK + br * 128 + (((2*ks + bkb) ^ (br & 7)) << 4);
                uint32_t bh[4];
                LDSM4(bh, ba);
                mma_f16(sacc[2*g],   ah, bh[0], bh[1]);
                mma_f16(sacc[2*g+1], ah, bh[2], bh[3]);
            }
        }

        // ---- decay + causal mask + pack to fp16 A-frags (registers only)
        const int   dbase = qt * QT_ - kt * KT_;
        const float f     = exp2f(lg * (float)dbase);
        const float fr0   = f * grow0;
        const float fr1   = f * grow1;
        const bool  edge  = (dbase < KT_);
        uint32_t SA[4][4];
        #pragma unroll
        for (int p = 0; p < 8; p++) {
            const float c0 = gc[p], c1 = gc[p] * ginv;
            float v00 = sacc[p][0] * fr0 * c0;
            float v01 = sacc[p][1] * fr0 * c1;
            float v10 = sacc[p][2] * fr1 * c0;
            float v11 = sacc[p][3] * fr1 * c1;
            if (edge) {
                const int tl0 = p * 8 + (lane & 3) * 2;
                const int d00 = dbase + rl0 - tl0;
                if (d00 < 0)     v00 = 0.f;
                if (d00 - 1 < 0) v01 = 0.f;
                if (d00 + 8 < 0) v10 = 0.f;
                if (d00 + 7 < 0) v11 = 0.f;
            }
            const int j = p >> 1, o = (p & 1) * 2;
            SA[j][o]     = packh2(v00, v01);
            SA[j][o + 1] = packh2(v10, v11);
        }

        // ---- O += S @ V (fp16 single pass), V via ldmatrix.trans
        #pragma unroll
        for (int j = 0; j < 4; j++) {
            uint32_t vr = j * 16 + vrow;
            #pragma unroll
            for (int g = 0; g < 4; g++) {
                uint32_t va = sV + vr * 128 + (((2*g + vnb) ^ (vr & 7)) << 4);
                uint32_t bv[4];
                LDSM4T(bv, va);
                mma_f16(oacc[2*g],   SA[j], bv[0], bv[1]);
                mma_f16(oacc[2*g+1], SA[j], bv[2], bv[3]);
            }
        }

        // issue tile kt+3 into the buffer consumed at iteration kt-1
        // (safe: all reads of it completed before this iteration's barrier)
        if (kt + 3 < nkt)
            attn_issue_kv(sb, (kt + 3) & 3, kt + 3,
                          g_kf + koff, g_vf + koff, tid);
        CP_COMMIT();   // one group per iteration (may be empty) keeps wait<2> exact
    }

    // ---- epilogue: y = O * silu(g) -> bf16 hi/lo for the out-projection
    const size_t row0 = (size_t)(b * S_ + qt * QT_ + rl0);
    #pragma unroll
    for (int p = 0; p < 8; p++) {
        const int col = h * DH_ + p * 8 + (lane & 3) * 2;
        #pragma unroll
        for (int half = 0; half < 2; half++) {
            const size_t idx2 = (row0 + half * 8) * D_ + col;
            float2 gv = *(const float2*)(g_g + idx2);
            float s0 = gv.x / (1.f + expf(-gv.x));
            float s1 = gv.y / (1.f + expf(-gv.y));
            float y0 = oacc[p][half*2 + 0] * s0;
            float y1 = oacc[p][half*2 + 1] * s1;
            uint32_t lo;
            uint32_t hi = pack2_hilo(y0, y1, lo);
            *(uint32_t*)&g_aoh[idx2] = hi;
            *(uint32_t*)&g_aol[idx2] = lo;
        }
    }
}

// ============================================================================
extern "C" void kernel_launch(void* const* d_in, const int* in_sizes, int n_in,
                              void* d_out, int out_size)
{
    const float* x  = (const float*)d_in[0];
    const float* wq = (const float*)d_in[1];
    const float* wk = (const float*)d_in[2];
    const float* wv = (const float*)d_in[3];
    const float* wg = (const float*)d_in[4];
    const float* wo = (const float*)d_in[5];
    float* out = (float*)d_out;

    cudaFuncSetAttribute(gemm_qkvg_bf,
                         cudaFuncAttributeMaxDynamicSharedMemorySize, GEMM_SMEM);
    cudaFuncSetAttribute(gemm_out_bf,
                         cudaFuncAttributeMaxDynamicSharedMemorySize, GEMM_SMEM);
    cudaFuncSetAttribute(attn_kernel,
                         cudaFuncAttributeMaxDynamicSharedMemorySize, ATTN_SMEM);

    split_kernel<<<dim3(M_*D_/4/256, 6), 256>>>(x, wq, wk, wv, wg, wo);

    gemm_qkvg_bf<<<dim3(D_/128, M_/128, 4), 256, GEMM_SMEM>>>();

    int nrope = M_ * H_ * 32;
    rope_kernel<<<(nrope + 255) / 256, 256>>>();

    attn_kernel<<<(S_/QT_) * H_ * B_, 256, ATTN_SMEM>>>();

    gemm_out_bf<<<dim3(D_/128, M_/128), 256, GEMM_SMEM>>>(out);
}

// round 11
// speedup vs baseline: 2.1731x; 1.2733x over previous
#include <cuda_runtime.h>
#include <cuda_fp16.h>
#include <stdint.h>
#include <math.h>

#define B_  2
#define S_  2048
#define D_  1024
#define H_  16
#define DH_ 64
#define M_  (B_*S_)   /* 4096 */

// ---- scratch (static device allocations; no cudaMalloc allowed) ----
__device__ __align__(16) float g_q [M_*D_];
__device__ __align__(16) float g_k [M_*D_];
__device__ __align__(16) float g_g [M_*D_];

// fp16 attention operands
__device__ __align__(16) __half g_qf[M_*D_], g_kf[M_*D_], g_vf[M_*D_];

// fp16 hi/lo split operands for the GEMMs (A side split, B side hi only)
__device__ __align__(16) __half g_xh [M_*D_], g_xl [M_*D_];
__device__ __align__(16) __half g_aoh[M_*D_], g_aol[M_*D_];
__device__ __align__(16) __half g_wqh[D_*D_];
__device__ __align__(16) __half g_wkh[D_*D_];
__device__ __align__(16) __half g_wvh[D_*D_];
__device__ __align__(16) __half g_wgh[D_*D_];
__device__ __align__(16) __half g_woh[D_*D_];

// ============================================================================
// PTX helpers
// ============================================================================
__device__ __forceinline__ uint32_t smem_u32(const void* p)
{
    uint32_t a;
    asm("{ .reg .u64 t; cvta.to.shared.u64 t, %1; cvt.u32.u64 %0, t; }"
        : "=r"(a) : "l"(p));
    return a;
}

__device__ __forceinline__ void cp16(uint32_t s, const void* g)
{
    asm volatile("cp.async.cg.shared.global [%0], [%1], 16;" :: "r"(s), "l"(g));
}
#define CP_COMMIT() asm volatile("cp.async.commit_group;" ::: "memory")
template<int N> __device__ __forceinline__ void cp_wait()
{
    asm volatile("cp.async.wait_group %0;" :: "n"(N) : "memory");
}

#define LDSM4(r, addr) \
    asm volatile("ldmatrix.sync.aligned.m8n8.x4.shared.b16 {%0,%1,%2,%3}, [%4];" \
        : "=r"((r)[0]), "=r"((r)[1]), "=r"((r)[2]), "=r"((r)[3]) : "r"(addr))

#define LDSM4T(r, addr) \
    asm volatile("ldmatrix.sync.aligned.m8n8.x4.trans.shared.b16 {%0,%1,%2,%3}, [%4];" \
        : "=r"((r)[0]), "=r"((r)[1]), "=r"((r)[2]), "=r"((r)[3]) : "r"(addr))

__device__ __forceinline__ void mma_f16(float c[4], const uint32_t a[4],
                                        uint32_t b0, uint32_t b1)
{
    asm volatile(
        "mma.sync.aligned.m16n8k16.row.col.f32.f16.f16.f32 "
        "{%0,%1,%2,%3},{%4,%5,%6,%7},{%8,%9},{%0,%1,%2,%3};"
        : "+f"(c[0]), "+f"(c[1]), "+f"(c[2]), "+f"(c[3])
        : "r"(a[0]), "r"(a[1]), "r"(a[2]), "r"(a[3]), "r"(b0), "r"(b1));
}

__device__ __forceinline__ uint32_t packh2(float a, float b)
{
    __half2 h = __floats2half2_rn(a, b);
    return *(uint32_t*)&h;
}

// pack two floats as fp16 hi pair; residuals as fp16 lo pair
__device__ __forceinline__ uint32_t packh2_hilo(float a, float b, uint32_t& lo)
{
    __half ha = __float2half_rn(a), hb = __float2half_rn(b);
    float ra = a - __half2float(ha);
    float rb = b - __half2float(hb);
    __half la = __float2half_rn(ra), lb = __float2half_rn(rb);
    lo = (uint32_t)__half_as_ushort(la) | ((uint32_t)__half_as_ushort(lb) << 16);
    return (uint32_t)__half_as_ushort(ha) | ((uint32_t)__half_as_ushort(hb) << 16);
}

__device__ __forceinline__ uint32_t hf_split_hi(float a, float& rem)
{
    __half h = __float2half_rn(a);
    rem = a - __half2float(h);
    return (uint32_t)__half_as_ushort(h);
}

// ============================================================================
// fp16 hi/lo split kernel: x -> hi+lo, weights -> hi only
// ============================================================================
__global__ void split_kernel(const float* __restrict__ x,
                             const float* __restrict__ wq, const float* __restrict__ wk,
                             const float* __restrict__ wv, const float* __restrict__ wg,
                             const float* __restrict__ wo)
{
    const float* src;
    __half *dh, *dl;
    int n4;
    switch (blockIdx.y) {
        case 0: src = x;  dh = g_xh;  dl = g_xl;     n4 = M_*D_/4; break;
        case 1: src = wq; dh = g_wqh; dl = nullptr;  n4 = D_*D_/4; break;
        case 2: src = wk; dh = g_wkh; dl = nullptr;  n4 = D_*D_/4; break;
        case 3: src = wv; dh = g_wvh; dl = nullptr;  n4 = D_*D_/4; break;
        case 4: src = wg; dh = g_wgh; dl = nullptr;  n4 = D_*D_/4; break;
        default:src = wo; dh = g_woh; dl = nullptr;  n4 = D_*D_/4; break;
    }
    int i4 = blockIdx.x * blockDim.x + threadIdx.x;
    if (i4 >= n4) return;
    float4 v = ((const float4*)src)[i4];
    float r0, r1, r2, r3;
    uint32_t h0 = hf_split_hi(v.x, r0), h1 = hf_split_hi(v.y, r1);
    uint32_t h2 = hf_split_hi(v.z, r2), h3 = hf_split_hi(v.w, r3);
    ((uint2*)dh)[i4] = make_uint2(h0 | (h1 << 16), h2 | (h3 << 16));
    if (dl) {
        uint32_t l0 = packh2(r0, r1);
        uint32_t l1 = packh2(r2, r3);
        ((uint2*)dl)[i4] = make_uint2(l0, l1);
    }
}

// ============================================================================
// fp16 2-pass split GEMM: C = (Ah + Al) @ Bh^T, fp32 accumulate.
// OM=0: float C.  OM=1: fp16 C (V projection).  OM=2: fp16 hi/lo C (unused).
// BM=BN=128, BK=32, 256 threads, 3-stage cp.async; stage = Ah|Al|Bh (24 KB).
// ============================================================================
#define BKH     32
#define NITG    (D_/BKH)
#define TILE_HB (128*BKH*2)           /* 8192 B */
#define STAGE_B (3*TILE_HB)           /* 24576 B */
#define NSTG    3
#define GEMM_SMEM (NSTG*STAGE_B)      /* 73728 B */

struct GemmSrcs { const __half *ah, *al, *bh; };

__device__ __forceinline__ void issue_stage(uint32_t sb, int stage, int k0,
                                            const GemmSrcs& s, int tid)
{
    const __half* srcs[3] = { s.ah, s.al, s.bh };
    const uint32_t stg = sb + stage * STAGE_B;
    #pragma unroll
    for (int m = 0; m < 3; m++) {
        const __half* src = srcs[m] + k0;
        const uint32_t tb = stg + m * TILE_HB;
        #pragma unroll
        for (int i = 0; i < 2; i++) {
            int j   = tid + i * 256;
            int row = j >> 2;
            int c   = j & 3;
            int csw = c ^ ((row >> 1) & 3);
            cp16(tb + row * 64 + csw * 16, src + (size_t)row * D_ + c * 8);
        }
    }
}

template<int OM>
__device__ __forceinline__ void gemm_f16_body(const GemmSrcs& s, float* C,
                                              __half* Cf)
{
    extern __shared__ char dsm[];
    const uint32_t sb = smem_u32(dsm);
    const int tid  = threadIdx.x;
    const int lane = tid & 31;
    const int w    = tid >> 5;
    const int wm   = (w >> 2) * 64;
    const int wn   = (w & 3) * 32;

    const int l7 = lane & 7;
    uint32_t aoff[4], asw[4], boff[2], bsw[2];
    const int akb = (lane >> 4) & 1;
    const int bkb = (lane >> 3) & 1;
    #pragma unroll
    for (int mf = 0; mf < 4; mf++) {
        int row = wm + mf * 16 + l7 + 8 * ((lane >> 3) & 1);
        aoff[mf] = row * 64;
        asw[mf]  = (row >> 1) & 3;
    }
    #pragma unroll
    for (int nfp = 0; nfp < 2; nfp++) {
        int row = wn + nfp * 16 + l7 + 8 * ((lane >> 4) & 1);
        boff[nfp] = row * 64;
        bsw[nfp]  = (row >> 1) & 3;
    }

    float acc[4][4][4];
    #pragma unroll
    for (int i = 0; i < 4; i++)
        #pragma unroll
        for (int j = 0; j < 4; j++)
            #pragma unroll
            for (int r = 0; r < 4; r++) acc[i][j][r] = 0.f;

    issue_stage(sb, 0, 0, s, tid);   CP_COMMIT();
    issue_stage(sb, 1, BKH, s, tid); CP_COMMIT();

    for (int it = 0; it < NITG; it++) {
        if (it == NITG - 1) cp_wait<0>(); else cp_wait<1>();
        __syncthreads();
        if (it + 2 < NITG) issue_stage(sb, (it + 2) % NSTG, (it + 2) * BKH, s, tid);
        CP_COMMIT();

        const uint32_t stg = sb + (it % NSTG) * STAGE_B;
        const uint32_t sAh = stg, sAl = stg + TILE_HB;
        const uint32_t sBh = stg + 2*TILE_HB;

        #pragma unroll
        for (int ks = 0; ks < 2; ks++) {
            // B fragments for this k-step
            uint32_t bh[2][4];
            #pragma unroll
            for (int nfp = 0; nfp < 2; nfp++) {
                uint32_t off = boff[nfp] + ((((uint32_t)(2*ks + bkb)) ^ bsw[nfp]) << 4);
                LDSM4(bh[nfp], sBh + off);
            }
            // stream A hi/lo fragments per mf
            #pragma unroll
            for (int mf = 0; mf < 4; mf++) {
                uint32_t off = aoff[mf] + ((((uint32_t)(2*ks + akb)) ^ asw[mf]) << 4);
                uint32_t ah[4], al[4];
                LDSM4(ah, sAh + off);
                LDSM4(al, sAl + off);
                #pragma unroll
                for (int nf = 0; nf < 4; nf++) {
                    uint32_t b0 = bh[nf >> 1][(nf & 1)*2], b1 = bh[nf >> 1][(nf & 1)*2 + 1];
                    mma_f16(acc[mf][nf], ah, b0, b1);
                    mma_f16(acc[mf][nf], al, b0, b1);
                }
            }
        }
        __syncthreads();
    }

    const int rbase = blockIdx.y * 128 + wm + (lane >> 2);
    const int cbase = blockIdx.x * 128 + wn + ((lane & 3) << 1);
    #pragma unroll
    for (int mf = 0; mf < 4; mf++)
        #pragma unroll
        for (int nf = 0; nf < 4; nf++) {
            const size_t i0 = (size_t)(rbase + mf*16) * D_ + cbase + nf*8;
            const size_t i1 = i0 + (size_t)8 * D_;
            if (OM == 0) {
                *(float2*)(C + i0) = make_float2(acc[mf][nf][0], acc[mf][nf][1]);
                *(float2*)(C + i1) = make_float2(acc[mf][nf][2], acc[mf][nf][3]);
            } else {
                *(uint32_t*)&Cf[i0] = packh2(acc[mf][nf][0], acc[mf][nf][1]);
                *(uint32_t*)&Cf[i1] = packh2(acc[mf][nf][2], acc[mf][nf][3]);
            }
        }
}

__global__ __launch_bounds__(256, 2)
void gemm_qkvg_f16()
{
    GemmSrcs s;
    const size_t yoff = (size_t)blockIdx.y * 128 * D_;
    const size_t xoff = (size_t)blockIdx.x * 128 * D_;
    s.ah = g_xh + yoff; s.al = g_xl + yoff;
    if (blockIdx.z == 2) {
        s.bh = g_wvh + xoff;
        gemm_f16_body<1>(s, nullptr, g_vf);
        return;
    }
    float* C;
    switch (blockIdx.z) {
        case 0:  s.bh = g_wqh + xoff; C = g_q; break;
        case 1:  s.bh = g_wkh + xoff; C = g_k; break;
        default: s.bh = g_wgh + xoff; C = g_g; break;
    }
    gemm_f16_body<0>(s, C, nullptr);
}

__global__ __launch_bounds__(256, 2)
void gemm_out_f16(float* __restrict__ C)
{
    GemmSrcs s;
    const size_t yoff = (size_t)blockIdx.y * 128 * D_;
    const size_t xoff = (size_t)blockIdx.x * 128 * D_;
    s.ah = g_aoh + yoff; s.al = g_aol + yoff;
    s.bh = g_woh + xoff;
    gemm_f16_body<0>(s, C, nullptr);
}

// ============================================================================
// RoPE: read float q/k, write rotated values as fp16
// ============================================================================
__global__ void rope_kernel()
{
    int i = blockIdx.x * blockDim.x + threadIdx.x;
    if (i >= M_ * H_ * 32) return;
    int j  = i & 31;
    int h  = (i >> 5) & (H_ - 1);
    int bs = i >> 9;
    int s  = bs & (S_ - 1);

    float inv = exp2f(-(float)j * 0.41524101186092029f);
    float ang = (float)s * inv;
    float sn, cs;
    sincosf(ang, &sn, &cs);

    int base = bs * D_ + h * DH_ + j;
    float q1 = g_q[base], q2 = g_q[base + 32];
    float k1 = g_k[base], k2 = g_k[base + 32];
    g_qf[base]      = __float2half_rn(q1 * cs - q2 * sn);
    g_qf[base + 32] = __float2half_rn(q2 * cs + q1 * sn);
    g_kf[base]      = __float2half_rn(k1 * cs - k2 * sn);
    g_kf[base + 32] = __float2half_rn(k2 * cs + k1 * sn);
}

// ============================================================================
// fp16 single-pass flash retention, 4-stage cp.async K/V pipeline (R10).
// smem: Qf 16K | 4 stages x (K 8K | V 8K) = 80 KB. 2 CTAs/SM.
// ============================================================================
#define QT_ 128
#define KT_ 64
#define OFF_QF 0
#define OFF_ST 16384
#define STG_SZ 16384
#define ATTN_SMEM 81920

__device__ __forceinline__ void attn_issue_q(uint32_t sb, const __half* qf, int tid)
{
    #pragma unroll
    for (int i = 0; i < 4; i++) {
        int u   = tid + i * 256;
        int row = u >> 3;
        int c   = u & 7;
        int cs  = c ^ (row & 7);
        cp16(sb + OFF_QF + row * 128 + cs * 16, qf + (size_t)row * D_ + c * 8);
    }
}

__device__ __forceinline__ void attn_issue_kv(uint32_t sb, int stage, int kt,
                                              const __half* kf, const __half* vf,
                                              int tid)
{
    const __half* srcs[2] = { kf + (size_t)(kt * KT_) * D_,
                              vf + (size_t)(kt * KT_) * D_ };
    const uint32_t stg = sb + OFF_ST + stage * STG_SZ;
    #pragma unroll
    for (int m = 0; m < 2; m++) {
        const __half* src = srcs[m];
        const uint32_t tb = stg + m * 8192;
        #pragma unroll
        for (int i = 0; i < 2; i++) {
            int u   = tid + i * 256;
            int row = u >> 3;
            int c   = u & 7;
            int cs  = c ^ (row & 7);
            cp16(tb + row * 128 + cs * 16, src + (size_t)row * D_ + c * 8);
        }
    }
}

__global__ __launch_bounds__(256, 2)
void attn_kernel()
{
    extern __shared__ char dsm[];
    const uint32_t sb = smem_u32(dsm);

    // global heavy-first: all (h,b) of the heaviest qt launch first
    const int idx = blockIdx.x;
    const int qt  = (S_/QT_ - 1) - (idx >> 5);
    const int h   = idx & 15;
    const int b   = (idx >> 4) & 1;

    const int tid  = threadIdx.x;
    const int lane = tid & 31;
    const int w    = tid >> 5;
    const int l7   = lane & 7;

    const float gamma = 1.0f - exp2f(-5.0f - (float)h);
    const float lg    = log2f(gamma);

    const size_t qoff = (size_t)(b * S_ + qt * QT_) * D_ + h * DH_;
    const size_t koff = (size_t)(b * S_) * D_ + h * DH_;
    const int nkt = 2 * qt + 2;

    attn_issue_q(sb, g_qf + qoff, tid);
    attn_issue_kv(sb, 0, 0, g_kf + koff, g_vf + koff, tid);
    CP_COMMIT();
    if (1 < nkt) attn_issue_kv(sb, 1, 1, g_kf + koff, g_vf + koff, tid);
    CP_COMMIT();
    if (2 < nkt) attn_issue_kv(sb, 2, 2, g_kf + koff, g_vf + koff, tid);
    CP_COMMIT();

    const int rl0 = w * 16 + (lane >> 2);
    const float grow0 = 0.125f * exp2f(lg * (float)rl0);
    const float grow1 = 0.125f * exp2f(lg * (float)(rl0 + 8));
    const float ginv  = exp2f(-lg);
    float gc[8];
    #pragma unroll
    for (int p = 0; p < 8; p++)
        gc[p] = exp2f(-lg * (float)(p * 8 + (lane & 3) * 2));

    float oacc[8][4];
    #pragma unroll
    for (int p = 0; p < 8; p++)
        #pragma unroll
        for (int r = 0; r < 4; r++) oacc[p][r] = 0.f;

    const uint32_t arow = (uint32_t)(w * 16 + l7 + 8 * ((lane >> 3) & 1));
    const uint32_t akb  = (lane >> 4) & 1;
    const uint32_t brow = (uint32_t)(l7 + 8 * ((lane >> 4) & 1));
    const uint32_t bkb  = (lane >> 3) & 1;
    const uint32_t vrow = (uint32_t)(l7 + 8 * ((lane >> 3) & 1));
    const uint32_t vnb  = (lane >> 4) & 1;

    for (int kt = 0; kt < nkt; kt++) {
        cp_wait<2>();
        __syncthreads();

        const uint32_t stg = sb + OFF_ST + (kt & 3) * STG_SZ;
        const uint32_t sK = stg, sV = stg + 8192;

        float sacc[8][4];
        #pragma unroll
        for (int p = 0; p < 8; p++)
            #pragma unroll
            for (int r = 0; r < 4; r++) sacc[p][r] = 0.f;

        #pragma unroll
        for (int ks = 0; ks < 4; ks++) {
            uint32_t qa = sb + OFF_QF + arow * 128 + (((2*ks + akb) ^ (arow & 7)) << 4);
            uint32_t ah[4];
            LDSM4(ah, qa);
            #pragma unroll
            for (int g = 0; g < 4; g++) {
                uint32_t br = g * 16 + brow;
                uint32_t ba = sK + br * 128 + (((2*ks + bkb) ^ (br & 7)) << 4);
                uint32_t bh[4];
                LDSM4(bh, ba);
                mma_f16(sacc[2*g],   ah, bh[0], bh[1]);
                mma_f16(sacc[2*g+1], ah, bh[2], bh[3]);
            }
        }

        const int   dbase = qt * QT_ - kt * KT_;
        const float f     = exp2f(lg * (float)dbase);
        const float fr0   = f * grow0;
        const float fr1   = f * grow1;
        const bool  edge  = (dbase < KT_);
        uint32_t SA[4][4];
        #pragma unroll
        for (int p = 0; p < 8; p++) {
            const float c0 = gc[p], c1 = gc[p] * ginv;
            float v00 = sacc[p][0] * fr0 * c0;
            float v01 = sacc[p][1] * fr0 * c1;
            float v10 = sacc[p][2] * fr1 * c0;
            float v11 = sacc[p][3] * fr1 * c1;
            if (edge) {
                const int tl0 = p * 8 + (lane & 3) * 2;
                const int d00 = dbase + rl0 - tl0;
                if (d00 < 0)     v00 = 0.f;
                if (d00 - 1 < 0) v01 = 0.f;
                if (d00 + 8 < 0) v10 = 0.f;
                if (d00 + 7 < 0) v11 = 0.f;
            }
            const int j = p >> 1, o = (p & 1) * 2;
            SA[j][o]     = packh2(v00, v01);
            SA[j][o + 1] = packh2(v10, v11);
        }

        #pragma unroll
        for (int j = 0; j < 4; j++) {
            uint32_t vr = j * 16 + vrow;
            #pragma unroll
            for (int g = 0; g < 4; g++) {
                uint32_t va = sV + vr * 128 + (((2*g + vnb) ^ (vr & 7)) << 4);
                uint32_t bv[4];
                LDSM4T(bv, va);
                mma_f16(oacc[2*g],   SA[j], bv[0], bv[1]);
                mma_f16(oacc[2*g+1], SA[j], bv[2], bv[3]);
            }
        }

        if (kt + 3 < nkt)
            attn_issue_kv(sb, (kt + 3) & 3, kt + 3,
                          g_kf + koff, g_vf + koff, tid);
        CP_COMMIT();
    }

    // ---- epilogue: y = O * silu(g) -> fp16 hi/lo for the out-projection
    const size_t row0 = (size_t)(b * S_ + qt * QT_ + rl0);
    #pragma unroll
    for (int p = 0; p < 8; p++) {
        const int col = h * DH_ + p * 8 + (lane & 3) * 2;
        #pragma unroll
        for (int half = 0; half < 2; half++) {
            const size_t idx2 = (row0 + half * 8) * D_ + col;
            float2 gv = *(const float2*)(g_g + idx2);
            float s0 = gv.x / (1.f + expf(-gv.x));
            float s1 = gv.y / (1.f + expf(-gv.y));
            float y0 = oacc[p][half*2 + 0] * s0;
            float y1 = oacc[p][half*2 + 1] * s1;
            uint32_t lo;
            uint32_t hi = packh2_hilo(y0, y1, lo);
            *(uint32_t*)&g_aoh[idx2] = hi;
            *(uint32_t*)&g_aol[idx2] = lo;
        }
    }
}

// ============================================================================
extern "C" void kernel_launch(void* const* d_in, const int* in_sizes, int n_in,
                              void* d_out, int out_size)
{
    const float* x  = (const float*)d_in[0];
    const float* wq = (const float*)d_in[1];
    const float* wk = (const float*)d_in[2];
    const float* wv = (const float*)d_in[3];
    const float* wg = (const float*)d_in[4];
    const float* wo = (const float*)d_in[5];
    float* out = (float*)d_out;

    cudaFuncSetAttribute(gemm_qkvg_f16,
                         cudaFuncAttributeMaxDynamicSharedMemorySize, GEMM_SMEM);
    cudaFuncSetAttribute(gemm_out_f16,
                         cudaFuncAttributeMaxDynamicSharedMemorySize, GEMM_SMEM);
    cudaFuncSetAttribute(attn_kernel,
                         cudaFuncAttributeMaxDynamicSharedMemorySize, ATTN_SMEM);

    split_kernel<<<dim3(M_*D_/4/256, 6), 256>>>(x, wq, wk, wv, wg, wo);

    gemm_qkvg_f16<<<dim3(D_/128, M_/128, 4), 256, GEMM_SMEM>>>();

    int nrope = M_ * H_ * 32;
    rope_kernel<<<(nrope + 255) / 256, 256>>>();

    attn_kernel<<<(S_/QT_) * H_ * B_, 256, ATTN_SMEM>>>();

    gemm_out_f16<<<dim3(D_/128, M_/128), 256, GEMM_SMEM>>>(out);
}

// round 12
// speedup vs baseline: 2.2292x; 1.0258x over previous
#include <cuda_runtime.h>
#include <cuda_fp16.h>
#include <stdint.h>
#include <math.h>

#define B_  2
#define S_  2048
#define D_  1024
#define H_  16
#define DH_ 64
#define M_  (B_*S_)   /* 4096 */

// ---- scratch (static device allocations; no cudaMalloc allowed) ----
__device__ __align__(16) float g_g [M_*D_];

// fp16 attention operands (q/k written by GEMM, rotated in place by rope)
__device__ __align__(16) __half g_qf[M_*D_], g_kf[M_*D_], g_vf[M_*D_];

// fp16 hi/lo split operands for the GEMMs (A side split, B side hi only)
__device__ __align__(16) __half g_xh [M_*D_], g_xl [M_*D_];
__device__ __align__(16) __half g_aoh[M_*D_], g_aol[M_*D_];
__device__ __align__(16) __half g_wqh[D_*D_];
__device__ __align__(16) __half g_wkh[D_*D_];
__device__ __align__(16) __half g_wvh[D_*D_];
__device__ __align__(16) __half g_wgh[D_*D_];
__device__ __align__(16) __half g_woh[D_*D_];

// ============================================================================
// PTX helpers
// ============================================================================
__device__ __forceinline__ uint32_t smem_u32(const void* p)
{
    uint32_t a;
    asm("{ .reg .u64 t; cvta.to.shared.u64 t, %1; cvt.u32.u64 %0, t; }"
        : "=r"(a) : "l"(p));
    return a;
}

__device__ __forceinline__ void cp16(uint32_t s, const void* g)
{
    asm volatile("cp.async.cg.shared.global [%0], [%1], 16;" :: "r"(s), "l"(g));
}
#define CP_COMMIT() asm volatile("cp.async.commit_group;" ::: "memory")
template<int N> __device__ __forceinline__ void cp_wait()
{
    asm volatile("cp.async.wait_group %0;" :: "n"(N) : "memory");
}

#define LDSM4(r, addr) \
    asm volatile("ldmatrix.sync.aligned.m8n8.x4.shared.b16 {%0,%1,%2,%3}, [%4];" \
        : "=r"((r)[0]), "=r"((r)[1]), "=r"((r)[2]), "=r"((r)[3]) : "r"(addr))

#define LDSM4T(r, addr) \
    asm volatile("ldmatrix.sync.aligned.m8n8.x4.trans.shared.b16 {%0,%1,%2,%3}, [%4];" \
        : "=r"((r)[0]), "=r"((r)[1]), "=r"((r)[2]), "=r"((r)[3]) : "r"(addr))

__device__ __forceinline__ void mma_f16(float c[4], const uint32_t a[4],
                                        uint32_t b0, uint32_t b1)
{
    asm volatile(
        "mma.sync.aligned.m16n8k16.row.col.f32.f16.f16.f32 "
        "{%0,%1,%2,%3},{%4,%5,%6,%7},{%8,%9},{%0,%1,%2,%3};"
        : "+f"(c[0]), "+f"(c[1]), "+f"(c[2]), "+f"(c[3])
        : "r"(a[0]), "r"(a[1]), "r"(a[2]), "r"(a[3]), "r"(b0), "r"(b1));
}

__device__ __forceinline__ uint32_t packh2(float a, float b)
{
    __half2 h = __floats2half2_rn(a, b);
    return *(uint32_t*)&h;
}

__device__ __forceinline__ uint32_t packh2_hilo(float a, float b, uint32_t& lo)
{
    __half ha = __float2half_rn(a), hb = __float2half_rn(b);
    float ra = a - __half2float(ha);
    float rb = b - __half2float(hb);
    __half la = __float2half_rn(ra), lb = __float2half_rn(rb);
    lo = (uint32_t)__half_as_ushort(la) | ((uint32_t)__half_as_ushort(lb) << 16);
    return (uint32_t)__half_as_ushort(ha) | ((uint32_t)__half_as_ushort(hb) << 16);
}

__device__ __forceinline__ uint32_t hf_split_hi(float a, float& rem)
{
    __half h = __float2half_rn(a);
    rem = a - __half2float(h);
    return (uint32_t)__half_as_ushort(h);
}

// ============================================================================
// fp16 hi/lo split kernel: x -> hi+lo, weights -> hi only
// ============================================================================
__global__ void split_kernel(const float* __restrict__ x,
                             const float* __restrict__ wq, const float* __restrict__ wk,
                             const float* __restrict__ wv, const float* __restrict__ wg,
                             const float* __restrict__ wo)
{
    const float* src;
    __half *dh, *dl;
    int n4;
    switch (blockIdx.y) {
        case 0: src = x;  dh = g_xh;  dl = g_xl;     n4 = M_*D_/4; break;
        case 1: src = wq; dh = g_wqh; dl = nullptr;  n4 = D_*D_/4; break;
        case 2: src = wk; dh = g_wkh; dl = nullptr;  n4 = D_*D_/4; break;
        case 3: src = wv; dh = g_wvh; dl = nullptr;  n4 = D_*D_/4; break;
        case 4: src = wg; dh = g_wgh; dl = nullptr;  n4 = D_*D_/4; break;
        default:src = wo; dh = g_woh; dl = nullptr;  n4 = D_*D_/4; break;
    }
    int i4 = blockIdx.x * blockDim.x + threadIdx.x;
    if (i4 >= n4) return;
    float4 v = ((const float4*)src)[i4];
    float r0, r1, r2, r3;
    uint32_t h0 = hf_split_hi(v.x, r0), h1 = hf_split_hi(v.y, r1);
    uint32_t h2 = hf_split_hi(v.z, r2), h3 = hf_split_hi(v.w, r3);
    ((uint2*)dh)[i4] = make_uint2(h0 | (h1 << 16), h2 | (h3 << 16));
    if (dl) {
        uint32_t l0 = packh2(r0, r1);
        uint32_t l1 = packh2(r2, r3);
        ((uint2*)dl)[i4] = make_uint2(l0, l1);
    }
}

// ============================================================================
// fp16 2-pass split GEMM: C = (Ah + Al) @ Bh^T, fp32 accumulate.
// OM=0: float C.  OM=1: fp16 C.
// BM=BN=128, BK=32, 256 threads, 4-stage cp.async; stage = Ah|Al|Bh (24 KB).
// ============================================================================
#define BKH     32
#define NITG    (D_/BKH)
#define TILE_HB (128*BKH*2)           /* 8192 B */
#define STAGE_B (3*TILE_HB)           /* 24576 B */
#define NSTG    4
#define GEMM_SMEM (NSTG*STAGE_B)      /* 98304 B */

struct GemmSrcs { const __half *ah, *al, *bh; };

__device__ __forceinline__ void issue_stage(uint32_t sb, int stage, int k0,
                                            const GemmSrcs& s, int tid)
{
    const __half* srcs[3] = { s.ah, s.al, s.bh };
    const uint32_t stg = sb + stage * STAGE_B;
    #pragma unroll
    for (int m = 0; m < 3; m++) {
        const __half* src = srcs[m] + k0;
        const uint32_t tb = stg + m * TILE_HB;
        #pragma unroll
        for (int i = 0; i < 2; i++) {
            int j   = tid + i * 256;
            int row = j >> 2;
            int c   = j & 3;
            int csw = c ^ ((row >> 1) & 3);
            cp16(tb + row * 64 + csw * 16, src + (size_t)row * D_ + c * 8);
        }
    }
}

template<int OM>
__device__ __forceinline__ void gemm_f16_body(const GemmSrcs& s, float* C,
                                              __half* Cf)
{
    extern __shared__ char dsm[];
    const uint32_t sb = smem_u32(dsm);
    const int tid  = threadIdx.x;
    const int lane = tid & 31;
    const int w    = tid >> 5;
    const int wm   = (w >> 2) * 64;
    const int wn   = (w & 3) * 32;

    const int l7 = lane & 7;
    uint32_t aoff[4], asw[4], boff[2], bsw[2];
    const int akb = (lane >> 4) & 1;
    const int bkb = (lane >> 3) & 1;
    #pragma unroll
    for (int mf = 0; mf < 4; mf++) {
        int row = wm + mf * 16 + l7 + 8 * ((lane >> 3) & 1);
        aoff[mf] = row * 64;
        asw[mf]  = (row >> 1) & 3;
    }
    #pragma unroll
    for (int nfp = 0; nfp < 2; nfp++) {
        int row = wn + nfp * 16 + l7 + 8 * ((lane >> 4) & 1);
        boff[nfp] = row * 64;
        bsw[nfp]  = (row >> 1) & 3;
    }

    float acc[4][4][4];
    #pragma unroll
    for (int i = 0; i < 4; i++)
        #pragma unroll
        for (int j = 0; j < 4; j++)
            #pragma unroll
            for (int r = 0; r < 4; r++) acc[i][j][r] = 0.f;

    // prologue: stages 0..2 (3 committed groups)
    issue_stage(sb, 0, 0, s, tid);       CP_COMMIT();
    issue_stage(sb, 1, BKH, s, tid);     CP_COMMIT();
    issue_stage(sb, 2, 2 * BKH, s, tid); CP_COMMIT();

    for (int it = 0; it < NITG; it++) {
        cp_wait<2>();
        __syncthreads();
        if (it + 3 < NITG) issue_stage(sb, (it + 3) % NSTG, (it + 3) * BKH, s, tid);
        CP_COMMIT();   // one group per iteration (may be empty) keeps wait<2> exact

        const uint32_t stg = sb + (it % NSTG) * STAGE_B;
        const uint32_t sAh = stg, sAl = stg + TILE_HB;
        const uint32_t sBh = stg + 2*TILE_HB;

        #pragma unroll
        for (int ks = 0; ks < 2; ks++) {
            uint32_t bh[2][4];
            #pragma unroll
            for (int nfp = 0; nfp < 2; nfp++) {
                uint32_t off = boff[nfp] + ((((uint32_t)(2*ks + bkb)) ^ bsw[nfp]) << 4);
                LDSM4(bh[nfp], sBh + off);
            }
            #pragma unroll
            for (int mf = 0; mf < 4; mf++) {
                uint32_t off = aoff[mf] + ((((uint32_t)(2*ks + akb)) ^ asw[mf]) << 4);
                uint32_t ah[4], al[4];
                LDSM4(ah, sAh + off);
                LDSM4(al, sAl + off);
                #pragma unroll
                for (int nf = 0; nf < 4; nf++) {
                    uint32_t b0 = bh[nf >> 1][(nf & 1)*2], b1 = bh[nf >> 1][(nf & 1)*2 + 1];
                    mma_f16(acc[mf][nf], ah, b0, b1);
                    mma_f16(acc[mf][nf], al, b0, b1);
                }
            }
        }
        __syncthreads();
    }

    const int rbase = blockIdx.y * 128 + wm + (lane >> 2);
    const int cbase = blockIdx.x * 128 + wn + ((lane & 3) << 1);
    #pragma unroll
    for (int mf = 0; mf < 4; mf++)
        #pragma unroll
        for (int nf = 0; nf < 4; nf++) {
            const size_t i0 = (size_t)(rbase + mf*16) * D_ + cbase + nf*8;
            const size_t i1 = i0 + (size_t)8 * D_;
            if (OM == 0) {
                *(float2*)(C + i0) = make_float2(acc[mf][nf][0], acc[mf][nf][1]);
                *(float2*)(C + i1) = make_float2(acc[mf][nf][2], acc[mf][nf][3]);
            } else {
                *(uint32_t*)&Cf[i0] = packh2(acc[mf][nf][0], acc[mf][nf][1]);
                *(uint32_t*)&Cf[i1] = packh2(acc[mf][nf][2], acc[mf][nf][3]);
            }
        }
}

__global__ __launch_bounds__(256, 2)
void gemm_qkvg_f16()
{
    GemmSrcs s;
    const size_t yoff = (size_t)blockIdx.y * 128 * D_;
    const size_t xoff = (size_t)blockIdx.x * 128 * D_;
    s.ah = g_xh + yoff; s.al = g_xl + yoff;
    switch (blockIdx.z) {
        case 0:  s.bh = g_wqh + xoff; gemm_f16_body<1>(s, nullptr, g_qf); break;
        case 1:  s.bh = g_wkh + xoff; gemm_f16_body<1>(s, nullptr, g_kf); break;
        case 2:  s.bh = g_wvh + xoff; gemm_f16_body<1>(s, nullptr, g_vf); break;
        default: s.bh = g_wgh + xoff; gemm_f16_body<0>(s, g_g, nullptr);  break;
    }
}

__global__ __launch_bounds__(256, 2)
void gemm_out_f16(float* __restrict__ C)
{
    GemmSrcs s;
    const size_t yoff = (size_t)blockIdx.y * 128 * D_;
    const size_t xoff = (size_t)blockIdx.x * 128 * D_;
    s.ah = g_aoh + yoff; s.al = g_aol + yoff;
    s.bh = g_woh + xoff;
    gemm_f16_body<0>(s, C, nullptr);
}

// ============================================================================
// RoPE: rotate q/k fp16 in place
// ============================================================================
__global__ void rope_kernel()
{
    int i = blockIdx.x * blockDim.x + threadIdx.x;
    if (i >= M_ * H_ * 32) return;
    int j  = i & 31;
    int h  = (i >> 5) & (H_ - 1);
    int bs = i >> 9;
    int s  = bs & (S_ - 1);

    float inv = exp2f(-(float)j * 0.41524101186092029f);
    float ang = (float)s * inv;
    float sn, cs;
    sincosf(ang, &sn, &cs);

    int base = bs * D_ + h * DH_ + j;
    float q1 = __half2float(g_qf[base]), q2 = __half2float(g_qf[base + 32]);
    float k1 = __half2float(g_kf[base]), k2 = __half2float(g_kf[base + 32]);
    g_qf[base]      = __float2half_rn(q1 * cs - q2 * sn);
    g_qf[base + 32] = __float2half_rn(q2 * cs + q1 * sn);
    g_kf[base]      = __float2half_rn(k1 * cs - k2 * sn);
    g_kf[base + 32] = __float2half_rn(k2 * cs + k1 * sn);
}

// ============================================================================
// fp16 single-pass flash retention, 4-stage cp.async K/V pipeline (R10/R11).
// smem: Qf 16K | 4 stages x (K 8K | V 8K) = 80 KB. 2 CTAs/SM.
// ============================================================================
#define QT_ 128
#define KT_ 64
#define OFF_QF 0
#define OFF_ST 16384
#define STG_SZ 16384
#define ATTN_SMEM 81920

__device__ __forceinline__ void attn_issue_q(uint32_t sb, const __half* qf, int tid)
{
    #pragma unroll
    for (int i = 0; i < 4; i++) {
        int u   = tid + i * 256;
        int row = u >> 3;
        int c   = u & 7;
        int cs  = c ^ (row & 7);
        cp16(sb + OFF_QF + row * 128 + cs * 16, qf + (size_t)row * D_ + c * 8);
    }
}

__device__ __forceinline__ void attn_issue_kv(uint32_t sb, int stage, int kt,
                                              const __half* kf, const __half* vf,
                                              int tid)
{
    const __half* srcs[2] = { kf + (size_t)(kt * KT_) * D_,
                              vf + (size_t)(kt * KT_) * D_ };
    const uint32_t stg = sb + OFF_ST + stage * STG_SZ;
    #pragma unroll
    for (int m = 0; m < 2; m++) {
        const __half* src = srcs[m];
        const uint32_t tb = stg + m * 8192;
        #pragma unroll
        for (int i = 0; i < 2; i++) {
            int u   = tid + i * 256;
            int row = u >> 3;
            int c   = u & 7;
            int cs  = c ^ (row & 7);
            cp16(tb + row * 128 + cs * 16, src + (size_t)row * D_ + c * 8);
        }
    }
}

__global__ __launch_bounds__(256, 2)
void attn_kernel()
{
    extern __shared__ char dsm[];
    const uint32_t sb = smem_u32(dsm);

    // global heavy-first: all (h,b) of the heaviest qt launch first
    const int idx = blockIdx.x;
    const int qt  = (S_/QT_ - 1) - (idx >> 5);
    const int h   = idx & 15;
    const int b   = (idx >> 4) & 1;

    const int tid  = threadIdx.x;
    const int lane = tid & 31;
    const int w    = tid >> 5;
    const int l7   = lane & 7;

    const float gamma = 1.0f - exp2f(-5.0f - (float)h);
    const float lg    = log2f(gamma);

    const size_t qoff = (size_t)(b * S_ + qt * QT_) * D_ + h * DH_;
    const size_t koff = (size_t)(b * S_) * D_ + h * DH_;
    const int nkt = 2 * qt + 2;

    attn_issue_q(sb, g_qf + qoff, tid);
    attn_issue_kv(sb, 0, 0, g_kf + koff, g_vf + koff, tid);
    CP_COMMIT();
    if (1 < nkt) attn_issue_kv(sb, 1, 1, g_kf + koff, g_vf + koff, tid);
    CP_COMMIT();
    if (2 < nkt) attn_issue_kv(sb, 2, 2, g_kf + koff, g_vf + koff, tid);
    CP_COMMIT();

    const int rl0 = w * 16 + (lane >> 2);
    const float grow0 = 0.125f * exp2f(lg * (float)rl0);
    const float grow1 = 0.125f * exp2f(lg * (float)(rl0 + 8));
    const float ginv  = exp2f(-lg);
    float gc[8];
    #pragma unroll
    for (int p = 0; p < 8; p++)
        gc[p] = exp2f(-lg * (float)(p * 8 + (lane & 3) * 2));

    float oacc[8][4];
    #pragma unroll
    for (int p = 0; p < 8; p++)
        #pragma unroll
        for (int r = 0; r < 4; r++) oacc[p][r] = 0.f;

    const uint32_t arow = (uint32_t)(w * 16 + l7 + 8 * ((lane >> 3) & 1));
    const uint32_t akb  = (lane >> 4) & 1;
    const uint32_t brow = (uint32_t)(l7 + 8 * ((lane >> 4) & 1));
    const uint32_t bkb  = (lane >> 3) & 1;
    const uint32_t vrow = (uint32_t)(l7 + 8 * ((lane >> 3) & 1));
    const uint32_t vnb  = (lane >> 4) & 1;

    for (int kt = 0; kt < nkt; kt++) {
        cp_wait<2>();
        __syncthreads();

        const uint32_t stg = sb + OFF_ST + (kt & 3) * STG_SZ;
        const uint32_t sK = stg, sV = stg + 8192;

        float sacc[8][4];
        #pragma unroll
        for (int p = 0; p < 8; p++)
            #pragma unroll
            for (int r = 0; r < 4; r++) sacc[p][r] = 0.f;

        #pragma unroll
        for (int ks = 0; ks < 4; ks++) {
            uint32_t qa = sb + OFF_QF + arow * 128 + (((2*ks + akb) ^ (arow & 7)) << 4);
            uint32_t ah[4];
            LDSM4(ah, qa);
            #pragma unroll
            for (int g = 0; g < 4; g++) {
                uint32_t br = g * 16 + brow;
                uint32_t ba = sK + br * 128 + (((2*ks + bkb) ^ (br & 7)) << 4);
                uint32_t bh[4];
                LDSM4(bh, ba);
                mma_f16(sacc[2*g],   ah, bh[0], bh[1]);
                mma_f16(sacc[2*g+1], ah, bh[2], bh[3]);
            }
        }

        const int   dbase = qt * QT_ - kt * KT_;
        const float f     = exp2f(lg * (float)dbase);
        const float fr0   = f * grow0;
        const float fr1   = f * grow1;
        const bool  edge  = (dbase < KT_);
        uint32_t SA[4][4];
        #pragma unroll
        for (int p = 0; p < 8; p++) {
            const float c0 = gc[p], c1 = gc[p] * ginv;
            float v00 = sacc[p][0] * fr0 * c0;
            float v01 = sacc[p][1] * fr0 * c1;
            float v10 = sacc[p][2] * fr1 * c0;
            float v11 = sacc[p][3] * fr1 * c1;
            if (edge) {
                const int tl0 = p * 8 + (lane & 3) * 2;
                const int d00 = dbase + rl0 - tl0;
                if (d00 < 0)     v00 = 0.f;
                if (d00 - 1 < 0) v01 = 0.f;
                if (d00 + 8 < 0) v10 = 0.f;
                if (d00 + 7 < 0) v11 = 0.f;
            }
            const int j = p >> 1, o = (p & 1) * 2;
            SA[j][o]     = packh2(v00, v01);
            SA[j][o + 1] = packh2(v10, v11);
        }

        #pragma unroll
        for (int j = 0; j < 4; j++) {
            uint32_t vr = j * 16 + vrow;
            #pragma unroll
            for (int g = 0; g < 4; g++) {
                uint32_t va = sV + vr * 128 + (((2*g + vnb) ^ (vr & 7)) << 4);
                uint32_t bv[4];
                LDSM4T(bv, va);
                mma_f16(oacc[2*g],   SA[j], bv[0], bv[1]);
                mma_f16(oacc[2*g+1], SA[j], bv[2], bv[3]);
            }
        }

        if (kt + 3 < nkt)
            attn_issue_kv(sb, (kt + 3) & 3, kt + 3,
                          g_kf + koff, g_vf + koff, tid);
        CP_COMMIT();
    }

    // ---- epilogue: y = O * silu(g) -> fp16 hi/lo for the out-projection
    const size_t row0 = (size_t)(b * S_ + qt * QT_ + rl0);
    #pragma unroll
    for (int p = 0; p < 8; p++) {
        const int col = h * DH_ + p * 8 + (lane & 3) * 2;
        #pragma unroll
        for (int half = 0; half < 2; half++) {
            const size_t idx2 = (row0 + half * 8) * D_ + col;
            float2 gv = *(const float2*)(g_g + idx2);
            float s0 = gv.x / (1.f + expf(-gv.x));
            float s1 = gv.y / (1.f + expf(-gv.y));
            float y0 = oacc[p][half*2 + 0] * s0;
            float y1 = oacc[p][half*2 + 1] * s1;
            uint32_t lo;
            uint32_t hi = packh2_hilo(y0, y1, lo);
            *(uint32_t*)&g_aoh[idx2] = hi;
            *(uint32_t*)&g_aol[idx2] = lo;
        }
    }
}

// ============================================================================
extern "C" void kernel_launch(void* const* d_in, const int* in_sizes, int n_in,
                              void* d_out, int out_size)
{
    const float* x  = (const float*)d_in[0];
    const float* wq = (const float*)d_in[1];
    const float* wk = (const float*)d_in[2];
    const float* wv = (const float*)d_in[3];
    const float* wg = (const float*)d_in[4];
    const float* wo = (const float*)d_in[5];
    float* out = (float*)d_out;

    cudaFuncSetAttribute(gemm_qkvg_f16,
                         cudaFuncAttributeMaxDynamicSharedMemorySize, GEMM_SMEM);
    cudaFuncSetAttribute(gemm_out_f16,
                         cudaFuncAttributeMaxDynamicSharedMemorySize, GEMM_SMEM);
    cudaFuncSetAttribute(attn_kernel,
                         cudaFuncAttributeMaxDynamicSharedMemorySize, ATTN_SMEM);

    split_kernel<<<dim3(M_*D_/4/256, 6), 256>>>(x, wq, wk, wv, wg, wo);

    gemm_qkvg_f16<<<dim3(D_/128, M_/128, 4), 256, GEMM_SMEM>>>();

    int nrope = M_ * H_ * 32;
    rope_kernel<<<(nrope + 255) / 256, 256>>>();

    attn_kernel<<<(S_/QT_) * H_ * B_, 256, ATTN_SMEM>>>();

    gemm_out_f16<<<dim3(D_/128, M_/128), 256, GEMM_SMEM>>>(out);
}

// round 13
// speedup vs baseline: 2.6290x; 1.1794x over previous
#include <cuda_runtime.h>
#include <cuda_fp16.h>
#include <stdint.h>
#include <math.h>

#define B_  2
#define S_  2048
#define D_  1024
#define H_  16
#define DH_ 64
#define M_  (B_*S_)   /* 4096 */

// ---- scratch (static device allocations; no cudaMalloc allowed) ----
__device__ __align__(16) float g_g [M_*D_];

// fp16 attention operands (q/k written by GEMM, rotated in place by rope)
__device__ __align__(16) __half g_qf[M_*D_], g_kf[M_*D_], g_vf[M_*D_];

// fp16 hi/lo split operands for the GEMMs (A side split, B side hi only)
__device__ __align__(16) __half g_xh [M_*D_], g_xl [M_*D_];
__device__ __align__(16) __half g_aoh[M_*D_], g_aol[M_*D_];
__device__ __align__(16) __half g_wqh[D_*D_];
__device__ __align__(16) __half g_wkh[D_*D_];
__device__ __align__(16) __half g_wvh[D_*D_];
__device__ __align__(16) __half g_wgh[D_*D_];
__device__ __align__(16) __half g_woh[D_*D_];

// ============================================================================
// PTX helpers
// ============================================================================
__device__ __forceinline__ uint32_t smem_u32(const void* p)
{
    uint32_t a;
    asm("{ .reg .u64 t; cvta.to.shared.u64 t, %1; cvt.u32.u64 %0, t; }"
        : "=r"(a) : "l"(p));
    return a;
}

__device__ __forceinline__ void cp16(uint32_t s, const void* g)
{
    asm volatile("cp.async.cg.shared.global [%0], [%1], 16;" :: "r"(s), "l"(g));
}
#define CP_COMMIT() asm volatile("cp.async.commit_group;" ::: "memory")
template<int N> __device__ __forceinline__ void cp_wait()
{
    asm volatile("cp.async.wait_group %0;" :: "n"(N) : "memory");
}

#define LDSM4(r, addr) \
    asm volatile("ldmatrix.sync.aligned.m8n8.x4.shared.b16 {%0,%1,%2,%3}, [%4];" \
        : "=r"((r)[0]), "=r"((r)[1]), "=r"((r)[2]), "=r"((r)[3]) : "r"(addr))

#define LDSM4T(r, addr) \
    asm volatile("ldmatrix.sync.aligned.m8n8.x4.trans.shared.b16 {%0,%1,%2,%3}, [%4];" \
        : "=r"((r)[0]), "=r"((r)[1]), "=r"((r)[2]), "=r"((r)[3]) : "r"(addr))

__device__ __forceinline__ void mma_f16(float c[4], const uint32_t a[4],
                                        uint32_t b0, uint32_t b1)
{
    asm volatile(
        "mma.sync.aligned.m16n8k16.row.col.f32.f16.f16.f32 "
        "{%0,%1,%2,%3},{%4,%5,%6,%7},{%8,%9},{%0,%1,%2,%3};"
        : "+f"(c[0]), "+f"(c[1]), "+f"(c[2]), "+f"(c[3])
        : "r"(a[0]), "r"(a[1]), "r"(a[2]), "r"(a[3]), "r"(b0), "r"(b1));
}

__device__ __forceinline__ uint32_t packh2(float a, float b)
{
    __half2 h = __floats2half2_rn(a, b);
    return *(uint32_t*)&h;
}

__device__ __forceinline__ uint32_t packh2_hilo(float a, float b, uint32_t& lo)
{
    __half ha = __float2half_rn(a), hb = __float2half_rn(b);
    float ra = a - __half2float(ha);
    float rb = b - __half2float(hb);
    __half la = __float2half_rn(ra), lb = __float2half_rn(rb);
    lo = (uint32_t)__half_as_ushort(la) | ((uint32_t)__half_as_ushort(lb) << 16);
    return (uint32_t)__half_as_ushort(ha) | ((uint32_t)__half_as_ushort(hb) << 16);
}

__device__ __forceinline__ uint32_t hf_split_hi(float a, float& rem)
{
    __half h = __float2half_rn(a);
    rem = a - __half2float(h);
    return (uint32_t)__half_as_ushort(h);
}

// ============================================================================
// fp16 hi/lo split kernel: x -> hi+lo, weights -> hi only
// ============================================================================
__global__ void split_kernel(const float* __restrict__ x,
                             const float* __restrict__ wq, const float* __restrict__ wk,
                             const float* __restrict__ wv, const float* __restrict__ wg,
                             const float* __restrict__ wo)
{
    const float* src;
    __half *dh, *dl;
    int n4;
    switch (blockIdx.y) {
        case 0: src = x;  dh = g_xh;  dl = g_xl;     n4 = M_*D_/4; break;
        case 1: src = wq; dh = g_wqh; dl = nullptr;  n4 = D_*D_/4; break;
        case 2: src = wk; dh = g_wkh; dl = nullptr;  n4 = D_*D_/4; break;
        case 3: src = wv; dh = g_wvh; dl = nullptr;  n4 = D_*D_/4; break;
        case 4: src = wg; dh = g_wgh; dl = nullptr;  n4 = D_*D_/4; break;
        default:src = wo; dh = g_woh; dl = nullptr;  n4 = D_*D_/4; break;
    }
    int i4 = blockIdx.x * blockDim.x + threadIdx.x;
    if (i4 >= n4) return;
    float4 v = ((const float4*)src)[i4];
    float r0, r1, r2, r3;
    uint32_t h0 = hf_split_hi(v.x, r0), h1 = hf_split_hi(v.y, r1);
    uint32_t h2 = hf_split_hi(v.z, r2), h3 = hf_split_hi(v.w, r3);
    ((uint2*)dh)[i4] = make_uint2(h0 | (h1 << 16), h2 | (h3 << 16));
    if (dl) {
        uint32_t l0 = packh2(r0, r1);
        uint32_t l1 = packh2(r2, r3);
        ((uint2*)dl)[i4] = make_uint2(l0, l1);
    }
}

// ============================================================================
// fp16 GEMM: C = A @ Bh^T, fp32 accumulate.
// SPLITA=1: A = Ah + Al (2-pass).  SPLITA=0: A = Ah (1-pass).
// OM=0: float C.  OM=1: fp16 C.
// BM=BN=128, BK=32, 256 threads, 4-stage cp.async.
// stage = Ah|[Al]|Bh  (SPLITA ? 24 KB : 16 KB)
// ============================================================================
#define BKH     32
#define NITG    (D_/BKH)
#define TILE_HB (128*BKH*2)           /* 8192 B */
#define GEMM_SMEM (4*3*TILE_HB)       /* 98304 B (max: SPLITA 4-stage) */

struct GemmSrcs { const __half *ah, *al, *bh; };

template<bool SPLITA>
__device__ __forceinline__ void issue_stage(uint32_t sb, int stage, int k0,
                                            const GemmSrcs& s, int tid)
{
    const int NT = SPLITA ? 3 : 2;
    const __half* srcs[3] = { s.ah, SPLITA ? s.al : s.bh, s.bh };
    const uint32_t stg = sb + stage * (NT * TILE_HB);
    #pragma unroll
    for (int m = 0; m < NT; m++) {
        const __half* src = srcs[m] + k0;
        const uint32_t tb = stg + m * TILE_HB;
        #pragma unroll
        for (int i = 0; i < 2; i++) {
            int j   = tid + i * 256;
            int row = j >> 2;
            int c   = j & 3;
            int csw = c ^ ((row >> 1) & 3);
            cp16(tb + row * 64 + csw * 16, src + (size_t)row * D_ + c * 8);
        }
    }
}

template<int OM, bool SPLITA>
__device__ __forceinline__ void gemm_f16_body(const GemmSrcs& s, float* C,
                                              __half* Cf)
{
    extern __shared__ char dsm[];
    const uint32_t sb = smem_u32(dsm);
    const int tid  = threadIdx.x;
    const int lane = tid & 31;
    const int w    = tid >> 5;
    const int wm   = (w >> 2) * 64;
    const int wn   = (w & 3) * 32;
    const int NT   = SPLITA ? 3 : 2;

    const int l7 = lane & 7;
    uint32_t aoff[4], asw[4], boff[2], bsw[2];
    const int akb = (lane >> 4) & 1;
    const int bkb = (lane >> 3) & 1;
    #pragma unroll
    for (int mf = 0; mf < 4; mf++) {
        int row = wm + mf * 16 + l7 + 8 * ((lane >> 3) & 1);
        aoff[mf] = row * 64;
        asw[mf]  = (row >> 1) & 3;
    }
    #pragma unroll
    for (int nfp = 0; nfp < 2; nfp++) {
        int row = wn + nfp * 16 + l7 + 8 * ((lane >> 4) & 1);
        boff[nfp] = row * 64;
        bsw[nfp]  = (row >> 1) & 3;
    }

    float acc[4][4][4];
    #pragma unroll
    for (int i = 0; i < 4; i++)
        #pragma unroll
        for (int j = 0; j < 4; j++)
            #pragma unroll
            for (int r = 0; r < 4; r++) acc[i][j][r] = 0.f;

    // prologue: stages 0..2 (3 committed groups)
    issue_stage<SPLITA>(sb, 0, 0, s, tid);       CP_COMMIT();
    issue_stage<SPLITA>(sb, 1, BKH, s, tid);     CP_COMMIT();
    issue_stage<SPLITA>(sb, 2, 2 * BKH, s, tid); CP_COMMIT();

    for (int it = 0; it < NITG; it++) {
        cp_wait<2>();
        __syncthreads();
        if (it + 3 < NITG)
            issue_stage<SPLITA>(sb, (it + 3) % 4, (it + 3) * BKH, s, tid);
        CP_COMMIT();   // one group per iteration (may be empty) keeps wait<2> exact

        const uint32_t stg = sb + (it % 4) * (NT * TILE_HB);
        const uint32_t sAh = stg;
        const uint32_t sAl = stg + TILE_HB;                 // valid iff SPLITA
        const uint32_t sBh = stg + (NT - 1) * TILE_HB;

        #pragma unroll
        for (int ks = 0; ks < 2; ks++) {
            uint32_t bh[2][4];
            #pragma unroll
            for (int nfp = 0; nfp < 2; nfp++) {
                uint32_t off = boff[nfp] + ((((uint32_t)(2*ks + bkb)) ^ bsw[nfp]) << 4);
                LDSM4(bh[nfp], sBh + off);
            }
            #pragma unroll
            for (int mf = 0; mf < 4; mf++) {
                uint32_t off = aoff[mf] + ((((uint32_t)(2*ks + akb)) ^ asw[mf]) << 4);
                uint32_t ah[4];
                LDSM4(ah, sAh + off);
                if (SPLITA) {
                    uint32_t al[4];
                    LDSM4(al, sAl + off);
                    #pragma unroll
                    for (int nf = 0; nf < 4; nf++) {
                        uint32_t b0 = bh[nf >> 1][(nf & 1)*2], b1 = bh[nf >> 1][(nf & 1)*2 + 1];
                        mma_f16(acc[mf][nf], ah, b0, b1);
                        mma_f16(acc[mf][nf], al, b0, b1);
                    }
                } else {
                    #pragma unroll
                    for (int nf = 0; nf < 4; nf++) {
                        uint32_t b0 = bh[nf >> 1][(nf & 1)*2], b1 = bh[nf >> 1][(nf & 1)*2 + 1];
                        mma_f16(acc[mf][nf], ah, b0, b1);
                    }
                }
            }
        }
        __syncthreads();
    }

    const int rbase = blockIdx.y * 128 + wm + (lane >> 2);
    const int cbase = blockIdx.x * 128 + wn + ((lane & 3) << 1);
    #pragma unroll
    for (int mf = 0; mf < 4; mf++)
        #pragma unroll
        for (int nf = 0; nf < 4; nf++) {
            const size_t i0 = (size_t)(rbase + mf*16) * D_ + cbase + nf*8;
            const size_t i1 = i0 + (size_t)8 * D_;
            if (OM == 0) {
                *(float2*)(C + i0) = make_float2(acc[mf][nf][0], acc[mf][nf][1]);
                *(float2*)(C + i1) = make_float2(acc[mf][nf][2], acc[mf][nf][3]);
            } else {
                *(uint32_t*)&Cf[i0] = packh2(acc[mf][nf][0], acc[mf][nf][1]);
                *(uint32_t*)&Cf[i1] = packh2(acc[mf][nf][2], acc[mf][nf][3]);
            }
        }
}

__global__ __launch_bounds__(256, 2)
void gemm_qkvg_f16()
{
    GemmSrcs s;
    const size_t yoff = (size_t)blockIdx.y * 128 * D_;
    const size_t xoff = (size_t)blockIdx.x * 128 * D_;
    s.ah = g_xh + yoff; s.al = g_xl + yoff;
    switch (blockIdx.z) {
        // Q, K, V projections: 1-pass fp16 (A-lo dropped; error budgeted)
        case 0:  s.bh = g_wqh + xoff; gemm_f16_body<1, false>(s, nullptr, g_qf); break;
        case 1:  s.bh = g_wkh + xoff; gemm_f16_body<1, false>(s, nullptr, g_kf); break;
        case 2:  s.bh = g_wvh + xoff; gemm_f16_body<1, false>(s, nullptr, g_vf); break;
        // Gate: 2-pass (multiplies output directly)
        default: s.bh = g_wgh + xoff; gemm_f16_body<0, true>(s, g_g, nullptr);   break;
    }
}

__global__ __launch_bounds__(256, 2)
void gemm_out_f16(float* __restrict__ C)
{
    GemmSrcs s;
    const size_t yoff = (size_t)blockIdx.y * 128 * D_;
    const size_t xoff = (size_t)blockIdx.x * 128 * D_;
    s.ah = g_aoh + yoff; s.al = g_aol + yoff;
    s.bh = g_woh + xoff;
    gemm_f16_body<0, true>(s, C, nullptr);
}

// ============================================================================
// RoPE: rotate q/k fp16 in place
// ============================================================================
__global__ void rope_kernel()
{
    int i = blockIdx.x * blockDim.x + threadIdx.x;
    if (i >= M_ * H_ * 32) return;
    int j  = i & 31;
    int h  = (i >> 5) & (H_ - 1);
    int bs = i >> 9;
    int s  = bs & (S_ - 1);

    float inv = exp2f(-(float)j * 0.41524101186092029f);
    float ang = (float)s * inv;
    float sn, cs;
    sincosf(ang, &sn, &cs);

    int base = bs * D_ + h * DH_ + j;
    float q1 = __half2float(g_qf[base]), q2 = __half2float(g_qf[base + 32]);
    float k1 = __half2float(g_kf[base]), k2 = __half2float(g_kf[base + 32]);
    g_qf[base]      = __float2half_rn(q1 * cs - q2 * sn);
    g_qf[base + 32] = __float2half_rn(q2 * cs + q1 * sn);
    g_kf[base]      = __float2half_rn(k1 * cs - k2 * sn);
    g_kf[base + 32] = __float2half_rn(k2 * cs + k1 * sn);
}

// ============================================================================
// fp16 single-pass flash retention, 4-stage cp.async K/V pipeline (R10-R12).
// smem: Qf 16K | 4 stages x (K 8K | V 8K) = 80 KB. 2 CTAs/SM.
// ============================================================================
#define QT_ 128
#define KT_ 64
#define OFF_QF 0
#define OFF_ST 16384
#define STG_SZ 16384
#define ATTN_SMEM 81920

__device__ __forceinline__ void attn_issue_q(uint32_t sb, const __half* qf, int tid)
{
    #pragma unroll
    for (int i = 0; i < 4; i++) {
        int u   = tid + i * 256;
        int row = u >> 3;
        int c   = u & 7;
        int cs  = c ^ (row & 7);
        cp16(sb + OFF_QF + row * 128 + cs * 16, qf + (size_t)row * D_ + c * 8);
    }
}

__device__ __forceinline__ void attn_issue_kv(uint32_t sb, int stage, int kt,
                                              const __half* kf, const __half* vf,
                                              int tid)
{
    const __half* srcs[2] = { kf + (size_t)(kt * KT_) * D_,
                              vf + (size_t)(kt * KT_) * D_ };
    const uint32_t stg = sb + OFF_ST + stage * STG_SZ;
    #pragma unroll
    for (int m = 0; m < 2; m++) {
        const __half* src = srcs[m];
        const uint32_t tb = stg + m * 8192;
        #pragma unroll
        for (int i = 0; i < 2; i++) {
            int u   = tid + i * 256;
            int row = u >> 3;
            int c   = u & 7;
            int cs  = c ^ (row & 7);
            cp16(tb + row * 128 + cs * 16, src + (size_t)row * D_ + c * 8);
        }
    }
}

__global__ __launch_bounds__(256, 2)
void attn_kernel()
{
    extern __shared__ char dsm[];
    const uint32_t sb = smem_u32(dsm);

    // global heavy-first: all (h,b) of the heaviest qt launch first
    const int idx = blockIdx.x;
    const int qt  = (S_/QT_ - 1) - (idx >> 5);
    const int h   = idx & 15;
    const int b   = (idx >> 4) & 1;

    const int tid  = threadIdx.x;
    const int lane = tid & 31;
    const int w    = tid >> 5;
    const int l7   = lane & 7;

    const float gamma = 1.0f - exp2f(-5.0f - (float)h);
    const float lg    = log2f(gamma);

    const size_t qoff = (size_t)(b * S_ + qt * QT_) * D_ + h * DH_;
    const size_t koff = (size_t)(b * S_) * D_ + h * DH_;
    const int nkt = 2 * qt + 2;

    attn_issue_q(sb, g_qf + qoff, tid);
    attn_issue_kv(sb, 0, 0, g_kf + koff, g_vf + koff, tid);
    CP_COMMIT();
    if (1 < nkt) attn_issue_kv(sb, 1, 1, g_kf + koff, g_vf + koff, tid);
    CP_COMMIT();
    if (2 < nkt) attn_issue_kv(sb, 2, 2, g_kf + koff, g_vf + koff, tid);
    CP_COMMIT();

    const int rl0 = w * 16 + (lane >> 2);
    const float grow0 = 0.125f * exp2f(lg * (float)rl0);
    const float grow1 = 0.125f * exp2f(lg * (float)(rl0 + 8));
    const float ginv  = exp2f(-lg);
    float gc[8];
    #pragma unroll
    for (int p = 0; p < 8; p++)
        gc[p] = exp2f(-lg * (float)(p * 8 + (lane & 3) * 2));

    float oacc[8][4];
    #pragma unroll
    for (int p = 0; p < 8; p++)
        #pragma unroll
        for (int r = 0; r < 4; r++) oacc[p][r] = 0.f;

    const uint32_t arow = (uint32_t)(w * 16 + l7 + 8 * ((lane >> 3) & 1));
    const uint32_t akb  = (lane >> 4) & 1;
    const uint32_t brow = (uint32_t)(l7 + 8 * ((lane >> 4) & 1));
    const uint32_t bkb  = (lane >> 3) & 1;
    const uint32_t vrow = (uint32_t)(l7 + 8 * ((lane >> 3) & 1));
    const uint32_t vnb  = (lane >> 4) & 1;

    for (int kt = 0; kt < nkt; kt++) {
        cp_wait<2>();
        __syncthreads();

        const uint32_t stg = sb + OFF_ST + (kt & 3) * STG_SZ;
        const uint32_t sK = stg, sV = stg + 8192;

        float sacc[8][4];
        #pragma unroll
        for (int p = 0; p < 8; p++)
            #pragma unroll
            for (int r = 0; r < 4; r++) sacc[p][r] = 0.f;

        #pragma unroll
        for (int ks = 0; ks < 4; ks++) {
            uint32_t qa = sb + OFF_QF + arow * 128 + (((2*ks + akb) ^ (arow & 7)) << 4);
            uint32_t ah[4];
            LDSM4(ah, qa);
            #pragma unroll
            for (int g = 0; g < 4; g++) {
                uint32_t br = g * 16 + brow;
                uint32_t ba = sK + br * 128 + (((2*ks + bkb) ^ (br & 7)) << 4);
                uint32_t bh[4];
                LDSM4(bh, ba);
                mma_f16(sacc[2*g],   ah, bh[0], bh[1]);
                mma_f16(sacc[2*g+1], ah, bh[2], bh[3]);
            }
        }

        const int   dbase = qt * QT_ - kt * KT_;
        const float f     = exp2f(lg * (float)dbase);
        const float fr0   = f * grow0;
        const float fr1   = f * grow1;
        const bool  edge  = (dbase < KT_);
        uint32_t SA[4][4];
        #pragma unroll
        for (int p = 0; p < 8; p++) {
            const float c0 = gc[p], c1 = gc[p] * ginv;
            float v00 = sacc[p][0] * fr0 * c0;
            float v01 = sacc[p][1] * fr0 * c1;
            float v10 = sacc[p][2] * fr1 * c0;
            float v11 = sacc[p][3] * fr1 * c1;
            if (edge) {
                const int tl0 = p * 8 + (lane & 3) * 2;
                const int d00 = dbase + rl0 - tl0;
                if (d00 < 0)     v00 = 0.f;
                if (d00 - 1 < 0) v01 = 0.f;
                if (d00 + 8 < 0) v10 = 0.f;
                if (d00 + 7 < 0) v11 = 0.f;
            }
            const int j = p >> 1, o = (p & 1) * 2;
            SA[j][o]     = packh2(v00, v01);
            SA[j][o + 1] = packh2(v10, v11);
        }

        #pragma unroll
        for (int j = 0; j < 4; j++) {
            uint32_t vr = j * 16 + vrow;
            #pragma unroll
            for (int g = 0; g < 4; g++) {
                uint32_t va = sV + vr * 128 + (((2*g + vnb) ^ (vr & 7)) << 4);
                uint32_t bv[4];
                LDSM4T(bv, va);
                mma_f16(oacc[2*g],   SA[j], bv[0], bv[1]);
                mma_f16(oacc[2*g+1], SA[j], bv[2], bv[3]);
            }
        }

        if (kt + 3 < nkt)
            attn_issue_kv(sb, (kt + 3) & 3, kt + 3,
                          g_kf + koff, g_vf + koff, tid);
        CP_COMMIT();
    }

    // ---- epilogue: y = O * silu(g) -> fp16 hi/lo for the out-projection
    const size_t row0 = (size_t)(b * S_ + qt * QT_ + rl0);
    #pragma unroll
    for (int p = 0; p < 8; p++) {
        const int col = h * DH_ + p * 8 + (lane & 3) * 2;
        #pragma unroll
        for (int half = 0; half < 2; half++) {
            const size_t idx2 = (row0 + half * 8) * D_ + col;
            float2 gv = *(const float2*)(g_g + idx2);
            float s0 = gv.x / (1.f + expf(-gv.x));
            float s1 = gv.y / (1.f + expf(-gv.y));
            float y0 = oacc[p][half*2 + 0] * s0;
            float y1 = oacc[p][half*2 + 1] * s1;
            uint32_t lo;
            uint32_t hi = packh2_hilo(y0, y1, lo);
            *(uint32_t*)&g_aoh[idx2] = hi;
            *(uint32_t*)&g_aol[idx2] = lo;
        }
    }
}

// ============================================================================
extern "C" void kernel_launch(void* const* d_in, const int* in_sizes, int n_in,
                              void* d_out, int out_size)
{
    const float* x  = (const float*)d_in[0];
    const float* wq = (const float*)d_in[1];
    const float* wk = (const float*)d_in[2];
    const float* wv = (const float*)d_in[3];
    const float* wg = (const float*)d_in[4];
    const float* wo = (const float*)d_in[5];
    float* out = (float*)d_out;

    cudaFuncSetAttribute(gemm_qkvg_f16,
                         cudaFuncAttributeMaxDynamicSharedMemorySize, GEMM_SMEM);
    cudaFuncSetAttribute(gemm_out_f16,
                         cudaFuncAttributeMaxDynamicSharedMemorySize, GEMM_SMEM);
    cudaFuncSetAttribute(attn_kernel,
                         cudaFuncAttributeMaxDynamicSharedMemorySize, ATTN_SMEM);

    split_kernel<<<dim3(M_*D_/4/256, 6), 256>>>(x, wq, wk, wv, wg, wo);

    gemm_qkvg_f16<<<dim3(D_/128, M_/128, 4), 256, GEMM_SMEM>>>();

    int nrope = M_ * H_ * 32;
    rope_kernel<<<(nrope + 255) / 256, 256>>>();

    attn_kernel<<<(S_/QT_) * H_ * B_, 256, ATTN_SMEM>>>();

    gemm_out_f16<<<dim3(D_/128, M_/128), 256, GEMM_SMEM>>>(out);
}

// round 14
// speedup vs baseline: 2.6302x; 1.0005x over previous
#include <cuda_runtime.h>
#include <cuda_fp16.h>
#include <stdint.h>
#include <math.h>

#define B_  2
#define S_  2048
#define D_  1024
#define H_  16
#define DH_ 64
#define M_  (B_*S_)   /* 4096 */

// ---- scratch (static device allocations; no cudaMalloc allowed) ----
__device__ __align__(16) float g_g [M_*D_];

// fp16 attention operands (q/k written by GEMM, rotated in place by rope)
__device__ __align__(16) __half g_qf[M_*D_], g_kf[M_*D_], g_vf[M_*D_];

// fp16 hi/lo split operands for the GEMMs (A side split, B side hi only)
__device__ __align__(16) __half g_xh [M_*D_], g_xl [M_*D_];
__device__ __align__(16) __half g_aoh[M_*D_], g_aol[M_*D_];
__device__ __align__(16) __half g_wqh[D_*D_];
__device__ __align__(16) __half g_wkh[D_*D_];
__device__ __align__(16) __half g_wvh[D_*D_];
__device__ __align__(16) __half g_wgh[D_*D_];
__device__ __align__(16) __half g_woh[D_*D_];

// ============================================================================
// PTX helpers
// ============================================================================
__device__ __forceinline__ uint32_t smem_u32(const void* p)
{
    uint32_t a;
    asm("{ .reg .u64 t; cvta.to.shared.u64 t, %1; cvt.u32.u64 %0, t; }"
        : "=r"(a) : "l"(p));
    return a;
}

__device__ __forceinline__ void cp16(uint32_t s, const void* g)
{
    asm volatile("cp.async.cg.shared.global [%0], [%1], 16;" :: "r"(s), "l"(g));
}
#define CP_COMMIT() asm volatile("cp.async.commit_group;" ::: "memory")
template<int N> __device__ __forceinline__ void cp_wait()
{
    asm volatile("cp.async.wait_group %0;" :: "n"(N) : "memory");
}

#define LDSM4(r, addr) \
    asm volatile("ldmatrix.sync.aligned.m8n8.x4.shared.b16 {%0,%1,%2,%3}, [%4];" \
        : "=r"((r)[0]), "=r"((r)[1]), "=r"((r)[2]), "=r"((r)[3]) : "r"(addr))

#define LDSM4T(r, addr) \
    asm volatile("ldmatrix.sync.aligned.m8n8.x4.trans.shared.b16 {%0,%1,%2,%3}, [%4];" \
        : "=r"((r)[0]), "=r"((r)[1]), "=r"((r)[2]), "=r"((r)[3]) : "r"(addr))

__device__ __forceinline__ void mma_f16(float c[4], const uint32_t a[4],
                                        uint32_t b0, uint32_t b1)
{
    asm volatile(
        "mma.sync.aligned.m16n8k16.row.col.f32.f16.f16.f32 "
        "{%0,%1,%2,%3},{%4,%5,%6,%7},{%8,%9},{%0,%1,%2,%3};"
        : "+f"(c[0]), "+f"(c[1]), "+f"(c[2]), "+f"(c[3])
        : "r"(a[0]), "r"(a[1]), "r"(a[2]), "r"(a[3]), "r"(b0), "r"(b1));
}

__device__ __forceinline__ uint32_t packh2(float a, float b)
{
    __half2 h = __floats2half2_rn(a, b);
    return *(uint32_t*)&h;
}

__device__ __forceinline__ uint32_t packh2_hilo(float a, float b, uint32_t& lo)
{
    __half ha = __float2half_rn(a), hb = __float2half_rn(b);
    float ra = a - __half2float(ha);
    float rb = b - __half2float(hb);
    __half la = __float2half_rn(ra), lb = __float2half_rn(rb);
    lo = (uint32_t)__half_as_ushort(la) | ((uint32_t)__half_as_ushort(lb) << 16);
    return (uint32_t)__half_as_ushort(ha) | ((uint32_t)__half_as_ushort(hb) << 16);
}

__device__ __forceinline__ uint32_t hf_split_hi(float a, float& rem)
{
    __half h = __float2half_rn(a);
    rem = a - __half2float(h);
    return (uint32_t)__half_as_ushort(h);
}

// ============================================================================
// fp16 hi/lo split kernel: x -> hi+lo, weights -> hi only
// ============================================================================
__global__ void split_kernel(const float* __restrict__ x,
                             const float* __restrict__ wq, const float* __restrict__ wk,
                             const float* __restrict__ wv, const float* __restrict__ wg,
                             const float* __restrict__ wo)
{
    const float* src;
    __half *dh, *dl;
    int n4;
    switch (blockIdx.y) {
        case 0: src = x;  dh = g_xh;  dl = g_xl;     n4 = M_*D_/4; break;
        case 1: src = wq; dh = g_wqh; dl = nullptr;  n4 = D_*D_/4; break;
        case 2: src = wk; dh = g_wkh; dl = nullptr;  n4 = D_*D_/4; break;
        case 3: src = wv; dh = g_wvh; dl = nullptr;  n4 = D_*D_/4; break;
        case 4: src = wg; dh = g_wgh; dl = nullptr;  n4 = D_*D_/4; break;
        default:src = wo; dh = g_woh; dl = nullptr;  n4 = D_*D_/4; break;
    }
    int i4 = blockIdx.x * blockDim.x + threadIdx.x;
    if (i4 >= n4) return;
    float4 v = ((const float4*)src)[i4];
    float r0, r1, r2, r3;
    uint32_t h0 = hf_split_hi(v.x, r0), h1 = hf_split_hi(v.y, r1);
    uint32_t h2 = hf_split_hi(v.z, r2), h3 = hf_split_hi(v.w, r3);
    ((uint2*)dh)[i4] = make_uint2(h0 | (h1 << 16), h2 | (h3 << 16));
    if (dl) {
        uint32_t l0 = packh2(r0, r1);
        uint32_t l1 = packh2(r2, r3);
        ((uint2*)dl)[i4] = make_uint2(l0, l1);
    }
}

// ============================================================================
// fp16 GEMM: C = A @ Bh^T, fp32 accumulate.
// SPLITA=1: A = Ah + Al (2-pass).  SPLITA=0: A = Ah (1-pass).
// OM=0: float C.  OM=1: fp16 C.
// BM=BN=128, BK=32, 256 threads, 4-stage cp.async.
// One barrier per iteration: the trailing sync is dead because issue(it+3)
// writes buffer (it-1)%4, whose readers all passed the top barrier of it.
// ============================================================================
#define BKH     32
#define NITG    (D_/BKH)
#define TILE_HB (128*BKH*2)           /* 8192 B */
#define GEMM_SMEM (4*3*TILE_HB)       /* 98304 B (max: SPLITA 4-stage) */

struct GemmSrcs { const __half *ah, *al, *bh; };

template<bool SPLITA>
__device__ __forceinline__ void issue_stage(uint32_t sb, int stage, int k0,
                                            const GemmSrcs& s, int tid)
{
    const int NT = SPLITA ? 3 : 2;
    const __half* srcs[3] = { s.ah, SPLITA ? s.al : s.bh, s.bh };
    const uint32_t stg = sb + stage * (NT * TILE_HB);
    #pragma unroll
    for (int m = 0; m < NT; m++) {
        const __half* src = srcs[m] + k0;
        const uint32_t tb = stg + m * TILE_HB;
        #pragma unroll
        for (int i = 0; i < 2; i++) {
            int j   = tid + i * 256;
            int row = j >> 2;
            int c   = j & 3;
            int csw = c ^ ((row >> 1) & 3);
            cp16(tb + row * 64 + csw * 16, src + (size_t)row * D_ + c * 8);
        }
    }
}

template<int OM, bool SPLITA>
__device__ __forceinline__ void gemm_f16_body(const GemmSrcs& s, float* C,
                                              __half* Cf)
{
    extern __shared__ char dsm[];
    const uint32_t sb = smem_u32(dsm);
    const int tid  = threadIdx.x;
    const int lane = tid & 31;
    const int w    = tid >> 5;
    const int wm   = (w >> 2) * 64;
    const int wn   = (w & 3) * 32;
    const int NT   = SPLITA ? 3 : 2;

    const int l7 = lane & 7;
    uint32_t aoff[4], asw[4], boff[2], bsw[2];
    const int akb = (lane >> 4) & 1;
    const int bkb = (lane >> 3) & 1;
    #pragma unroll
    for (int mf = 0; mf < 4; mf++) {
        int row = wm + mf * 16 + l7 + 8 * ((lane >> 3) & 1);
        aoff[mf] = row * 64;
        asw[mf]  = (row >> 1) & 3;
    }
    #pragma unroll
    for (int nfp = 0; nfp < 2; nfp++) {
        int row = wn + nfp * 16 + l7 + 8 * ((lane >> 4) & 1);
        boff[nfp] = row * 64;
        bsw[nfp]  = (row >> 1) & 3;
    }

    float acc[4][4][4];
    #pragma unroll
    for (int i = 0; i < 4; i++)
        #pragma unroll
        for (int j = 0; j < 4; j++)
            #pragma unroll
            for (int r = 0; r < 4; r++) acc[i][j][r] = 0.f;

    // prologue: stages 0..2 (3 committed groups)
    issue_stage<SPLITA>(sb, 0, 0, s, tid);       CP_COMMIT();
    issue_stage<SPLITA>(sb, 1, BKH, s, tid);     CP_COMMIT();
    issue_stage<SPLITA>(sb, 2, 2 * BKH, s, tid); CP_COMMIT();

    for (int it = 0; it < NITG; it++) {
        cp_wait<2>();
        __syncthreads();
        if (it + 3 < NITG)
            issue_stage<SPLITA>(sb, (it + 3) % 4, (it + 3) * BKH, s, tid);
        CP_COMMIT();   // one group per iteration (may be empty) keeps wait<2> exact

        const uint32_t stg = sb + (it % 4) * (NT * TILE_HB);
        const uint32_t sAh = stg;
        const uint32_t sAl = stg + TILE_HB;                 // valid iff SPLITA
        const uint32_t sBh = stg + (NT - 1) * TILE_HB;

        #pragma unroll
        for (int ks = 0; ks < 2; ks++) {
            uint32_t bh[2][4];
            #pragma unroll
            for (int nfp = 0; nfp < 2; nfp++) {
                uint32_t off = boff[nfp] + ((((uint32_t)(2*ks + bkb)) ^ bsw[nfp]) << 4);
                LDSM4(bh[nfp], sBh + off);
            }
            #pragma unroll
            for (int mf = 0; mf < 4; mf++) {
                uint32_t off = aoff[mf] + ((((uint32_t)(2*ks + akb)) ^ asw[mf]) << 4);
                uint32_t ah[4];
                LDSM4(ah, sAh + off);
                if (SPLITA) {
                    uint32_t al[4];
                    LDSM4(al, sAl + off);
                    #pragma unroll
                    for (int nf = 0; nf < 4; nf++) {
                        uint32_t b0 = bh[nf >> 1][(nf & 1)*2], b1 = bh[nf >> 1][(nf & 1)*2 + 1];
                        mma_f16(acc[mf][nf], ah, b0, b1);
                        mma_f16(acc[mf][nf], al, b0, b1);
                    }
                } else {
                    #pragma unroll
                    for (int nf = 0; nf < 4; nf++) {
                        uint32_t b0 = bh[nf >> 1][(nf & 1)*2], b1 = bh[nf >> 1][(nf & 1)*2 + 1];
                        mma_f16(acc[mf][nf], ah, b0, b1);
                    }
                }
            }
        }
        // no trailing __syncthreads: next iteration's top barrier provides
        // the reconvergence point; buffer-rotation distance 4 guarantees
        // write/read separation (see header comment).
    }

    const int rbase = blockIdx.y * 128 + wm + (lane >> 2);
    const int cbase = blockIdx.x * 128 + wn + ((lane & 3) << 1);
    #pragma unroll
    for (int mf = 0; mf < 4; mf++)
        #pragma unroll
        for (int nf = 0; nf < 4; nf++) {
            const size_t i0 = (size_t)(rbase + mf*16) * D_ + cbase + nf*8;
            const size_t i1 = i0 + (size_t)8 * D_;
            if (OM == 0) {
                *(float2*)(C + i0) = make_float2(acc[mf][nf][0], acc[mf][nf][1]);
                *(float2*)(C + i1) = make_float2(acc[mf][nf][2], acc[mf][nf][3]);
            } else {
                *(uint32_t*)&Cf[i0] = packh2(acc[mf][nf][0], acc[mf][nf][1]);
                *(uint32_t*)&Cf[i1] = packh2(acc[mf][nf][2], acc[mf][nf][3]);
            }
        }
}

__global__ __launch_bounds__(256, 2)
void gemm_qkvg_f16()
{
    GemmSrcs s;
    const size_t yoff = (size_t)blockIdx.y * 128 * D_;
    const size_t xoff = (size_t)blockIdx.x * 128 * D_;
    s.ah = g_xh + yoff; s.al = g_xl + yoff;
    switch (blockIdx.z) {
        // Q, K, V projections: 1-pass fp16 (A-lo dropped; error budgeted)
        case 0:  s.bh = g_wqh + xoff; gemm_f16_body<1, false>(s, nullptr, g_qf); break;
        case 1:  s.bh = g_wkh + xoff; gemm_f16_body<1, false>(s, nullptr, g_kf); break;
        case 2:  s.bh = g_wvh + xoff; gemm_f16_body<1, false>(s, nullptr, g_vf); break;
        // Gate: 2-pass (multiplies output directly)
        default: s.bh = g_wgh + xoff; gemm_f16_body<0, true>(s, g_g, nullptr);   break;
    }
}

__global__ __launch_bounds__(256, 2)
void gemm_out_f16(float* __restrict__ C)
{
    GemmSrcs s;
    const size_t yoff = (size_t)blockIdx.y * 128 * D_;
    const size_t xoff = (size_t)blockIdx.x * 128 * D_;
    s.ah = g_aoh + yoff; s.al = g_aol + yoff;
    s.bh = g_woh + xoff;
    gemm_f16_body<0, true>(s, C, nullptr);
}

// ============================================================================
// RoPE: rotate q/k fp16 in place
// ============================================================================
__global__ void rope_kernel()
{
    int i = blockIdx.x * blockDim.x + threadIdx.x;
    if (i >= M_ * H_ * 32) return;
    int j  = i & 31;
    int h  = (i >> 5) & (H_ - 1);
    int bs = i >> 9;
    int s  = bs & (S_ - 1);

    float inv = exp2f(-(float)j * 0.41524101186092029f);
    float ang = (float)s * inv;
    float sn, cs;
    sincosf(ang, &sn, &cs);

    int base = bs * D_ + h * DH_ + j;
    float q1 = __half2float(g_qf[base]), q2 = __half2float(g_qf[base + 32]);
    float k1 = __half2float(g_kf[base]), k2 = __half2float(g_kf[base + 32]);
    g_qf[base]      = __float2half_rn(q1 * cs - q2 * sn);
    g_qf[base + 32] = __float2half_rn(q2 * cs + q1 * sn);
    g_kf[base]      = __float2half_rn(k1 * cs - k2 * sn);
    g_kf[base + 32] = __float2half_rn(k2 * cs + k1 * sn);
}

// ============================================================================
// fp16 single-pass flash retention, 4-stage cp.async K/V pipeline.
// Prefetch for kt+3 hoisted before compute (buffer (kt-1)&3's readers all
// passed this iteration's top barrier). smem 80 KB, 2 CTAs/SM.
// ============================================================================
#define QT_ 128
#define KT_ 64
#define OFF_QF 0
#define OFF_ST 16384
#define STG_SZ 16384
#define ATTN_SMEM 81920

__device__ __forceinline__ void attn_issue_q(uint32_t sb, const __half* qf, int tid)
{
    #pragma unroll
    for (int i = 0; i < 4; i++) {
        int u   = tid + i * 256;
        int row = u >> 3;
        int c   = u & 7;
        int cs  = c ^ (row & 7);
        cp16(sb + OFF_QF + row * 128 + cs * 16, qf + (size_t)row * D_ + c * 8);
    }
}

__device__ __forceinline__ void attn_issue_kv(uint32_t sb, int stage, int kt,
                                              const __half* kf, const __half* vf,
                                              int tid)
{
    const __half* srcs[2] = { kf + (size_t)(kt * KT_) * D_,
                              vf + (size_t)(kt * KT_) * D_ };
    const uint32_t stg = sb + OFF_ST + stage * STG_SZ;
    #pragma unroll
    for (int m = 0; m < 2; m++) {
        const __half* src = srcs[m];
        const uint32_t tb = stg + m * 8192;
        #pragma unroll
        for (int i = 0; i < 2; i++) {
            int u   = tid + i * 256;
            int row = u >> 3;
            int c   = u & 7;
            int cs  = c ^ (row & 7);
            cp16(tb + row * 128 + cs * 16, src + (size_t)row * D_ + c * 8);
        }
    }
}

__global__ __launch_bounds__(256, 2)
void attn_kernel()
{
    extern __shared__ char dsm[];
    const uint32_t sb = smem_u32(dsm);

    // global heavy-first: all (h,b) of the heaviest qt launch first
    const int idx = blockIdx.x;
    const int qt  = (S_/QT_ - 1) - (idx >> 5);
    const int h   = idx & 15;
    const int b   = (idx >> 4) & 1;

    const int tid  = threadIdx.x;
    const int lane = tid & 31;
    const int w    = tid >> 5;
    const int l7   = lane & 7;

    const float gamma = 1.0f - exp2f(-5.0f - (float)h);
    const float lg    = log2f(gamma);

    const size_t qoff = (size_t)(b * S_ + qt * QT_) * D_ + h * DH_;
    const size_t koff = (size_t)(b * S_) * D_ + h * DH_;
    const int nkt = 2 * qt + 2;

    attn_issue_q(sb, g_qf + qoff, tid);
    attn_issue_kv(sb, 0, 0, g_kf + koff, g_vf + koff, tid);
    CP_COMMIT();
    if (1 < nkt) attn_issue_kv(sb, 1, 1, g_kf + koff, g_vf + koff, tid);
    CP_COMMIT();
    if (2 < nkt) attn_issue_kv(sb, 2, 2, g_kf + koff, g_vf + koff, tid);
    CP_COMMIT();

    const int rl0 = w * 16 + (lane >> 2);
    const float grow0 = 0.125f * exp2f(lg * (float)rl0);
    const float grow1 = 0.125f * exp2f(lg * (float)(rl0 + 8));
    const float ginv  = exp2f(-lg);
    float gc[8];
    #pragma unroll
    for (int p = 0; p < 8; p++)
        gc[p] = exp2f(-lg * (float)(p * 8 + (lane & 3) * 2));

    float oacc[8][4];
    #pragma unroll
    for (int p = 0; p < 8; p++)
        #pragma unroll
        for (int r = 0; r < 4; r++) oacc[p][r] = 0.f;

    const uint32_t arow = (uint32_t)(w * 16 + l7 + 8 * ((lane >> 3) & 1));
    const uint32_t akb  = (lane >> 4) & 1;
    const uint32_t brow = (uint32_t)(l7 + 8 * ((lane >> 4) & 1));
    const uint32_t bkb  = (lane >> 3) & 1;
    const uint32_t vrow = (uint32_t)(l7 + 8 * ((lane >> 3) & 1));
    const uint32_t vnb  = (lane >> 4) & 1;

    for (int kt = 0; kt < nkt; kt++) {
        cp_wait<2>();
        __syncthreads();

        // prefetch kt+3 early: its buffer (kt-1)&3 was fully consumed before
        // the barrier above. Exactly one commit per iteration keeps wait<2> exact.
        if (kt + 3 < nkt)
            attn_issue_kv(sb, (kt + 3) & 3, kt + 3,
                          g_kf + koff, g_vf + koff, tid);
        CP_COMMIT();

        const uint32_t stg = sb + OFF_ST + (kt & 3) * STG_SZ;
        const uint32_t sK = stg, sV = stg + 8192;

        float sacc[8][4];
        #pragma unroll
        for (int p = 0; p < 8; p++)
            #pragma unroll
            for (int r = 0; r < 4; r++) sacc[p][r] = 0.f;

        #pragma unroll
        for (int ks = 0; ks < 4; ks++) {
            uint32_t qa = sb + OFF_QF + arow * 128 + (((2*ks + akb) ^ (arow & 7)) << 4);
            uint32_t ah[4];
            LDSM4(ah, qa);
            #pragma unroll
            for (int g = 0; g < 4; g++) {
                uint32_t br = g * 16 + brow;
                uint32_t ba = sK + br * 128 + (((2*ks + bkb) ^ (br & 7)) << 4);
                uint32_t bh[4];
                LDSM4(bh, ba);
                mma_f16(sacc[2*g],   ah, bh[0], bh[1]);
                mma_f16(sacc[2*g+1], ah, bh[2], bh[3]);
            }
        }

        const int   dbase = qt * QT_ - kt * KT_;
        const float f     = exp2f(lg * (float)dbase);
        const float fr0   = f * grow0;
        const float fr1   = f * grow1;
        const bool  edge  = (dbase < KT_);
        uint32_t SA[4][4];
        #pragma unroll
        for (int p = 0; p < 8; p++) {
            const float c0 = gc[p], c1 = gc[p] * ginv;
            float v00 = sacc[p][0] * fr0 * c0;
            float v01 = sacc[p][1] * fr0 * c1;
            float v10 = sacc[p][2] * fr1 * c0;
            float v11 = sacc[p][3] * fr1 * c1;
            if (edge) {
                const int tl0 = p * 8 + (lane & 3) * 2;
                const int d00 = dbase + rl0 - tl0;
                if (d00 < 0)     v00 = 0.f;
                if (d00 - 1 < 0) v01 = 0.f;
                if (d00 + 8 < 0) v10 = 0.f;
                if (d00 + 7 < 0) v11 = 0.f;
            }
            const int j = p >> 1, o = (p & 1) * 2;
            SA[j][o]     = packh2(v00, v01);
            SA[j][o + 1] = packh2(v10, v11);
        }

        #pragma unroll
        for (int j = 0; j < 4; j++) {
            uint32_t vr = j * 16 + vrow;
            #pragma unroll
            for (int g = 0; g < 4; g++) {
                uint32_t va = sV + vr * 128 + (((2*g + vnb) ^ (vr & 7)) << 4);
                uint32_t bv[4];
                LDSM4T(bv, va);
                mma_f16(oacc[2*g],   SA[j], bv[0], bv[1]);
                mma_f16(oacc[2*g+1], SA[j], bv[2], bv[3]);
            }
        }
    }

    // ---- epilogue: y = O * silu(g) -> fp16 hi/lo for the out-projection
    const size_t row0 = (size_t)(b * S_ + qt * QT_ + rl0);
    #pragma unroll
    for (int p = 0; p < 8; p++) {
        const int col = h * DH_ + p * 8 + (lane & 3) * 2;
        #pragma unroll
        for (int half = 0; half < 2; half++) {
            const size_t idx2 = (row0 + half * 8) * D_ + col;
            float2 gv = *(const float2*)(g_g + idx2);
            float s0 = gv.x / (1.f + expf(-gv.x));
            float s1 = gv.y / (1.f + expf(-gv.y));
            float y0 = oacc[p][half*2 + 0] * s0;
            float y1 = oacc[p][half*2 + 1] * s1;
            uint32_t lo;
            uint32_t hi = packh2_hilo(y0, y1, lo);
            *(uint32_t*)&g_aoh[idx2] = hi;
            *(uint32_t*)&g_aol[idx2] = lo;
        }
    }
}

// ============================================================================
extern "C" void kernel_launch(void* const* d_in, const int* in_sizes, int n_in,
                              void* d_out, int out_size)
{
    const float* x  = (const float*)d_in[0];
    const float* wq = (const float*)d_in[1];
    const float* wk = (const float*)d_in[2];
    const float* wv = (const float*)d_in[3];
    const float* wg = (const float*)d_in[4];
    const float* wo = (const float*)d_in[5];
    float* out = (float*)d_out;

    cudaFuncSetAttribute(gemm_qkvg_f16,
                         cudaFuncAttributeMaxDynamicSharedMemorySize, GEMM_SMEM);
    cudaFuncSetAttribute(gemm_out_f16,
                         cudaFuncAttributeMaxDynamicSharedMemorySize, GEMM_SMEM);
    cudaFuncSetAttribute(attn_kernel,
                         cudaFuncAttributeMaxDynamicSharedMemorySize, ATTN_SMEM);

    split_kernel<<<dim3(M_*D_/4/256, 6), 256>>>(x, wq, wk, wv, wg, wo);

    gemm_qkvg_f16<<<dim3(D_/128, M_/128, 4), 256, GEMM_SMEM>>>();

    int nrope = M_ * H_ * 32;
    rope_kernel<<<(nrope + 255) / 256, 256>>>();

    attn_kernel<<<(S_/QT_) * H_ * B_, 256, ATTN_SMEM>>>();

    gemm_out_f16<<<dim3(D_/128, M_/128), 256, GEMM_SMEM>>>(out);
}

// round 15
// speedup vs baseline: 3.1701x; 1.2052x over previous
#include <cuda_runtime.h>
#include <cuda_fp16.h>
#include <stdint.h>
#include <math.h>

#define B_  2
#define S_  2048
#define D_  1024
#define H_  16
#define DH_ 64
#define M_  (B_*S_)   /* 4096 */

// ---- scratch (static device allocations; no cudaMalloc allowed) ----
__device__ __align__(16) float g_g [M_*D_];

// fp16 attention operands (q/k written by GEMM, rotated in place by rope)
__device__ __align__(16) __half g_qf[M_*D_], g_kf[M_*D_], g_vf[M_*D_];

// fp16 operands for the GEMMs (all single-pass: A-hi @ B-hi)
__device__ __align__(16) __half g_xh [M_*D_];
__device__ __align__(16) __half g_ao [M_*D_];
__device__ __align__(16) __half g_wqh[D_*D_];
__device__ __align__(16) __half g_wkh[D_*D_];
__device__ __align__(16) __half g_wvh[D_*D_];
__device__ __align__(16) __half g_wgh[D_*D_];
__device__ __align__(16) __half g_woh[D_*D_];

// ============================================================================
// PTX helpers
// ============================================================================
__device__ __forceinline__ uint32_t smem_u32(const void* p)
{
    uint32_t a;
    asm("{ .reg .u64 t; cvta.to.shared.u64 t, %1; cvt.u32.u64 %0, t; }"
        : "=r"(a) : "l"(p));
    return a;
}

__device__ __forceinline__ void cp16(uint32_t s, const void* g)
{
    asm volatile("cp.async.cg.shared.global [%0], [%1], 16;" :: "r"(s), "l"(g));
}
#define CP_COMMIT() asm volatile("cp.async.commit_group;" ::: "memory")
template<int N> __device__ __forceinline__ void cp_wait()
{
    asm volatile("cp.async.wait_group %0;" :: "n"(N) : "memory");
}

#define LDSM4(r, addr) \
    asm volatile("ldmatrix.sync.aligned.m8n8.x4.shared.b16 {%0,%1,%2,%3}, [%4];" \
        : "=r"((r)[0]), "=r"((r)[1]), "=r"((r)[2]), "=r"((r)[3]) : "r"(addr))

#define LDSM4T(r, addr) \
    asm volatile("ldmatrix.sync.aligned.m8n8.x4.trans.shared.b16 {%0,%1,%2,%3}, [%4];" \
        : "=r"((r)[0]), "=r"((r)[1]), "=r"((r)[2]), "=r"((r)[3]) : "r"(addr))

__device__ __forceinline__ void mma_f16(float c[4], const uint32_t a[4],
                                        uint32_t b0, uint32_t b1)
{
    asm volatile(
        "mma.sync.aligned.m16n8k16.row.col.f32.f16.f16.f32 "
        "{%0,%1,%2,%3},{%4,%5,%6,%7},{%8,%9},{%0,%1,%2,%3};"
        : "+f"(c[0]), "+f"(c[1]), "+f"(c[2]), "+f"(c[3])
        : "r"(a[0]), "r"(a[1]), "r"(a[2]), "r"(a[3]), "r"(b0), "r"(b1));
}

__device__ __forceinline__ uint32_t packh2(float a, float b)
{
    __half2 h = __floats2half2_rn(a, b);
    return *(uint32_t*)&h;
}

// ============================================================================
// fp16 convert kernel: x + weights -> fp16
// ============================================================================
__global__ void split_kernel(const float* __restrict__ x,
                             const float* __restrict__ wq, const float* __restrict__ wk,
                             const float* __restrict__ wv, const float* __restrict__ wg,
                             const float* __restrict__ wo)
{
    const float* src;
    __half* dh;
    int n4;
    switch (blockIdx.y) {
        case 0: src = x;  dh = g_xh;  n4 = M_*D_/4; break;
        case 1: src = wq; dh = g_wqh; n4 = D_*D_/4; break;
        case 2: src = wk; dh = g_wkh; n4 = D_*D_/4; break;
        case 3: src = wv; dh = g_wvh; n4 = D_*D_/4; break;
        case 4: src = wg; dh = g_wgh; n4 = D_*D_/4; break;
        default:src = wo; dh = g_woh; n4 = D_*D_/4; break;
    }
    int i4 = blockIdx.x * blockDim.x + threadIdx.x;
    if (i4 >= n4) return;
    float4 v = ((const float4*)src)[i4];
    ((uint2*)dh)[i4] = make_uint2(packh2(v.x, v.y), packh2(v.z, v.w));
}

// ============================================================================
// fp16 single-pass GEMM: C = Ah @ Bh^T, fp32 accumulate.
// OM=0: float C.  OM=1: fp16 C.
// BM=BN=128, BK=32, 256 threads, 4-stage cp.async; stage = Ah|Bh (16 KB).
// One barrier per iteration (rotation distance 4 covers write/read separation).
// ============================================================================
#define BKH     32
#define NITG    (D_/BKH)
#define TILE_HB (128*BKH*2)           /* 8192 B */
#define STAGE_B (2*TILE_HB)           /* 16384 B */
#define GEMM_SMEM (4*STAGE_B)         /* 65536 B */

struct GemmSrcs { const __half *ah, *bh; };

__device__ __forceinline__ void issue_stage(uint32_t sb, int stage, int k0,
                                            const GemmSrcs& s, int tid)
{
    const __half* srcs[2] = { s.ah, s.bh };
    const uint32_t stg = sb + stage * STAGE_B;
    #pragma unroll
    for (int m = 0; m < 2; m++) {
        const __half* src = srcs[m] + k0;
        const uint32_t tb = stg + m * TILE_HB;
        #pragma unroll
        for (int i = 0; i < 2; i++) {
            int j   = tid + i * 256;
            int row = j >> 2;
            int c   = j & 3;
            int csw = c ^ ((row >> 1) & 3);
            cp16(tb + row * 64 + csw * 16, src + (size_t)row * D_ + c * 8);
        }
    }
}

template<int OM>
__device__ __forceinline__ void gemm_f16_body(const GemmSrcs& s, float* C,
                                              __half* Cf)
{
    extern __shared__ char dsm[];
    const uint32_t sb = smem_u32(dsm);
    const int tid  = threadIdx.x;
    const int lane = tid & 31;
    const int w    = tid >> 5;
    const int wm   = (w >> 2) * 64;
    const int wn   = (w & 3) * 32;

    const int l7 = lane & 7;
    uint32_t aoff[4], asw[4], boff[2], bsw[2];
    const int akb = (lane >> 4) & 1;
    const int bkb = (lane >> 3) & 1;
    #pragma unroll
    for (int mf = 0; mf < 4; mf++) {
        int row = wm + mf * 16 + l7 + 8 * ((lane >> 3) & 1);
        aoff[mf] = row * 64;
        asw[mf]  = (row >> 1) & 3;
    }
    #pragma unroll
    for (int nfp = 0; nfp < 2; nfp++) {
        int row = wn + nfp * 16 + l7 + 8 * ((lane >> 4) & 1);
        boff[nfp] = row * 64;
        bsw[nfp]  = (row >> 1) & 3;
    }

    float acc[4][4][4];
    #pragma unroll
    for (int i = 0; i < 4; i++)
        #pragma unroll
        for (int j = 0; j < 4; j++)
            #pragma unroll
            for (int r = 0; r < 4; r++) acc[i][j][r] = 0.f;

    // prologue: stages 0..2 (3 committed groups)
    issue_stage(sb, 0, 0, s, tid);       CP_COMMIT();
    issue_stage(sb, 1, BKH, s, tid);     CP_COMMIT();
    issue_stage(sb, 2, 2 * BKH, s, tid); CP_COMMIT();

    for (int it = 0; it < NITG; it++) {
        cp_wait<2>();
        __syncthreads();
        if (it + 3 < NITG)
            issue_stage(sb, (it + 3) % 4, (it + 3) * BKH, s, tid);
        CP_COMMIT();   // one group per iteration (may be empty) keeps wait<2> exact

        const uint32_t stg = sb + (it % 4) * STAGE_B;
        const uint32_t sAh = stg;
        const uint32_t sBh = stg + TILE_HB;

        #pragma unroll
        for (int ks = 0; ks < 2; ks++) {
            uint32_t bh[2][4];
            #pragma unroll
            for (int nfp = 0; nfp < 2; nfp++) {
                uint32_t off = boff[nfp] + ((((uint32_t)(2*ks + bkb)) ^ bsw[nfp]) << 4);
                LDSM4(bh[nfp], sBh + off);
            }
            #pragma unroll
            for (int mf = 0; mf < 4; mf++) {
                uint32_t off = aoff[mf] + ((((uint32_t)(2*ks + akb)) ^ asw[mf]) << 4);
                uint32_t ah[4];
                LDSM4(ah, sAh + off);
                #pragma unroll
                for (int nf = 0; nf < 4; nf++) {
                    uint32_t b0 = bh[nf >> 1][(nf & 1)*2], b1 = bh[nf >> 1][(nf & 1)*2 + 1];
                    mma_f16(acc[mf][nf], ah, b0, b1);
                }
            }
        }
        // no trailing barrier: rotation distance 4 + next top barrier suffice
    }

    const int rbase = blockIdx.y * 128 + wm + (lane >> 2);
    const int cbase = blockIdx.x * 128 + wn + ((lane & 3) << 1);
    #pragma unroll
    for (int mf = 0; mf < 4; mf++)
        #pragma unroll
        for (int nf = 0; nf < 4; nf++) {
            const size_t i0 = (size_t)(rbase + mf*16) * D_ + cbase + nf*8;
            const size_t i1 = i0 + (size_t)8 * D_;
            if (OM == 0) {
                *(float2*)(C + i0) = make_float2(acc[mf][nf][0], acc[mf][nf][1]);
                *(float2*)(C + i1) = make_float2(acc[mf][nf][2], acc[mf][nf][3]);
            } else {
                *(uint32_t*)&Cf[i0] = packh2(acc[mf][nf][0], acc[mf][nf][1]);
                *(uint32_t*)&Cf[i1] = packh2(acc[mf][nf][2], acc[mf][nf][3]);
            }
        }
}

__global__ __launch_bounds__(256, 2)
void gemm_qkvg_f16()
{
    GemmSrcs s;
    const size_t yoff = (size_t)blockIdx.y * 128 * D_;
    const size_t xoff = (size_t)blockIdx.x * 128 * D_;
    s.ah = g_xh + yoff;
    switch (blockIdx.z) {
        case 0:  s.bh = g_wqh + xoff; gemm_f16_body<1>(s, nullptr, g_qf); break;
        case 1:  s.bh = g_wkh + xoff; gemm_f16_body<1>(s, nullptr, g_kf); break;
        case 2:  s.bh = g_wvh + xoff; gemm_f16_body<1>(s, nullptr, g_vf); break;
        default: s.bh = g_wgh + xoff; gemm_f16_body<0>(s, g_g, nullptr);  break;
    }
}

__global__ __launch_bounds__(256, 2)
void gemm_out_f16(float* __restrict__ C)
{
    GemmSrcs s;
    const size_t yoff = (size_t)blockIdx.y * 128 * D_;
    const size_t xoff = (size_t)blockIdx.x * 128 * D_;
    s.ah = g_ao + yoff;
    s.bh = g_woh + xoff;
    gemm_f16_body<0>(s, C, nullptr);
}

// ============================================================================
// RoPE: rotate q/k fp16 in place
// ============================================================================
__global__ void rope_kernel()
{
    int i = blockIdx.x * blockDim.x + threadIdx.x;
    if (i >= M_ * H_ * 32) return;
    int j  = i & 31;
    int h  = (i >> 5) & (H_ - 1);
    int bs = i >> 9;
    int s  = bs & (S_ - 1);

    float inv = exp2f(-(float)j * 0.41524101186092029f);
    float ang = (float)s * inv;
    float sn, cs;
    sincosf(ang, &sn, &cs);

    int base = bs * D_ + h * DH_ + j;
    float q1 = __half2float(g_qf[base]), q2 = __half2float(g_qf[base + 32]);
    float k1 = __half2float(g_kf[base]), k2 = __half2float(g_kf[base + 32]);
    g_qf[base]      = __float2half_rn(q1 * cs - q2 * sn);
    g_qf[base + 32] = __float2half_rn(q2 * cs + q1 * sn);
    g_kf[base]      = __float2half_rn(k1 * cs - k2 * sn);
    g_kf[base + 32] = __float2half_rn(k2 * cs + k1 * sn);
}

// ============================================================================
// fp16 single-pass flash retention, 4-stage cp.async K/V pipeline.
// smem: Qf 16K | 4 stages x (K 8K | V 8K) = 80 KB. 2 CTAs/SM.
// ============================================================================
#define QT_ 128
#define KT_ 64
#define OFF_QF 0
#define OFF_ST 16384
#define STG_SZ 16384
#define ATTN_SMEM 81920

__device__ __forceinline__ void attn_issue_q(uint32_t sb, const __half* qf, int tid)
{
    #pragma unroll
    for (int i = 0; i < 4; i++) {
        int u   = tid + i * 256;
        int row = u >> 3;
        int c   = u & 7;
        int cs  = c ^ (row & 7);
        cp16(sb + OFF_QF + row * 128 + cs * 16, qf + (size_t)row * D_ + c * 8);
    }
}

__device__ __forceinline__ void attn_issue_kv(uint32_t sb, int stage, int kt,
                                              const __half* kf, const __half* vf,
                                              int tid)
{
    const __half* srcs[2] = { kf + (size_t)(kt * KT_) * D_,
                              vf + (size_t)(kt * KT_) * D_ };
    const uint32_t stg = sb + OFF_ST + stage * STG_SZ;
    #pragma unroll
    for (int m = 0; m < 2; m++) {
        const __half* src = srcs[m];
        const uint32_t tb = stg + m * 8192;
        #pragma unroll
        for (int i = 0; i < 2; i++) {
            int u   = tid + i * 256;
            int row = u >> 3;
            int c   = u & 7;
            int cs  = c ^ (row & 7);
            cp16(tb + row * 128 + cs * 16, src + (size_t)row * D_ + c * 8);
        }
    }
}

__global__ __launch_bounds__(256, 2)
void attn_kernel()
{
    extern __shared__ char dsm[];
    const uint32_t sb = smem_u32(dsm);

    // global heavy-first: all (h,b) of the heaviest qt launch first
    const int idx = blockIdx.x;
    const int qt  = (S_/QT_ - 1) - (idx >> 5);
    const int h   = idx & 15;
    const int b   = (idx >> 4) & 1;

    const int tid  = threadIdx.x;
    const int lane = tid & 31;
    const int w    = tid >> 5;
    const int l7   = lane & 7;

    const float gamma = 1.0f - exp2f(-5.0f - (float)h);
    const float lg    = log2f(gamma);

    const size_t qoff = (size_t)(b * S_ + qt * QT_) * D_ + h * DH_;
    const size_t koff = (size_t)(b * S_) * D_ + h * DH_;
    const int nkt = 2 * qt + 2;

    attn_issue_q(sb, g_qf + qoff, tid);
    attn_issue_kv(sb, 0, 0, g_kf + koff, g_vf + koff, tid);
    CP_COMMIT();
    if (1 < nkt) attn_issue_kv(sb, 1, 1, g_kf + koff, g_vf + koff, tid);
    CP_COMMIT();
    if (2 < nkt) attn_issue_kv(sb, 2, 2, g_kf + koff, g_vf + koff, tid);
    CP_COMMIT();

    const int rl0 = w * 16 + (lane >> 2);
    const float grow0 = 0.125f * exp2f(lg * (float)rl0);
    const float grow1 = 0.125f * exp2f(lg * (float)(rl0 + 8));
    const float ginv  = exp2f(-lg);
    float gc[8];
    #pragma unroll
    for (int p = 0; p < 8; p++)
        gc[p] = exp2f(-lg * (float)(p * 8 + (lane & 3) * 2));

    float oacc[8][4];
    #pragma unroll
    for (int p = 0; p < 8; p++)
        #pragma unroll
        for (int r = 0; r < 4; r++) oacc[p][r] = 0.f;

    const uint32_t arow = (uint32_t)(w * 16 + l7 + 8 * ((lane >> 3) & 1));
    const uint32_t akb  = (lane >> 4) & 1;
    const uint32_t brow = (uint32_t)(l7 + 8 * ((lane >> 4) & 1));
    const uint32_t bkb  = (lane >> 3) & 1;
    const uint32_t vrow = (uint32_t)(l7 + 8 * ((lane >> 3) & 1));
    const uint32_t vnb  = (lane >> 4) & 1;

    for (int kt = 0; kt < nkt; kt++) {
        cp_wait<2>();
        __syncthreads();

        // prefetch kt+3 early: buffer (kt-1)&3 fully consumed before the barrier
        if (kt + 3 < nkt)
            attn_issue_kv(sb, (kt + 3) & 3, kt + 3,
                          g_kf + koff, g_vf + koff, tid);
        CP_COMMIT();

        const uint32_t stg = sb + OFF_ST + (kt & 3) * STG_SZ;
        const uint32_t sK = stg, sV = stg + 8192;

        float sacc[8][4];
        #pragma unroll
        for (int p = 0; p < 8; p++)
            #pragma unroll
            for (int r = 0; r < 4; r++) sacc[p][r] = 0.f;

        #pragma unroll
        for (int ks = 0; ks < 4; ks++) {
            uint32_t qa = sb + OFF_QF + arow * 128 + (((2*ks + akb) ^ (arow & 7)) << 4);
            uint32_t ah[4];
            LDSM4(ah, qa);
            #pragma unroll
            for (int g = 0; g < 4; g++) {
                uint32_t br = g * 16 + brow;
                uint32_t ba = sK + br * 128 + (((2*ks + bkb) ^ (br & 7)) << 4);
                uint32_t bh[4];
                LDSM4(bh, ba);
                mma_f16(sacc[2*g],   ah, bh[0], bh[1]);
                mma_f16(sacc[2*g+1], ah, bh[2], bh[3]);
            }
        }

        const int   dbase = qt * QT_ - kt * KT_;
        const float f     = exp2f(lg * (float)dbase);
        const float fr0   = f * grow0;
        const float fr1   = f * grow1;
        const bool  edge  = (dbase < KT_);
        uint32_t SA[4][4];
        #pragma unroll
        for (int p = 0; p < 8; p++) {
            const float c0 = gc[p], c1 = gc[p] * ginv;
            float v00 = sacc[p][0] * fr0 * c0;
            float v01 = sacc[p][1] * fr0 * c1;
            float v10 = sacc[p][2] * fr1 * c0;
            float v11 = sacc[p][3] * fr1 * c1;
            if (edge) {
                const int tl0 = p * 8 + (lane & 3) * 2;
                const int d00 = dbase + rl0 - tl0;
                if (d00 < 0)     v00 = 0.f;
                if (d00 - 1 < 0) v01 = 0.f;
                if (d00 + 8 < 0) v10 = 0.f;
                if (d00 + 7 < 0) v11 = 0.f;
            }
            const int j = p >> 1, o = (p & 1) * 2;
            SA[j][o]     = packh2(v00, v01);
            SA[j][o + 1] = packh2(v10, v11);
        }

        #pragma unroll
        for (int j = 0; j < 4; j++) {
            uint32_t vr = j * 16 + vrow;
            #pragma unroll
            for (int g = 0; g < 4; g++) {
                uint32_t va = sV + vr * 128 + (((2*g + vnb) ^ (vr & 7)) << 4);
                uint32_t bv[4];
                LDSM4T(bv, va);
                mma_f16(oacc[2*g],   SA[j], bv[0], bv[1]);
                mma_f16(oacc[2*g+1], SA[j], bv[2], bv[3]);
            }
        }
    }

    // ---- epilogue: y = O * silu(g) -> single fp16 for the out-projection
    const size_t row0 = (size_t)(b * S_ + qt * QT_ + rl0);
    #pragma unroll
    for (int p = 0; p < 8; p++) {
        const int col = h * DH_ + p * 8 + (lane & 3) * 2;
        #pragma unroll
        for (int half = 0; half < 2; half++) {
            const size_t idx2 = (row0 + half * 8) * D_ + col;
            float2 gv = *(const float2*)(g_g + idx2);
            float s0 = gv.x / (1.f + expf(-gv.x));
            float s1 = gv.y / (1.f + expf(-gv.y));
            float y0 = oacc[p][half*2 + 0] * s0;
            float y1 = oacc[p][half*2 + 1] * s1;
            *(uint32_t*)&g_ao[idx2] = packh2(y0, y1);
        }
    }
}

// ============================================================================
extern "C" void kernel_launch(void* const* d_in, const int* in_sizes, int n_in,
                              void* d_out, int out_size)
{
    const float* x  = (const float*)d_in[0];
    const float* wq = (const float*)d_in[1];
    const float* wk = (const float*)d_in[2];
    const float* wv = (const float*)d_in[3];
    const float* wg = (const float*)d_in[4];
    const float* wo = (const float*)d_in[5];
    float* out = (float*)d_out;

    cudaFuncSetAttribute(gemm_qkvg_f16,
                         cudaFuncAttributeMaxDynamicSharedMemorySize, GEMM_SMEM);
    cudaFuncSetAttribute(gemm_out_f16,
                         cudaFuncAttributeMaxDynamicSharedMemorySize, GEMM_SMEM);
    cudaFuncSetAttribute(attn_kernel,
                         cudaFuncAttributeMaxDynamicSharedMemorySize, ATTN_SMEM);

    split_kernel<<<dim3(M_*D_/4/256, 6), 256>>>(x, wq, wk, wv, wg, wo);

    gemm_qkvg_f16<<<dim3(D_/128, M_/128, 4), 256, GEMM_SMEM>>>();

    int nrope = M_ * H_ * 32;
    rope_kernel<<<(nrope + 255) / 256, 256>>>();

    attn_kernel<<<(S_/QT_) * H_ * B_, 256, ATTN_SMEM>>>();

    gemm_out_f16<<<dim3(D_/128, M_/128), 256, GEMM_SMEM>>>(out);
}

// round 16
// speedup vs baseline: 3.2894x; 1.0376x over previous
#include <cuda_runtime.h>
#include <cuda_fp16.h>
#include <stdint.h>
#include <math.h>

#define B_  2
#define S_  2048
#define D_  1024
#define H_  16
#define DH_ 64
#define M_  (B_*S_)   /* 4096 */

// ---- scratch (static device allocations; no cudaMalloc allowed) ----
__device__ __align__(16) float g_g [M_*D_];

// fp16 attention operands (q/k written by GEMM, rotated in place by rope)
__device__ __align__(16) __half g_qf[M_*D_], g_kf[M_*D_], g_vf[M_*D_];

// fp16 operands for the GEMMs (all single-pass: A-hi @ B-hi)
__device__ __align__(16) __half g_xh [M_*D_];
__device__ __align__(16) __half g_ao [M_*D_];
__device__ __align__(16) __half g_wqh[D_*D_];
__device__ __align__(16) __half g_wkh[D_*D_];
__device__ __align__(16) __half g_wvh[D_*D_];
__device__ __align__(16) __half g_wgh[D_*D_];
__device__ __align__(16) __half g_woh[D_*D_];

// ============================================================================
// PTX helpers
// ============================================================================
__device__ __forceinline__ uint32_t smem_u32(const void* p)
{
    uint32_t a;
    asm("{ .reg .u64 t; cvta.to.shared.u64 t, %1; cvt.u32.u64 %0, t; }"
        : "=r"(a) : "l"(p));
    return a;
}

__device__ __forceinline__ void cp16(uint32_t s, const void* g)
{
    asm volatile("cp.async.cg.shared.global [%0], [%1], 16;" :: "r"(s), "l"(g));
}
#define CP_COMMIT() asm volatile("cp.async.commit_group;" ::: "memory")
template<int N> __device__ __forceinline__ void cp_wait()
{
    asm volatile("cp.async.wait_group %0;" :: "n"(N) : "memory");
}

#define LDSM4(r, addr) \
    asm volatile("ldmatrix.sync.aligned.m8n8.x4.shared.b16 {%0,%1,%2,%3}, [%4];" \
        : "=r"((r)[0]), "=r"((r)[1]), "=r"((r)[2]), "=r"((r)[3]) : "r"(addr))

#define LDSM4T(r, addr) \
    asm volatile("ldmatrix.sync.aligned.m8n8.x4.trans.shared.b16 {%0,%1,%2,%3}, [%4];" \
        : "=r"((r)[0]), "=r"((r)[1]), "=r"((r)[2]), "=r"((r)[3]) : "r"(addr))

__device__ __forceinline__ void mma_f16(float c[4], const uint32_t a[4],
                                        uint32_t b0, uint32_t b1)
{
    asm volatile(
        "mma.sync.aligned.m16n8k16.row.col.f32.f16.f16.f32 "
        "{%0,%1,%2,%3},{%4,%5,%6,%7},{%8,%9},{%0,%1,%2,%3};"
        : "+f"(c[0]), "+f"(c[1]), "+f"(c[2]), "+f"(c[3])
        : "r"(a[0]), "r"(a[1]), "r"(a[2]), "r"(a[3]), "r"(b0), "r"(b1));
}

__device__ __forceinline__ uint32_t packh2(float a, float b)
{
    __half2 h = __floats2half2_rn(a, b);
    return *(uint32_t*)&h;
}

// ============================================================================
// fp16 convert kernel: x + weights -> fp16, exact flattened grid
// chunks: x = M*D/4, each weight = D*D/4
// ============================================================================
#define XCH   (M_*D_/4)          /* 1048576 */
#define WCH   (D_*D_/4)          /* 262144  */
#define SPLIT_BLOCKS ((XCH + 5*WCH) / 256)   /* 9216 */

__global__ void split_kernel(const float* __restrict__ x,
                             const float* __restrict__ wq, const float* __restrict__ wk,
                             const float* __restrict__ wv, const float* __restrict__ wg,
                             const float* __restrict__ wo)
{
    int gi = blockIdx.x * 256 + threadIdx.x;
    const float* src;
    __half* dh;
    int off;
    if (gi < XCH) {
        src = x; dh = g_xh; off = gi;
    } else {
        int r = gi - XCH;
        int wsel = r >> 18;          // / WCH
        off = r & (WCH - 1);
        switch (wsel) {
            case 0:  src = wq; dh = g_wqh; break;
            case 1:  src = wk; dh = g_wkh; break;
            case 2:  src = wv; dh = g_wvh; break;
            case 3:  src = wg; dh = g_wgh; break;
            default: src = wo; dh = g_woh; break;
        }
    }
    float4 v = ((const float4*)src)[off];
    ((uint2*)dh)[off] = make_uint2(packh2(v.x, v.y), packh2(v.z, v.w));
}

// ============================================================================
// fp16 single-pass GEMM: C = Ah @ Bh^T, fp32 accumulate.
// OM=0: float C.  OM=1: fp16 C.
// BM=BN=128, BK=32, 256 threads, 4-stage cp.async; stage = Ah|Bh (16 KB).
// ============================================================================
#define BKH     32
#define NITG    (D_/BKH)
#define TILE_HB (128*BKH*2)           /* 8192 B */
#define STAGE_B (2*TILE_HB)           /* 16384 B */
#define GEMM_SMEM (4*STAGE_B)         /* 65536 B */

struct GemmSrcs { const __half *ah, *bh; };

__device__ __forceinline__ void issue_stage(uint32_t sb, int stage, int k0,
                                            const GemmSrcs& s, int tid)
{
    const __half* srcs[2] = { s.ah, s.bh };
    const uint32_t stg = sb + stage * STAGE_B;
    #pragma unroll
    for (int m = 0; m < 2; m++) {
        const __half* src = srcs[m] + k0;
        const uint32_t tb = stg + m * TILE_HB;
        #pragma unroll
        for (int i = 0; i < 2; i++) {
            int j   = tid + i * 256;
            int row = j >> 2;
            int c   = j & 3;
            int csw = c ^ ((row >> 1) & 3);
            cp16(tb + row * 64 + csw * 16, src + (size_t)row * D_ + c * 8);
        }
    }
}

template<int OM>
__device__ __forceinline__ void gemm_f16_body(const GemmSrcs& s, float* C,
                                              __half* Cf)
{
    extern __shared__ char dsm[];
    const uint32_t sb = smem_u32(dsm);
    const int tid  = threadIdx.x;
    const int lane = tid & 31;
    const int w    = tid >> 5;
    const int wm   = (w >> 2) * 64;
    const int wn   = (w & 3) * 32;

    const int l7 = lane & 7;
    uint32_t aoff[4], asw[4], boff[2], bsw[2];
    const int akb = (lane >> 4) & 1;
    const int bkb = (lane >> 3) & 1;
    #pragma unroll
    for (int mf = 0; mf < 4; mf++) {
        int row = wm + mf * 16 + l7 + 8 * ((lane >> 3) & 1);
        aoff[mf] = row * 64;
        asw[mf]  = (row >> 1) & 3;
    }
    #pragma unroll
    for (int nfp = 0; nfp < 2; nfp++) {
        int row = wn + nfp * 16 + l7 + 8 * ((lane >> 4) & 1);
        boff[nfp] = row * 64;
        bsw[nfp]  = (row >> 1) & 3;
    }

    float acc[4][4][4];
    #pragma unroll
    for (int i = 0; i < 4; i++)
        #pragma unroll
        for (int j = 0; j < 4; j++)
            #pragma unroll
            for (int r = 0; r < 4; r++) acc[i][j][r] = 0.f;

    // prologue: stages 0..2 (3 committed groups)
    issue_stage(sb, 0, 0, s, tid);       CP_COMMIT();
    issue_stage(sb, 1, BKH, s, tid);     CP_COMMIT();
    issue_stage(sb, 2, 2 * BKH, s, tid); CP_COMMIT();

    for (int it = 0; it < NITG; it++) {
        cp_wait<2>();
        __syncthreads();
        if (it + 3 < NITG)
            issue_stage(sb, (it + 3) % 4, (it + 3) * BKH, s, tid);
        CP_COMMIT();   // one group per iteration (may be empty) keeps wait<2> exact

        const uint32_t stg = sb + (it % 4) * STAGE_B;
        const uint32_t sAh = stg;
        const uint32_t sBh = stg + TILE_HB;

        #pragma unroll
        for (int ks = 0; ks < 2; ks++) {
            uint32_t bh[2][4];
            #pragma unroll
            for (int nfp = 0; nfp < 2; nfp++) {
                uint32_t off = boff[nfp] + ((((uint32_t)(2*ks + bkb)) ^ bsw[nfp]) << 4);
                LDSM4(bh[nfp], sBh + off);
            }
            #pragma unroll
            for (int mf = 0; mf < 4; mf++) {
                uint32_t off = aoff[mf] + ((((uint32_t)(2*ks + akb)) ^ asw[mf]) << 4);
                uint32_t ah[4];
                LDSM4(ah, sAh + off);
                #pragma unroll
                for (int nf = 0; nf < 4; nf++) {
                    uint32_t b0 = bh[nf >> 1][(nf & 1)*2], b1 = bh[nf >> 1][(nf & 1)*2 + 1];
                    mma_f16(acc[mf][nf], ah, b0, b1);
                }
            }
        }
        // no trailing barrier: rotation distance 4 + next top barrier suffice
    }

    const int rbase = blockIdx.y * 128 + wm + (lane >> 2);
    const int cbase = blockIdx.x * 128 + wn + ((lane & 3) << 1);
    #pragma unroll
    for (int mf = 0; mf < 4; mf++)
        #pragma unroll
        for (int nf = 0; nf < 4; nf++) {
            const size_t i0 = (size_t)(rbase + mf*16) * D_ + cbase + nf*8;
            const size_t i1 = i0 + (size_t)8 * D_;
            if (OM == 0) {
                *(float2*)(C + i0) = make_float2(acc[mf][nf][0], acc[mf][nf][1]);
                *(float2*)(C + i1) = make_float2(acc[mf][nf][2], acc[mf][nf][3]);
            } else {
                *(uint32_t*)&Cf[i0] = packh2(acc[mf][nf][0], acc[mf][nf][1]);
                *(uint32_t*)&Cf[i1] = packh2(acc[mf][nf][2], acc[mf][nf][3]);
            }
        }
}

__global__ __launch_bounds__(256, 2)
void gemm_qkvg_f16()
{
    GemmSrcs s;
    const size_t yoff = (size_t)blockIdx.y * 128 * D_;
    const size_t xoff = (size_t)blockIdx.x * 128 * D_;
    s.ah = g_xh + yoff;
    switch (blockIdx.z) {
        case 0:  s.bh = g_wqh + xoff; gemm_f16_body<1>(s, nullptr, g_qf); break;
        case 1:  s.bh = g_wkh + xoff; gemm_f16_body<1>(s, nullptr, g_kf); break;
        case 2:  s.bh = g_wvh + xoff; gemm_f16_body<1>(s, nullptr, g_vf); break;
        default: s.bh = g_wgh + xoff; gemm_f16_body<0>(s, g_g, nullptr);  break;
    }
}

__global__ __launch_bounds__(256, 2)
void gemm_out_f16(float* __restrict__ C)
{
    GemmSrcs s;
    const size_t yoff = (size_t)blockIdx.y * 128 * D_;
    const size_t xoff = (size_t)blockIdx.x * 128 * D_;
    s.ah = g_ao + yoff;
    s.bh = g_woh + xoff;
    gemm_f16_body<0>(s, C, nullptr);
}

// ============================================================================
// RoPE: rotate q/k fp16 in place
// ============================================================================
__global__ void rope_kernel()
{
    int i = blockIdx.x * blockDim.x + threadIdx.x;
    if (i >= M_ * H_ * 32) return;
    int j  = i & 31;
    int h  = (i >> 5) & (H_ - 1);
    int bs = i >> 9;
    int s  = bs & (S_ - 1);

    float inv = exp2f(-(float)j * 0.41524101186092029f);
    float ang = (float)s * inv;
    float sn, cs;
    sincosf(ang, &sn, &cs);

    int base = bs * D_ + h * DH_ + j;
    float q1 = __half2float(g_qf[base]), q2 = __half2float(g_qf[base + 32]);
    float k1 = __half2float(g_kf[base]), k2 = __half2float(g_kf[base + 32]);
    g_qf[base]      = __float2half_rn(q1 * cs - q2 * sn);
    g_qf[base + 32] = __float2half_rn(q2 * cs + q1 * sn);
    g_kf[base]      = __float2half_rn(k1 * cs - k2 * sn);
    g_kf[base + 32] = __float2half_rn(k2 * cs + k1 * sn);
}

// ============================================================================
// fp16 single-pass flash retention; PAIRED tile loop (nkt always even).
// One wait + one barrier + one commit per PAIR of K-tiles.
// smem: Qf 16K | 4 stages x (K 8K | V 8K) = 80 KB. 2 CTAs/SM.
// Safety: pair p uses stages (2p)&3,(2p+1)&3; pair p+1 issued after the
// barrier targets stages of pair p-1, whose consumption the barrier covers.
// ============================================================================
#define QT_ 128
#define KT_ 64
#define OFF_QF 0
#define OFF_ST 16384
#define STG_SZ 16384
#define ATTN_SMEM 81920

__device__ __forceinline__ void attn_issue_q(uint32_t sb, const __half* qf, int tid)
{
    #pragma unroll
    for (int i = 0; i < 4; i++) {
        int u   = tid + i * 256;
        int row = u >> 3;
        int c   = u & 7;
        int cs  = c ^ (row & 7);
        cp16(sb + OFF_QF + row * 128 + cs * 16, qf + (size_t)row * D_ + c * 8);
    }
}

__device__ __forceinline__ void attn_issue_kv(uint32_t sb, int stage, int kt,
                                              const __half* kf, const __half* vf,
                                              int tid)
{
    const __half* srcs[2] = { kf + (size_t)(kt * KT_) * D_,
                              vf + (size_t)(kt * KT_) * D_ };
    const uint32_t stg = sb + OFF_ST + stage * STG_SZ;
    #pragma unroll
    for (int m = 0; m < 2; m++) {
        const __half* src = srcs[m];
        const uint32_t tb = stg + m * 8192;
        #pragma unroll
        for (int i = 0; i < 2; i++) {
            int u   = tid + i * 256;
            int row = u >> 3;
            int c   = u & 7;
            int cs  = c ^ (row & 7);
            cp16(tb + row * 128 + cs * 16, src + (size_t)row * D_ + c * 8);
        }
    }
}

__global__ __launch_bounds__(256, 2)
void attn_kernel()
{
    extern __shared__ char dsm[];
    const uint32_t sb = smem_u32(dsm);

    // global heavy-first: all (h,b) of the heaviest qt launch first
    const int idx = blockIdx.x;
    const int qt  = (S_/QT_ - 1) - (idx >> 5);
    const int h   = idx & 15;
    const int b   = (idx >> 4) & 1;

    const int tid  = threadIdx.x;
    const int lane = tid & 31;
    const int w    = tid >> 5;
    const int l7   = lane & 7;

    const float gamma = 1.0f - exp2f(-5.0f - (float)h);
    const float lg    = log2f(gamma);

    const size_t qoff = (size_t)(b * S_ + qt * QT_) * D_ + h * DH_;
    const size_t koff = (size_t)(b * S_) * D_ + h * DH_;
    const int npair = qt + 1;          // nkt = 2qt+2 tiles = qt+1 pairs

    // prologue: Q + pair 0 (tiles 0,1 -> stages 0,1) in one group
    attn_issue_q(sb, g_qf + qoff, tid);
    attn_issue_kv(sb, 0, 0, g_kf + koff, g_vf + koff, tid);
    attn_issue_kv(sb, 1, 1, g_kf + koff, g_vf + koff, tid);
    CP_COMMIT();

    const int rl0 = w * 16 + (lane >> 2);
    const float grow0 = 0.125f * exp2f(lg * (float)rl0);
    const float grow1 = 0.125f * exp2f(lg * (float)(rl0 + 8));
    const float ginv  = exp2f(-lg);
    float gc[8];
    #pragma unroll
    for (int p = 0; p < 8; p++)
        gc[p] = exp2f(-lg * (float)(p * 8 + (lane & 3) * 2));

    float oacc[8][4];
    #pragma unroll
    for (int p = 0; p < 8; p++)
        #pragma unroll
        for (int r = 0; r < 4; r++) oacc[p][r] = 0.f;

    const uint32_t arow = (uint32_t)(w * 16 + l7 + 8 * ((lane >> 3) & 1));
    const uint32_t akb  = (lane >> 4) & 1;
    const uint32_t brow = (uint32_t)(l7 + 8 * ((lane >> 4) & 1));
    const uint32_t bkb  = (lane >> 3) & 1;
    const uint32_t vrow = (uint32_t)(l7 + 8 * ((lane >> 3) & 1));
    const uint32_t vnb  = (lane >> 4) & 1;

    for (int p = 0; p < npair; p++) {
        cp_wait<0>();          // pair p (the only outstanding group) has landed
        __syncthreads();       // publish; also frees pair p-1's stages

        if (p + 1 < npair) {   // prefetch pair p+1 into pair p-1's stages
            attn_issue_kv(sb, (2*p + 2) & 3, 2*p + 2, g_kf + koff, g_vf + koff, tid);
            attn_issue_kv(sb, (2*p + 3) & 3, 2*p + 3, g_kf + koff, g_vf + koff, tid);
            CP_COMMIT();
        }

        #pragma unroll
        for (int hh = 0; hh < 2; hh++) {
            const int kt = 2*p + hh;
            const uint32_t stg = sb + OFF_ST + (kt & 3) * STG_SZ;
            const uint32_t sK = stg, sV = stg + 8192;

            float sacc[8][4];
            #pragma unroll
            for (int q = 0; q < 8; q++)
                #pragma unroll
                for (int r = 0; r < 4; r++) sacc[q][r] = 0.f;

            #pragma unroll
            for (int ks = 0; ks < 4; ks++) {
                uint32_t qa = sb + OFF_QF + arow * 128 + (((2*ks + akb) ^ (arow & 7)) << 4);
                uint32_t ah[4];
                LDSM4(ah, qa);
                #pragma unroll
                for (int g = 0; g < 4; g++) {
                    uint32_t br = g * 16 + brow;
                    uint32_t ba = sK + br * 128 + (((2*ks + bkb) ^ (br & 7)) << 4);
                    uint32_t bh[4];
                    LDSM4(bh, ba);
                    mma_f16(sacc[2*g],   ah, bh[0], bh[1]);
                    mma_f16(sacc[2*g+1], ah, bh[2], bh[3]);
                }
            }

            const int   dbase = qt * QT_ - kt * KT_;
            const float f     = exp2f(lg * (float)dbase);
            const float fr0   = f * grow0;
            const float fr1   = f * grow1;
            const bool  edge  = (dbase < KT_);
            uint32_t SA[4][4];
            #pragma unroll
            for (int q = 0; q < 8; q++) {
                const float c0 = gc[q], c1 = gc[q] * ginv;
                float v00 = sacc[q][0] * fr0 * c0;
                float v01 = sacc[q][1] * fr0 * c1;
                float v10 = sacc[q][2] * fr1 * c0;
                float v11 = sacc[q][3] * fr1 * c1;
                if (edge) {
                    const int tl0 = q * 8 + (lane & 3) * 2;
                    const int d00 = dbase + rl0 - tl0;
                    if (d00 < 0)     v00 = 0.f;
                    if (d00 - 1 < 0) v01 = 0.f;
                    if (d00 + 8 < 0) v10 = 0.f;
                    if (d00 + 7 < 0) v11 = 0.f;
                }
                const int j = q >> 1, o = (q & 1) * 2;
                SA[j][o]     = packh2(v00, v01);
                SA[j][o + 1] = packh2(v10, v11);
            }

            #pragma unroll
            for (int j = 0; j < 4; j++) {
                uint32_t vr = j * 16 + vrow;
                #pragma unroll
                for (int g = 0; g < 4; g++) {
                    uint32_t va = sV + vr * 128 + (((2*g + vnb) ^ (vr & 7)) << 4);
                    uint32_t bv[4];
                    LDSM4T(bv, va);
                    mma_f16(oacc[2*g],   SA[j], bv[0], bv[1]);
                    mma_f16(oacc[2*g+1], SA[j], bv[2], bv[3]);
                }
            }
        }
    }

    // ---- epilogue: y = O * silu(g) -> single fp16 for the out-projection
    const size_t row0 = (size_t)(b * S_ + qt * QT_ + rl0);
    #pragma unroll
    for (int p = 0; p < 8; p++) {
        const int col = h * DH_ + p * 8 + (lane & 3) * 2;
        #pragma unroll
        for (int half = 0; half < 2; half++) {
            const size_t idx2 = (row0 + half * 8) * D_ + col;
            float2 gv = *(const float2*)(g_g + idx2);
            float s0 = gv.x / (1.f + expf(-gv.x));
            float s1 = gv.y / (1.f + expf(-gv.y));
            float y0 = oacc[p][half*2 + 0] * s0;
            float y1 = oacc[p][half*2 + 1] * s1;
            *(uint32_t*)&g_ao[idx2] = packh2(y0, y1);
        }
    }
}

// ============================================================================
extern "C" void kernel_launch(void* const* d_in, const int* in_sizes, int n_in,
                              void* d_out, int out_size)
{
    const float* x  = (const float*)d_in[0];
    const float* wq = (const float*)d_in[1];
    const float* wk = (const float*)d_in[2];
    const float* wv = (const float*)d_in[3];
    const float* wg = (const float*)d_in[4];
    const float* wo = (const float*)d_in[5];
    float* out = (float*)d_out;

    cudaFuncSetAttribute(gemm_qkvg_f16,
                         cudaFuncAttributeMaxDynamicSharedMemorySize, GEMM_SMEM);
    cudaFuncSetAttribute(gemm_out_f16,
                         cudaFuncAttributeMaxDynamicSharedMemorySize, GEMM_SMEM);
    cudaFuncSetAttribute(attn_kernel,
                         cudaFuncAttributeMaxDynamicSharedMemorySize, ATTN_SMEM);

    split_kernel<<<SPLIT_BLOCKS, 256>>>(x, wq, wk, wv, wg, wo);

    gemm_qkvg_f16<<<dim3(D_/128, M_/128, 4), 256, GEMM_SMEM>>>();

    int nrope = M_ * H_ * 32;
    rope_kernel<<<(nrope + 255) / 256, 256>>>();

    attn_kernel<<<(S_/QT_) * H_ * B_, 256, ATTN_SMEM>>>();

    gemm_out_f16<<<dim3(D_/128, M_/128), 256, GEMM_SMEM>>>(out);
}